// round 1
// baseline (speedup 1.0000x reference)
#include <cuda_runtime.h>
#include <math.h>

#define SEQ 2048
#define DIM 64
#define NH  16
#define BH  32          // block size (block_h == block_w == 32)
#define NB  (SEQ / BH)  // 64 blocks per dimension

// Block mask scratch: 1 byte per (head, q-block, k-block)
__device__ unsigned char g_bm[NH * NB * NB];

// ---------------------------------------------------------------------------
// Kernel 1: block-OR pooling of the dense mask -> g_bm
// One warp per 32x32 block; only lower-triangular (kb <= qb) blocks are read.
// ---------------------------------------------------------------------------
__global__ void block_mask_kernel(const int* __restrict__ mask) {
    int wid  = (blockIdx.x * blockDim.x + threadIdx.x) >> 5;
    int lane = threadIdx.x & 31;
    if (wid >= NH * NB * NB) return;
    int h   = wid >> 12;          // / (NB*NB)
    int rem = wid & (NB * NB - 1);
    int qb  = rem >> 6;
    int kb  = rem & (NB - 1);

    unsigned char res = 0;
    if (kb <= qb) {
        // lane = row within block; read 32 ints (8 x int4), OR-reduce
        const int4* p = (const int4*)(mask +
            ((size_t)h * SEQ + (size_t)qb * BH + lane) * SEQ + (size_t)kb * BH);
        int acc = 0;
        #pragma unroll
        for (int i = 0; i < 8; i++) {
            int4 a = p[i];
            acc |= a.x | a.y | a.z | a.w;
        }
        unsigned ballot = __ballot_sync(0xffffffffu, acc != 0);
        res = ballot ? 1 : 0;
    }
    if (lane == 0) g_bm[wid] = res;
}

// ---------------------------------------------------------------------------
// Kernel 2: block-sparse causal flash attention, fp32.
// Grid: (NB, NH). 128 threads. Thread (r = tid/4, quad = tid%4):
//   - holds Q[r, quad*16 .. quad*16+16) in registers
//   - computes partial dot over its 16-d slice, quad-reduced via shfl_xor
//   - owns output slice O[r, quad*16 .. +16)
// ---------------------------------------------------------------------------
__global__ __launch_bounds__(128, 4)
void attn_kernel(const float* __restrict__ qry,
                 const float* __restrict__ key,
                 const float* __restrict__ val,
                 float* __restrict__ out) {
    __shared__ float ksm[BH][DIM];
    __shared__ float vsm[BH][DIM];

    const int h   = blockIdx.y;
    const int qb  = (int)gridDim.x - 1 - (int)blockIdx.x;  // big tiles first
    const int tid = threadIdx.x;
    const int r    = tid >> 2;
    const int quad = tid & 3;

    // ---- stage Q tile through smem (coalesced), then into registers ----
    {
        const float4* src = (const float4*)(qry + ((size_t)h * SEQ + (size_t)qb * BH) * DIM);
        float4* dst = (float4*)&ksm[0][0];
        #pragma unroll
        for (int i = 0; i < 4; i++) dst[tid + i * 128] = src[tid + i * 128];
    }
    __syncthreads();
    float qreg[16];
    #pragma unroll
    for (int i = 0; i < 4; i++) {
        float4 t = *(const float4*)&ksm[r][quad * 16 + i * 4];
        qreg[i * 4 + 0] = t.x; qreg[i * 4 + 1] = t.y;
        qreg[i * 4 + 2] = t.z; qreg[i * 4 + 3] = t.w;
    }
    __syncthreads();

    float acc[16];
    #pragma unroll
    for (int i = 0; i < 16; i++) acc[i] = 0.f;
    float m = -INFINITY;
    float l = 0.f;

    const unsigned char* bm = g_bm + ((size_t)h * NB + qb) * NB;

    for (int kb = 0; kb <= qb; kb++) {
        if (!bm[kb]) continue;   // uniform across block

        // ---- load K and V tiles (coalesced float4) ----
        const float4* ks = (const float4*)(key + ((size_t)h * SEQ + (size_t)kb * BH) * DIM);
        const float4* vs = (const float4*)(val + ((size_t)h * SEQ + (size_t)kb * BH) * DIM);
        float4* kd = (float4*)&ksm[0][0];
        float4* vd = (float4*)&vsm[0][0];
        #pragma unroll
        for (int i = 0; i < 4; i++) {
            kd[tid + i * 128] = ks[tid + i * 128];
            vd[tid + i * 128] = vs[tid + i * 128];
        }
        __syncthreads();

        // ---- scores S[r, 0..31] (full row known to each quad thread) ----
        float s[BH];
        #pragma unroll
        for (int c = 0; c < BH; c++) {
            const float4* kr = (const float4*)&ksm[c][quad * 16];
            float4 k0 = kr[0], k1 = kr[1], k2 = kr[2], k3 = kr[3];
            float p;
            p  = qreg[0]  * k0.x; p = fmaf(qreg[1],  k0.y, p);
            p  = fmaf(qreg[2],  k0.z, p); p = fmaf(qreg[3],  k0.w, p);
            p  = fmaf(qreg[4],  k1.x, p); p = fmaf(qreg[5],  k1.y, p);
            p  = fmaf(qreg[6],  k1.z, p); p = fmaf(qreg[7],  k1.w, p);
            p  = fmaf(qreg[8],  k2.x, p); p = fmaf(qreg[9],  k2.y, p);
            p  = fmaf(qreg[10], k2.z, p); p = fmaf(qreg[11], k2.w, p);
            p  = fmaf(qreg[12], k3.x, p); p = fmaf(qreg[13], k3.y, p);
            p  = fmaf(qreg[14], k3.z, p); p = fmaf(qreg[15], k3.w, p);
            p += __shfl_xor_sync(0xffffffffu, p, 1);
            p += __shfl_xor_sync(0xffffffffu, p, 2);
            s[c] = p;
        }

        // ---- causal mask on the diagonal block ----
        if (kb == qb) {
            #pragma unroll
            for (int c = 0; c < BH; c++)
                if (c > r) s[c] = -INFINITY;
        }

        // ---- online softmax update (redundant per quad, no comm needed) ----
        float mt = m;
        #pragma unroll
        for (int c = 0; c < BH; c++) mt = fmaxf(mt, s[c]);
        float corr = __expf(m - mt);   // m=-inf, mt finite -> 0 (first tile)
        float lsum = 0.f;
        #pragma unroll
        for (int c = 0; c < BH; c++) {
            float p = __expf(s[c] - mt);
            s[c] = p;
            lsum += p;
        }
        l = l * corr + lsum;
        m = mt;
        #pragma unroll
        for (int i = 0; i < 16; i++) acc[i] *= corr;

        // ---- PV accumulate: acc[i] += sum_c P[r,c] * V[c, quad*16+i] ----
        #pragma unroll
        for (int c = 0; c < BH; c++) {
            const float4* vr = (const float4*)&vsm[c][quad * 16];
            float4 v0 = vr[0], v1 = vr[1], v2 = vr[2], v3 = vr[3];
            float p = s[c];
            acc[0]  = fmaf(p, v0.x, acc[0]);  acc[1]  = fmaf(p, v0.y, acc[1]);
            acc[2]  = fmaf(p, v0.z, acc[2]);  acc[3]  = fmaf(p, v0.w, acc[3]);
            acc[4]  = fmaf(p, v1.x, acc[4]);  acc[5]  = fmaf(p, v1.y, acc[5]);
            acc[6]  = fmaf(p, v1.z, acc[6]);  acc[7]  = fmaf(p, v1.w, acc[7]);
            acc[8]  = fmaf(p, v2.x, acc[8]);  acc[9]  = fmaf(p, v2.y, acc[9]);
            acc[10] = fmaf(p, v2.z, acc[10]); acc[11] = fmaf(p, v2.w, acc[11]);
            acc[12] = fmaf(p, v3.x, acc[12]); acc[13] = fmaf(p, v3.y, acc[13]);
            acc[14] = fmaf(p, v3.z, acc[14]); acc[15] = fmaf(p, v3.w, acc[15]);
        }
        __syncthreads();   // protect smem before next tile's load
    }

    // ---- finalize: divide by row sum (zeros if row fully masked) ----
    float inv = (l > 0.f) ? (1.f / l) : 0.f;
    float* obase = out + ((size_t)h * SEQ + (size_t)qb * BH + r) * DIM + quad * 16;
    float4* o4 = (float4*)obase;
    o4[0] = make_float4(acc[0] * inv,  acc[1] * inv,  acc[2] * inv,  acc[3] * inv);
    o4[1] = make_float4(acc[4] * inv,  acc[5] * inv,  acc[6] * inv,  acc[7] * inv);
    o4[2] = make_float4(acc[8] * inv,  acc[9] * inv,  acc[10] * inv, acc[11] * inv);
    o4[3] = make_float4(acc[12] * inv, acc[13] * inv, acc[14] * inv, acc[15] * inv);
}

// ---------------------------------------------------------------------------
// Launch
// ---------------------------------------------------------------------------
extern "C" void kernel_launch(void* const* d_in, const int* in_sizes, int n_in,
                              void* d_out, int out_size) {
    const float* qry  = (const float*)d_in[0];
    const float* key  = (const float*)d_in[1];
    const float* val  = (const float*)d_in[2];
    const int*   mask = (const int*)d_in[3];
    float* out = (float*)d_out;

    // 1 warp per block-mask entry; 256 threads (8 warps) per CTA
    int total_warps = NH * NB * NB;
    int cta = (total_warps * 32 + 255) / 256;
    block_mask_kernel<<<cta, 256>>>(mask);

    dim3 grid(NB, NH);
    attn_kernel<<<grid, 128>>>(qry, key, val, out);
}

// round 2
// speedup vs baseline: 2.2974x; 2.2974x over previous
#include <cuda_runtime.h>
#include <math.h>

#define SEQ  2048
#define DIM  64
#define NH   16
#define BH   32            // mask block size
#define NB   (SEQ / BH)    // 64 mask blocks per dim
#define QT   64            // q-tile rows per CTA
#define NQT  (SEQ / QT)    // 32 q-tiles
#define NSM  152           // GB300 SM count
#define NWORK (NH * NQT)   // 512 work items

// Block mask scratch: 1 byte per (head, q-block, k-block)
__device__ unsigned char g_bm[NH * NB * NB];

// ---------------------------------------------------------------------------
// packed f32x2 helpers (SASS FFMA2 path — only reachable via PTX f32x2 ops)
// ---------------------------------------------------------------------------
__device__ __forceinline__ unsigned long long pk2(float x) {
    unsigned long long r;
    asm("mov.b64 %0, {%1, %1};" : "=l"(r) : "f"(x));
    return r;
}
__device__ __forceinline__ unsigned long long ffma2(unsigned long long a,
                                                    unsigned long long b,
                                                    unsigned long long c) {
    unsigned long long d;
    asm("fma.rn.f32x2 %0, %1, %2, %3;" : "=l"(d) : "l"(a), "l"(b), "l"(c));
    return d;
}
__device__ __forceinline__ unsigned long long fmul2(unsigned long long a,
                                                    unsigned long long b) {
    unsigned long long d;
    asm("mul.rn.f32x2 %0, %1, %2;" : "=l"(d) : "l"(a), "l"(b));
    return d;
}
__device__ __forceinline__ void upk2(unsigned long long v, float& lo, float& hi) {
    asm("mov.b64 {%0, %1}, %2;" : "=f"(lo), "=f"(hi) : "l"(v));
}

// ---------------------------------------------------------------------------
// Kernel 1: block-OR pooling of the dense mask -> g_bm (lower-tri only)
// ---------------------------------------------------------------------------
__global__ void block_mask_kernel(const int* __restrict__ mask) {
    int wid  = (blockIdx.x * blockDim.x + threadIdx.x) >> 5;
    int lane = threadIdx.x & 31;
    if (wid >= NH * NB * NB) return;
    int h   = wid >> 12;
    int rem = wid & (NB * NB - 1);
    int qb  = rem >> 6;
    int kb  = rem & (NB - 1);

    unsigned char res = 0;
    if (kb <= qb) {
        const int4* p = (const int4*)(mask +
            ((size_t)h * SEQ + (size_t)qb * BH + lane) * SEQ + (size_t)kb * BH);
        int acc = 0;
        #pragma unroll
        for (int i = 0; i < 8; i++) {
            int4 a = p[i];
            acc |= a.x | a.y | a.z | a.w;
        }
        unsigned ballot = __ballot_sync(0xffffffffu, acc != 0);
        res = ballot ? 1 : 0;
    }
    if (lane == 0) g_bm[wid] = res;
}

// ---------------------------------------------------------------------------
// Kernel 2: block-sparse causal flash attention, fp32, f32x2-packed FMAs.
// CTA: 128 threads, tile 64 (q) x 64 (k). Thread (ty=tid/8, tx=tid&7):
//   QK: computes S[ty*4 .. +4)[tx*8 .. +8)  (4x8 register tile)
//   PV: accumulates O[ty*4 .. +4)[tx*8 .. +8)
// qsm: Q^T [d][r], kpsm: K^T [d][c] then reused as P [c][r], vsm: V [c][d].
// ---------------------------------------------------------------------------
__global__ __launch_bounds__(128, 4)
void attn_kernel(const float* __restrict__ qry,
                 const float* __restrict__ key,
                 const float* __restrict__ val,
                 float* __restrict__ out) {
    __shared__ float qsm [DIM][QT];   // Q^T: [d][row]
    __shared__ float kpsm[DIM][QT];   // K^T: [d][col]  /  P: [col][row]
    __shared__ float vsm [QT][DIM];   // V:   [col][d]

    // ---- snake work assignment: rank sorted by descending cost ----
    int bid  = blockIdx.x;
    int pos  = bid % NSM;
    int chnk = bid / NSM;
    int rank = (chnk & 1) ? (chnk * NSM + (NSM - 1 - pos)) : (chnk * NSM + pos);
    if (rank >= NWORK) return;
    const int qt = (NQT - 1) - (rank >> 4);   // heavy q-tiles first
    const int h  = rank & (NH - 1);

    const int tid = threadIdx.x;
    const int ty  = tid >> 3;          // 0..15  -> rows ty*4..+3
    const int tx  = tid & 7;           // 0..7   -> cols tx*8..+7
    const int R0  = ty * 4;
    const int C0  = tx * 8;
    const int qh  = ty >> 3;           // which 32-row mask half
    const int kh  = tx >> 2;           // which 32-col mask half

    // ---- stage Q^T (once per CTA) ----
    {
        int r  = tid >> 1;
        int dh = (tid & 1) * 32;
        const float4* src = (const float4*)(qry +
            ((size_t)(h * SEQ + qt * QT + r)) * DIM + dh);
        #pragma unroll
        for (int i = 0; i < 8; i++) {
            float4 t = src[i];
            int d = dh + i * 4;
            qsm[d + 0][r] = t.x; qsm[d + 1][r] = t.y;
            qsm[d + 2][r] = t.z; qsm[d + 3][r] = t.w;
        }
    }

    unsigned long long acc2[4][4];
    #pragma unroll
    for (int i = 0; i < 4; i++)
        #pragma unroll
        for (int j = 0; j < 4; j++) acc2[i][j] = 0ull;
    float m[4], l[4];
    #pragma unroll
    for (int i = 0; i < 4; i++) { m[i] = -1e30f; l[i] = 0.f; }

    const unsigned char* bmrow = g_bm + ((size_t)h * NB + qt * 2) * NB;

    for (int kt = 0; kt <= qt; kt++) {
        // ---- 2x2 sub-block mask for this 64x64 tile ----
        unsigned char b00 = bmrow[kt * 2], b01 = bmrow[kt * 2 + 1];
        unsigned char b10 = bmrow[NB + kt * 2], b11 = bmrow[NB + kt * 2 + 1];
        if (!(b00 | b01 | b10 | b11)) continue;
        const bool act = qh ? (kh ? (b11 != 0) : (b10 != 0))
                            : (kh ? (b01 != 0) : (b00 != 0));

        __syncthreads();   // prev PV done before overwriting kpsm/vsm

        // ---- load K^T (transpose) and V (direct) ----
        {
            int c  = tid >> 1;
            int dh = (tid & 1) * 32;
            const float4* src = (const float4*)(key +
                ((size_t)(h * SEQ + kt * QT + c)) * DIM + dh);
            #pragma unroll
            for (int i = 0; i < 8; i++) {
                float4 t = src[i];
                int d = dh + i * 4;
                kpsm[d + 0][c] = t.x; kpsm[d + 1][c] = t.y;
                kpsm[d + 2][c] = t.z; kpsm[d + 3][c] = t.w;
            }
        }
        {
            const float4* src = (const float4*)(val +
                ((size_t)(h * SEQ + kt * QT)) * DIM);
            float4* dst = (float4*)&vsm[0][0];
            #pragma unroll
            for (int i = 0; i < 8; i++) dst[tid + i * 128] = src[tid + i * 128];
        }
        __syncthreads();

        // ---- QK: s2[r][c2] += q[r] * k[c2]  (packed over c) ----
        unsigned long long s2[4][4];
        #pragma unroll
        for (int i = 0; i < 4; i++)
            #pragma unroll
            for (int j = 0; j < 4; j++) s2[i][j] = 0ull;

        #pragma unroll 8
        for (int d = 0; d < DIM; d++) {
            float4 qv = *(const float4*)&qsm[d][R0];
            ulonglong2 k01 = *(const ulonglong2*)&kpsm[d][C0];
            ulonglong2 k23 = *(const ulonglong2*)&kpsm[d][C0 + 4];
            unsigned long long q0 = pk2(qv.x), q1 = pk2(qv.y),
                               q2 = pk2(qv.z), q3 = pk2(qv.w);
            s2[0][0] = ffma2(q0, k01.x, s2[0][0]);
            s2[0][1] = ffma2(q0, k01.y, s2[0][1]);
            s2[0][2] = ffma2(q0, k23.x, s2[0][2]);
            s2[0][3] = ffma2(q0, k23.y, s2[0][3]);
            s2[1][0] = ffma2(q1, k01.x, s2[1][0]);
            s2[1][1] = ffma2(q1, k01.y, s2[1][1]);
            s2[1][2] = ffma2(q1, k23.x, s2[1][2]);
            s2[1][3] = ffma2(q1, k23.y, s2[1][3]);
            s2[2][0] = ffma2(q2, k01.x, s2[2][0]);
            s2[2][1] = ffma2(q2, k01.y, s2[2][1]);
            s2[2][2] = ffma2(q2, k23.x, s2[2][2]);
            s2[2][3] = ffma2(q2, k23.y, s2[2][3]);
            s2[3][0] = ffma2(q3, k01.x, s2[3][0]);
            s2[3][1] = ffma2(q3, k01.y, s2[3][1]);
            s2[3][2] = ffma2(q3, k23.x, s2[3][2]);
            s2[3][3] = ffma2(q3, k23.y, s2[3][3]);
        }

        // ---- unpack + masks ----
        float p[4][8];
        #pragma unroll
        for (int ri = 0; ri < 4; ri++)
            #pragma unroll
            for (int j = 0; j < 4; j++)
                upk2(s2[ri][j], p[ri][2 * j], p[ri][2 * j + 1]);

        if (!act) {
            #pragma unroll
            for (int ri = 0; ri < 4; ri++)
                #pragma unroll
                for (int c = 0; c < 8; c++) p[ri][c] = -1e30f;
        }
        if (kt == qt) {   // causal on diagonal tile (uniform branch)
            #pragma unroll
            for (int ri = 0; ri < 4; ri++)
                #pragma unroll
                for (int c = 0; c < 8; c++)
                    if (C0 + c > R0 + ri) p[ri][c] = -1e30f;
        }

        // ---- online softmax (stats reduced over the 8 tx threads) ----
        #pragma unroll
        for (int ri = 0; ri < 4; ri++) {
            float tm = p[ri][0];
            #pragma unroll
            for (int c = 1; c < 8; c++) tm = fmaxf(tm, p[ri][c]);
            tm = fmaxf(tm, __shfl_xor_sync(0xffffffffu, tm, 1));
            tm = fmaxf(tm, __shfl_xor_sync(0xffffffffu, tm, 2));
            tm = fmaxf(tm, __shfl_xor_sync(0xffffffffu, tm, 4));
            float newm = fmaxf(m[ri], tm);
            float corr = __expf(m[ri] - newm);
            float sum = 0.f;
            #pragma unroll
            for (int c = 0; c < 8; c++) {
                float e = __expf(p[ri][c] - newm);
                p[ri][c] = e;
                sum += e;
            }
            sum += __shfl_xor_sync(0xffffffffu, sum, 1);
            sum += __shfl_xor_sync(0xffffffffu, sum, 2);
            sum += __shfl_xor_sync(0xffffffffu, sum, 4);
            l[ri] = l[ri] * corr + sum;
            m[ri] = newm;
            unsigned long long c2 = pk2(corr);
            #pragma unroll
            for (int j = 0; j < 4; j++) acc2[ri][j] = fmul2(acc2[ri][j], c2);
        }

        __syncthreads();   // all QK reads of kpsm done -> safe to overwrite with P

        // ---- write P into kpsm as [col][row] ----
        #pragma unroll
        for (int c = 0; c < 8; c++) {
            *(float4*)&kpsm[C0 + c][R0] =
                make_float4(p[0][c], p[1][c], p[2][c], p[3][c]);
        }
        __syncthreads();

        // ---- PV: acc2[r][d2] += P[r][c] * V[c][d2]  (packed over d) ----
        #pragma unroll 8
        for (int c = 0; c < QT; c++) {
            float4 pv = *(const float4*)&kpsm[c][R0];
            ulonglong2 v01 = *(const ulonglong2*)&vsm[c][C0];
            ulonglong2 v23 = *(const ulonglong2*)&vsm[c][C0 + 4];
            unsigned long long p0 = pk2(pv.x), p1 = pk2(pv.y),
                               p2 = pk2(pv.z), p3 = pk2(pv.w);
            acc2[0][0] = ffma2(p0, v01.x, acc2[0][0]);
            acc2[0][1] = ffma2(p0, v01.y, acc2[0][1]);
            acc2[0][2] = ffma2(p0, v23.x, acc2[0][2]);
            acc2[0][3] = ffma2(p0, v23.y, acc2[0][3]);
            acc2[1][0] = ffma2(p1, v01.x, acc2[1][0]);
            acc2[1][1] = ffma2(p1, v01.y, acc2[1][1]);
            acc2[1][2] = ffma2(p1, v23.x, acc2[1][2]);
            acc2[1][3] = ffma2(p1, v23.y, acc2[1][3]);
            acc2[2][0] = ffma2(p2, v01.x, acc2[2][0]);
            acc2[2][1] = ffma2(p2, v01.y, acc2[2][1]);
            acc2[2][2] = ffma2(p2, v23.x, acc2[2][2]);
            acc2[2][3] = ffma2(p2, v23.y, acc2[2][3]);
            acc2[3][0] = ffma2(p3, v01.x, acc2[3][0]);
            acc2[3][1] = ffma2(p3, v01.y, acc2[3][1]);
            acc2[3][2] = ffma2(p3, v23.x, acc2[3][2]);
            acc2[3][3] = ffma2(p3, v23.y, acc2[3][3]);
        }
    }

    // ---- finalize ----
    #pragma unroll
    for (int ri = 0; ri < 4; ri++) {
        float inv = (m[ri] > -1e29f) ? (1.f / l[ri]) : 0.f;
        float o[8];
        #pragma unroll
        for (int j = 0; j < 4; j++) {
            float lo, hi;
            upk2(acc2[ri][j], lo, hi);
            o[2 * j]     = lo * inv;
            o[2 * j + 1] = hi * inv;
        }
        float* ob = out + ((size_t)(h * SEQ + qt * QT + R0 + ri)) * DIM + C0;
        *(float4*)(ob)     = make_float4(o[0], o[1], o[2], o[3]);
        *(float4*)(ob + 4) = make_float4(o[4], o[5], o[6], o[7]);
    }
}

// ---------------------------------------------------------------------------
// Launch
// ---------------------------------------------------------------------------
extern "C" void kernel_launch(void* const* d_in, const int* in_sizes, int n_in,
                              void* d_out, int out_size) {
    const float* qry  = (const float*)d_in[0];
    const float* key  = (const float*)d_in[1];
    const float* val  = (const float*)d_in[2];
    const int*   mask = (const int*)d_in[3];
    float* out = (float*)d_out;

    int total_warps = NH * NB * NB;
    int cta = (total_warps * 32 + 255) / 256;
    block_mask_kernel<<<cta, 256>>>(mask);

    attn_kernel<<<4 * NSM, 128>>>(qry, key, val, out);
}

// round 3
// speedup vs baseline: 3.6862x; 1.6045x over previous
#include <cuda_runtime.h>
#include <math.h>

#define SEQ  2048
#define DIM  64
#define NH   16
#define BH   32            // mask block size
#define NB   (SEQ / BH)    // 64 mask blocks per dim
#define QTR  128           // q rows per CTA
#define KTC  64            // k cols per tile
#define NQT  (SEQ / QTR)   // 16 q-tiles
#define NSM  152
#define NWORK (NH * NQT)   // 256 work items
#define PSTR 132           // padded P row stride (floats)

// smem layout (floats): qsm[64][128] | ksm[64][64] | vsm[64][64] | psm[64][132]
#define QSM_F (DIM * QTR)
#define KSM_F (DIM * KTC)
#define VSM_F (KTC * DIM)
#define PSM_F (KTC * PSTR)
#define SMEM_BYTES ((QSM_F + KSM_F + VSM_F + PSM_F) * 4)

__device__ unsigned char g_bm[NH * NB * NB];

// ---------------------------------------------------------------------------
// packed f32x2 helpers (SASS FFMA2 path)
// ---------------------------------------------------------------------------
typedef unsigned long long u64;
__device__ __forceinline__ u64 pk2(float x) {
    u64 r; asm("mov.b64 %0, {%1, %1};" : "=l"(r) : "f"(x)); return r;
}
__device__ __forceinline__ u64 ffma2(u64 a, u64 b, u64 c) {
    u64 d; asm("fma.rn.f32x2 %0, %1, %2, %3;" : "=l"(d) : "l"(a), "l"(b), "l"(c)); return d;
}
__device__ __forceinline__ u64 fmul2(u64 a, u64 b) {
    u64 d; asm("mul.rn.f32x2 %0, %1, %2;" : "=l"(d) : "l"(a), "l"(b)); return d;
}
__device__ __forceinline__ void upk2(u64 v, float& lo, float& hi) {
    asm("mov.b64 {%0, %1}, %2;" : "=f"(lo), "=f"(hi) : "l"(v));
}

// ---------------------------------------------------------------------------
// Kernel 1: block-OR pooling of the dense mask -> g_bm (lower-tri only)
// ---------------------------------------------------------------------------
__global__ void block_mask_kernel(const int* __restrict__ mask) {
    int wid  = (blockIdx.x * blockDim.x + threadIdx.x) >> 5;
    int lane = threadIdx.x & 31;
    if (wid >= NH * NB * NB) return;
    int h   = wid >> 12;
    int rem = wid & (NB * NB - 1);
    int qb  = rem >> 6;
    int kb  = rem & (NB - 1);

    unsigned char res = 0;
    if (kb <= qb) {
        const int4* p = (const int4*)(mask +
            ((size_t)h * SEQ + (size_t)qb * BH + lane) * SEQ + (size_t)kb * BH);
        int acc = 0;
        #pragma unroll
        for (int i = 0; i < 8; i++) {
            int4 a = p[i];
            acc |= a.x | a.y | a.z | a.w;
        }
        unsigned ballot = __ballot_sync(0xffffffffu, acc != 0);
        res = ballot ? 1 : 0;
    }
    if (lane == 0) g_bm[wid] = res;
}

// ---------------------------------------------------------------------------
// Kernel 2: block-sparse causal flash attention, fp32, f32x2-packed.
// CTA: 128 threads, Q-tile 128 rows x K-tile 64 cols.
// Thread (ty=tid/8, tx=tid&7): rows R0=ty*8..+8,
// cols {tx*4..+3} U {32+tx*4..+3}  (contiguous 16B spans -> 1-wf smem reads)
// ---------------------------------------------------------------------------
__global__ void __launch_bounds__(128, 2)
attn_kernel(const float* __restrict__ qry,
            const float* __restrict__ key,
            const float* __restrict__ val,
            float* __restrict__ out) {
    extern __shared__ float smem[];
    float* qsm = smem;                 // Q^T [d][r], stride QTR
    float* ksm = qsm + QSM_F;          // K^T [d][c], stride KTC
    float* vsm = ksm + KSM_F;          // V   [c][d], stride DIM
    float* psm = vsm + VSM_F;          // P   [c][r], stride PSTR

    // ---- snake work assignment (heavy q-tiles first) ----
    int bid  = blockIdx.x;
    int pos  = bid % NSM;
    int chnk = bid / NSM;
    int rank = (chnk & 1) ? (chnk * NSM + (NSM - 1 - pos)) : (chnk * NSM + pos);
    if (rank >= NWORK) return;
    const int qt = (NQT - 1) - (rank >> 4);
    const int h  = rank & (NH - 1);

    const int tid = threadIdx.x;
    const int ty  = tid >> 3;          // 0..15
    const int tx  = tid & 7;           // 0..7
    const int R0  = ty * 8;
    const int CA  = tx * 4;            // first col group
    const int CB  = 32 + tx * 4;       // second col group

    // ---- stage Q^T (once) ----
    #pragma unroll
    for (int pass = 0; pass < 2; pass++) {
        int r  = pass * 64 + (tid >> 1);
        int dh = (tid & 1) * 32;
        const float4* src = (const float4*)(qry +
            ((size_t)(h * SEQ + qt * QTR + r)) * DIM + dh);
        #pragma unroll
        for (int i = 0; i < 8; i++) {
            float4 t = src[i];
            int d = dh + i * 4;
            qsm[(d + 0) * QTR + r] = t.x; qsm[(d + 1) * QTR + r] = t.y;
            qsm[(d + 2) * QTR + r] = t.z; qsm[(d + 3) * QTR + r] = t.w;
        }
    }

    u64 acc2[8][4];
    #pragma unroll
    for (int i = 0; i < 8; i++)
        #pragma unroll
        for (int j = 0; j < 4; j++) acc2[i][j] = 0ull;
    float m[8], l[8];
    #pragma unroll
    for (int i = 0; i < 8; i++) { m[i] = -1e30f; l[i] = 0.f; }

    // mask row pointer for this thread's 32-row band
    const unsigned char* bmrow = g_bm +
        ((size_t)h * NB + (qt * 4 + (ty >> 2))) * NB;

    const int ktmax = 2 * qt + 1;
    for (int kt = 0; kt <= ktmax; kt++) {
        int a0 = bmrow[kt * 2];
        int a1 = bmrow[kt * 2 + 1];
        // barrier: prev PV reads of psm/vsm done; also CTA-wide tile-skip OR
        int tileact = __syncthreads_or(a0 | a1);
        if (!tileact) continue;

        // ---- load K^T (transpose) and V ----
        {
            int c  = tid >> 1;
            int dh = (tid & 1) * 32;
            const float4* src = (const float4*)(key +
                ((size_t)(h * SEQ + kt * KTC + c)) * DIM + dh);
            #pragma unroll
            for (int i = 0; i < 8; i++) {
                float4 t = src[i];
                int d = dh + i * 4;
                ksm[(d + 0) * KTC + c] = t.x; ksm[(d + 1) * KTC + c] = t.y;
                ksm[(d + 2) * KTC + c] = t.z; ksm[(d + 3) * KTC + c] = t.w;
            }
        }
        {
            const float4* src = (const float4*)(val +
                ((size_t)(h * SEQ + kt * KTC)) * DIM);
            float4* dst = (float4*)vsm;
            #pragma unroll
            for (int i = 0; i < 8; i++) dst[tid + i * 128] = src[tid + i * 128];
        }
        __syncthreads();

        // ---- QK: 8x8 register tile, packed over cols ----
        u64 s2[8][4];
        #pragma unroll
        for (int i = 0; i < 8; i++)
            #pragma unroll
            for (int j = 0; j < 4; j++) s2[i][j] = 0ull;

        #pragma unroll 4
        for (int d = 0; d < DIM; d++) {
            float4 qa = *(const float4*)&qsm[d * QTR + R0];
            float4 qb = *(const float4*)&qsm[d * QTR + R0 + 4];
            ulonglong2 kA = *(const ulonglong2*)&ksm[d * KTC + CA];
            ulonglong2 kB = *(const ulonglong2*)&ksm[d * KTC + CB];
            u64 q[8];
            q[0] = pk2(qa.x); q[1] = pk2(qa.y); q[2] = pk2(qa.z); q[3] = pk2(qa.w);
            q[4] = pk2(qb.x); q[5] = pk2(qb.y); q[6] = pk2(qb.z); q[7] = pk2(qb.w);
            #pragma unroll
            for (int r = 0; r < 8; r++) {
                s2[r][0] = ffma2(q[r], kA.x, s2[r][0]);
                s2[r][1] = ffma2(q[r], kA.y, s2[r][1]);
                s2[r][2] = ffma2(q[r], kB.x, s2[r][2]);
                s2[r][3] = ffma2(q[r], kB.y, s2[r][3]);
            }
        }

        // ---- unpack + masks ----
        float p[8][8];
        #pragma unroll
        for (int r = 0; r < 8; r++) {
            upk2(s2[r][0], p[r][0], p[r][1]);
            upk2(s2[r][1], p[r][2], p[r][3]);
            upk2(s2[r][2], p[r][4], p[r][5]);
            upk2(s2[r][3], p[r][6], p[r][7]);
        }
        if (!a0) {
            #pragma unroll
            for (int r = 0; r < 8; r++)
                #pragma unroll
                for (int j = 0; j < 4; j++) p[r][j] = -1e30f;
        }
        if (!a1) {
            #pragma unroll
            for (int r = 0; r < 8; r++)
                #pragma unroll
                for (int j = 4; j < 8; j++) p[r][j] = -1e30f;
        }
        if (kt >= 2 * qt) {   // boundary tiles: per-element causal
            #pragma unroll
            for (int r = 0; r < 8; r++) {
                int rowg = qt * QTR + R0 + r;
                #pragma unroll
                for (int j = 0; j < 8; j++) {
                    int colg = kt * KTC + ((j < 4) ? (CA + j) : (CB + j - 4));
                    if (colg > rowg) p[r][j] = -1e30f;
                }
            }
        }

        // ---- online softmax (reduce over the 8 tx lanes) ----
        #pragma unroll
        for (int r = 0; r < 8; r++) {
            float tm = p[r][0];
            #pragma unroll
            for (int j = 1; j < 8; j++) tm = fmaxf(tm, p[r][j]);
            tm = fmaxf(tm, __shfl_xor_sync(0xffffffffu, tm, 1));
            tm = fmaxf(tm, __shfl_xor_sync(0xffffffffu, tm, 2));
            tm = fmaxf(tm, __shfl_xor_sync(0xffffffffu, tm, 4));
            float newm = fmaxf(m[r], tm);
            float corr = __expf(m[r] - newm);
            float sum = 0.f;
            #pragma unroll
            for (int j = 0; j < 8; j++) {
                float e = __expf(p[r][j] - newm);
                p[r][j] = e;
                sum += e;
            }
            sum += __shfl_xor_sync(0xffffffffu, sum, 1);
            sum += __shfl_xor_sync(0xffffffffu, sum, 2);
            sum += __shfl_xor_sync(0xffffffffu, sum, 4);
            l[r] = l[r] * corr + sum;
            m[r] = newm;
            u64 c2 = pk2(corr);
            #pragma unroll
            for (int j = 0; j < 4; j++) acc2[r][j] = fmul2(acc2[r][j], c2);
        }

        // ---- write P [c][r] (separate buffer; no barrier needed before) ----
        #pragma unroll
        for (int j = 0; j < 8; j++) {
            int col = (j < 4) ? (CA + j) : (CB + j - 4);
            *(float4*)&psm[col * PSTR + R0] =
                make_float4(p[0][j], p[1][j], p[2][j], p[3][j]);
            *(float4*)&psm[col * PSTR + R0 + 4] =
                make_float4(p[4][j], p[5][j], p[6][j], p[7][j]);
        }
        __syncthreads();

        // ---- PV: 8 rows x 8 dims, packed over dims ----
        #pragma unroll 4
        for (int c = 0; c < KTC; c++) {
            float4 pa = *(const float4*)&psm[c * PSTR + R0];
            float4 pb = *(const float4*)&psm[c * PSTR + R0 + 4];
            ulonglong2 vA = *(const ulonglong2*)&vsm[c * DIM + CA];
            ulonglong2 vB = *(const ulonglong2*)&vsm[c * DIM + CB];
            u64 pp[8];
            pp[0] = pk2(pa.x); pp[1] = pk2(pa.y); pp[2] = pk2(pa.z); pp[3] = pk2(pa.w);
            pp[4] = pk2(pb.x); pp[5] = pk2(pb.y); pp[6] = pk2(pb.z); pp[7] = pk2(pb.w);
            #pragma unroll
            for (int r = 0; r < 8; r++) {
                acc2[r][0] = ffma2(pp[r], vA.x, acc2[r][0]);
                acc2[r][1] = ffma2(pp[r], vA.y, acc2[r][1]);
                acc2[r][2] = ffma2(pp[r], vB.x, acc2[r][2]);
                acc2[r][3] = ffma2(pp[r], vB.y, acc2[r][3]);
            }
        }
    }

    // ---- finalize ----
    #pragma unroll
    for (int r = 0; r < 8; r++) {
        float inv = (m[r] > -1e29f) ? (1.f / l[r]) : 0.f;
        float o[8];
        upk2(acc2[r][0], o[0], o[1]); upk2(acc2[r][1], o[2], o[3]);
        upk2(acc2[r][2], o[4], o[5]); upk2(acc2[r][3], o[6], o[7]);
        float* ob = out + ((size_t)(h * SEQ + qt * QTR + R0 + r)) * DIM;
        *(float4*)(ob + CA) = make_float4(o[0] * inv, o[1] * inv, o[2] * inv, o[3] * inv);
        *(float4*)(ob + CB) = make_float4(o[4] * inv, o[5] * inv, o[6] * inv, o[7] * inv);
    }
}

// ---------------------------------------------------------------------------
// Launch
// ---------------------------------------------------------------------------
extern "C" void kernel_launch(void* const* d_in, const int* in_sizes, int n_in,
                              void* d_out, int out_size) {
    const float* qry  = (const float*)d_in[0];
    const float* key  = (const float*)d_in[1];
    const float* val  = (const float*)d_in[2];
    const int*   mask = (const int*)d_in[3];
    float* out = (float*)d_out;

    int total_warps = NH * NB * NB;
    int cta = (total_warps * 32 + 255) / 256;
    block_mask_kernel<<<cta, 256>>>(mask);

    cudaFuncSetAttribute(attn_kernel,
                         cudaFuncAttributeMaxDynamicSharedMemorySize, SMEM_BYTES);
    attn_kernel<<<2 * NSM, 128, SMEM_BYTES>>>(qry, key, val, out);
}

// round 10
// speedup vs baseline: 4.2101x; 1.1421x over previous
#include <cuda_runtime.h>
#include <cuda_bf16.h>
#include <math.h>
#include <stdint.h>

#define SEQ  2048
#define DIM  64
#define NH   16
#define NB   64            // 32-wide mask blocks per dim
#define QTR  128           // q rows per work item
#define KTC  64            // k cols per tile
#define NQT  (SEQ / QTR)   // 16
#define NWORK (NH * NQT)   // 256
#define NSM  152

__device__ unsigned char g_bm[NH * NB * NB];
__device__ int g_ctr;

// ---------------- smem layout (bytes): bf16 tiles, 128B rows, swizzled -----
#define OF_QHI 128
#define OF_QLO (OF_QHI + 16384)   // Q: 128 x 64
#define OF_KHI (OF_QLO + 16384)   // K: 64 x 64
#define OF_KLO (OF_KHI + 8192)
#define OF_VHI (OF_KLO + 8192)    // V: 64 x 64 (row-major; ldmatrix.trans)
#define OF_VLO (OF_VHI + 8192)
#define SMEM_BYTES (OF_VLO + 8192)   // 65664

// ---------------------------------------------------------------------------
// helpers (all baseline PTX — no sm_103a-only features)
// ---------------------------------------------------------------------------
__device__ __forceinline__ uint32_t smem_u32(const void* p) {
    uint32_t a;
    asm("{ .reg .u64 t; cvta.to.shared.u64 t, %1; cvt.u32.u64 %0, t; }"
        : "=r"(a) : "l"(p));
    return a;
}
__device__ __forceinline__ uint32_t swz(uint32_t o) { return o ^ ((o >> 3) & 0x70); }

__device__ __forceinline__ void ldsm4(uint32_t addr, uint32_t r[4]) {
    asm volatile("ldmatrix.sync.aligned.m8n8.x4.shared.b16 {%0,%1,%2,%3}, [%4];"
        : "=r"(r[0]), "=r"(r[1]), "=r"(r[2]), "=r"(r[3]) : "r"(addr));
}
__device__ __forceinline__ void ldsm2(uint32_t addr, uint32_t r[2]) {
    asm volatile("ldmatrix.sync.aligned.m8n8.x2.shared.b16 {%0,%1}, [%2];"
        : "=r"(r[0]), "=r"(r[1]) : "r"(addr));
}
__device__ __forceinline__ void ldsm2t(uint32_t addr, uint32_t r[2]) {
    asm volatile("ldmatrix.sync.aligned.m8n8.x2.trans.shared.b16 {%0,%1}, [%2];"
        : "=r"(r[0]), "=r"(r[1]) : "r"(addr));
}
__device__ __forceinline__ void mma16816(float c[4], const uint32_t a[4],
                                         const uint32_t b[2]) {
    asm volatile(
        "mma.sync.aligned.m16n8k16.row.col.f32.bf16.bf16.f32 "
        "{%0,%1,%2,%3}, {%4,%5,%6,%7}, {%8,%9}, {%0,%1,%2,%3};"
        : "+f"(c[0]), "+f"(c[1]), "+f"(c[2]), "+f"(c[3])
        : "r"(a[0]), "r"(a[1]), "r"(a[2]), "r"(a[3]), "r"(b[0]), "r"(b[1]));
}
// split x into bf16 hi (returned as bits) and residual float
__device__ __forceinline__ void bsplit(float x, uint16_t& hb, float& lo) {
    __nv_bfloat16 bh = __float2bfloat16(x);
    hb = __bfloat16_as_ushort(bh);
    lo = x - __bfloat162float(bh);
}
__device__ __forceinline__ uint32_t pkbf(float x, float y) {  // lo=x, hi=y
    uint32_t r;
    asm("cvt.rn.bf16x2.f32 %0, %1, %2;" : "=r"(r) : "f"(y), "f"(x));
    return r;
}

// ---------------------------------------------------------------------------
// Kernel 1: block-OR pooling of the dense mask -> g_bm (lower-tri only)
// ---------------------------------------------------------------------------
__global__ void block_mask_kernel(const int* __restrict__ mask) {
    if (blockIdx.x == 0 && threadIdx.x == 0) g_ctr = 0;
    int wid  = (blockIdx.x * blockDim.x + threadIdx.x) >> 5;
    int lane = threadIdx.x & 31;
    if (wid >= NH * NB * NB) return;
    int h   = wid >> 12;
    int rem = wid & (NB * NB - 1);
    int qb  = rem >> 6;
    int kb  = rem & (NB - 1);

    unsigned char res = 0;
    if (kb <= qb) {
        const int4* p = (const int4*)(mask +
            ((size_t)h * SEQ + (size_t)qb * 32 + lane) * SEQ + (size_t)kb * 32);
        int acc = 0;
        #pragma unroll
        for (int i = 0; i < 8; i++) {
            int4 a = p[i];
            acc |= a.x | a.y | a.z | a.w;
        }
        unsigned ballot = __ballot_sync(0xffffffffu, acc != 0);
        res = ballot ? 1 : 0;
    }
    if (lane == 0) g_bm[wid] = res;
}

// ---------------------------------------------------------------------------
// Kernel 2: block-sparse causal flash attention on mma.sync bf16 (3-term split)
// 256 threads = 8 warps; warp w owns 16 q-rows. P stays in registers:
// QK C-fragments convert directly into PV A-fragments.
// ---------------------------------------------------------------------------
__global__ void __launch_bounds__(256, 2)
attn_mma(const float* __restrict__ qry, const float* __restrict__ key,
         const float* __restrict__ val, float* __restrict__ out) {
    extern __shared__ char smem[];
    const uint32_t sb = smem_u32(smem);
    int* widx = (int*)smem;

    const int tid  = threadIdx.x;
    const int w    = tid >> 5;
    const int lane = tid & 31;
    const int R0   = w * 16;

    for (;;) {
        __syncthreads();
        if (tid == 0) *widx = atomicAdd(&g_ctr, 1);
        __syncthreads();
        const int idx = *widx;
        if (idx >= NWORK) break;
        const int qt = (NQT - 1) - (idx >> 4);   // heavy items first
        const int h  = idx & (NH - 1);

        // ---- stage Q (bf16 hi/lo, swizzled 128B rows) ----
        {
            const int r  = tid >> 1;
            const int dh = (tid & 1) * 32;
            const float4* src = (const float4*)(qry +
                ((size_t)(h * SEQ + qt * QTR + r)) * DIM + dh);
            #pragma unroll
            for (int i = 0; i < 8; i++) {
                float4 v = src[i];
                uint16_t h0, h1, h2, h3; float l0, l1, l2, l3;
                bsplit(v.x, h0, l0); bsplit(v.y, h1, l1);
                bsplit(v.z, h2, l2); bsplit(v.w, h3, l3);
                uint32_t a = swz((uint32_t)(r * 128 + (dh + i * 4) * 2));
                *(uint2*)(smem + OF_QHI + a) =
                    make_uint2(h0 | ((uint32_t)h1 << 16), h2 | ((uint32_t)h3 << 16));
                *(uint2*)(smem + OF_QLO + a) =
                    make_uint2(pkbf(l0, l1), pkbf(l2, l3));
            }
        }

        // ---- per-thread softmax/output state (2 rows: r0, r0+8) ----
        float Of[8][4];
        #pragma unroll
        for (int n = 0; n < 8; n++)
            #pragma unroll
            for (int j = 0; j < 4; j++) Of[n][j] = 0.f;
        float m0 = -1e30f, m1 = -1e30f, l0s = 0.f, l1s = 0.f;

        const int qb = qt * 4 + (w >> 1);
        const unsigned char* bmp = g_bm + ((size_t)h * NB + qb) * NB;
        const int gr0 = qt * QTR + R0 + (lane >> 2);
        const int gr1 = gr0 + 8;

        const int ktmax = 2 * qt + 1;
        for (int kt = 0; kt <= ktmax; kt++) {
            const int b0 = bmp[2 * kt], b1 = bmp[2 * kt + 1];
            if (!__syncthreads_or(b0 | b1)) continue;

            // ---- stage K and V (bf16 hi/lo, both row-major [r][d]) ----
            {
                const int r  = tid >> 2;
                const int db = (tid & 3) * 16;
                const float4* ksrc = (const float4*)(key +
                    ((size_t)(h * SEQ + kt * KTC + r)) * DIM + db);
                const float4* vsrc = (const float4*)(val +
                    ((size_t)(h * SEQ + kt * KTC + r)) * DIM + db);
                #pragma unroll
                for (int i = 0; i < 4; i++) {
                    uint32_t a = swz((uint32_t)(r * 128 + (db + i * 4) * 2));
                    float4 kv = ksrc[i];
                    uint16_t h0, h1, h2, h3; float q0, q1, q2, q3;
                    bsplit(kv.x, h0, q0); bsplit(kv.y, h1, q1);
                    bsplit(kv.z, h2, q2); bsplit(kv.w, h3, q3);
                    *(uint2*)(smem + OF_KHI + a) =
                        make_uint2(h0 | ((uint32_t)h1 << 16), h2 | ((uint32_t)h3 << 16));
                    *(uint2*)(smem + OF_KLO + a) =
                        make_uint2(pkbf(q0, q1), pkbf(q2, q3));
                    float4 vv = vsrc[i];
                    bsplit(vv.x, h0, q0); bsplit(vv.y, h1, q1);
                    bsplit(vv.z, h2, q2); bsplit(vv.w, h3, q3);
                    *(uint2*)(smem + OF_VHI + a) =
                        make_uint2(h0 | ((uint32_t)h1 << 16), h2 | ((uint32_t)h3 << 16));
                    *(uint2*)(smem + OF_VLO + a) =
                        make_uint2(pkbf(q0, q1), pkbf(q2, q3));
                }
            }
            __syncthreads();

            // ---- QK: S[16 x 64] per warp via mma, 3 split terms ----
            float Sf[8][4];
            #pragma unroll
            for (int n = 0; n < 8; n++)
                #pragma unroll
                for (int j = 0; j < 4; j++) Sf[n][j] = 0.f;

            #pragma unroll
            for (int ks = 0; ks < 4; ks++) {
                uint32_t ahi[4], alo[4];
                const int arow = R0 + (lane & 15);
                const int acol = ks * 16 + ((lane >> 4) << 3);
                const uint32_t ao = swz((uint32_t)(arow * 128 + acol * 2));
                ldsm4(sb + OF_QHI + ao, ahi);
                ldsm4(sb + OF_QLO + ao, alo);
                const int bcol = ks * 16 + ((lane & 8) ? 8 : 0);
                #pragma unroll
                for (int n = 0; n < 8; n++) {
                    uint32_t bhi[2], blo[2];
                    const uint32_t bo =
                        swz((uint32_t)((n * 8 + (lane & 7)) * 128 + bcol * 2));
                    ldsm2(sb + OF_KHI + bo, bhi);
                    ldsm2(sb + OF_KLO + bo, blo);
                    mma16816(Sf[n], ahi, bhi);
                    mma16816(Sf[n], ahi, blo);
                    mma16816(Sf[n], alo, bhi);
                }
            }

            // ---- mask + row max ----
            const bool dg = (kt >= 2 * qt);
            const int  cb = kt * KTC;
            const bool aL = (b0 != 0), aR = (b1 != 0);
            float rm0 = -1e30f, rm1 = -1e30f;
            #pragma unroll
            for (int n = 0; n < 8; n++) {
                const bool an = (n < 4) ? aL : aR;
                const int c0 = cb + n * 8 + ((lane & 3) << 1);
                const bool k00 = an && (!dg || c0     <= gr0);
                const bool k01 = an && (!dg || c0 + 1 <= gr0);
                const bool k10 = an && (!dg || c0     <= gr1);
                const bool k11 = an && (!dg || c0 + 1 <= gr1);
                Sf[n][0] = k00 ? Sf[n][0] : -1e30f;
                Sf[n][1] = k01 ? Sf[n][1] : -1e30f;
                Sf[n][2] = k10 ? Sf[n][2] : -1e30f;
                Sf[n][3] = k11 ? Sf[n][3] : -1e30f;
                rm0 = fmaxf(rm0, fmaxf(Sf[n][0], Sf[n][1]));
                rm1 = fmaxf(rm1, fmaxf(Sf[n][2], Sf[n][3]));
            }
            rm0 = fmaxf(rm0, __shfl_xor_sync(0xffffffffu, rm0, 1));
            rm0 = fmaxf(rm0, __shfl_xor_sync(0xffffffffu, rm0, 2));
            rm1 = fmaxf(rm1, __shfl_xor_sync(0xffffffffu, rm1, 1));
            rm1 = fmaxf(rm1, __shfl_xor_sync(0xffffffffu, rm1, 2));

            const float nm0 = fmaxf(m0, rm0), nm1 = fmaxf(m1, rm1);
            const float corr0 = __expf(m0 - nm0), corr1 = __expf(m1 - nm1);
            m0 = nm0; m1 = nm1;

            // ---- exp + build P A-fragments (hi/lo) directly in registers ----
            uint32_t Pah[4][4], Pal[4][4];
            float rs0 = 0.f, rs1 = 0.f;
            #pragma unroll
            for (int ks = 0; ks < 4; ks++) {
                #pragma unroll
                for (int j = 0; j < 2; j++) {
                    const int n = 2 * ks + j;
                    float e0 = __expf(Sf[n][0] - nm0);
                    float e1 = __expf(Sf[n][1] - nm0);
                    float e2 = __expf(Sf[n][2] - nm1);
                    float e3 = __expf(Sf[n][3] - nm1);
                    rs0 += e0 + e1;
                    rs1 += e2 + e3;
                    uint16_t hb0, hb1, hb2, hb3; float q0, q1, q2, q3;
                    bsplit(e0, hb0, q0); bsplit(e1, hb1, q1);
                    bsplit(e2, hb2, q2); bsplit(e3, hb3, q3);
                    Pah[ks][2 * j]     = hb0 | ((uint32_t)hb1 << 16);
                    Pah[ks][2 * j + 1] = hb2 | ((uint32_t)hb3 << 16);
                    Pal[ks][2 * j]     = pkbf(q0, q1);
                    Pal[ks][2 * j + 1] = pkbf(q2, q3);
                }
            }
            rs0 += __shfl_xor_sync(0xffffffffu, rs0, 1);
            rs0 += __shfl_xor_sync(0xffffffffu, rs0, 2);
            rs1 += __shfl_xor_sync(0xffffffffu, rs1, 1);
            rs1 += __shfl_xor_sync(0xffffffffu, rs1, 2);
            l0s = l0s * corr0 + rs0;
            l1s = l1s * corr1 + rs1;

            // ---- rescale O, then PV: O += P * V (3 split terms) ----
            #pragma unroll
            for (int n = 0; n < 8; n++) {
                Of[n][0] *= corr0; Of[n][1] *= corr0;
                Of[n][2] *= corr1; Of[n][3] *= corr1;
            }
            #pragma unroll
            for (int ks = 0; ks < 4; ks++) {
                const int vrow = ks * 16 + (lane & 15);
                #pragma unroll
                for (int n = 0; n < 8; n++) {
                    uint32_t vhi[2], vlo[2];
                    const uint32_t vo =
                        swz((uint32_t)(vrow * 128 + n * 8 * 2));
                    ldsm2t(sb + OF_VHI + vo, vhi);
                    ldsm2t(sb + OF_VLO + vo, vlo);
                    mma16816(Of[n], Pah[ks], vhi);
                    mma16816(Of[n], Pah[ks], vlo);
                    mma16816(Of[n], Pal[ks], vhi);
                }
            }
        }

        // ---- epilogue ----
        const float inv0 = (m0 > -1e29f) ? (1.f / l0s) : 0.f;
        const float inv1 = (m1 > -1e29f) ? (1.f / l1s) : 0.f;
        float* ob0 = out + ((size_t)(h * SEQ + gr0)) * DIM;
        float* ob1 = out + ((size_t)(h * SEQ + gr1)) * DIM;
        #pragma unroll
        for (int n = 0; n < 8; n++) {
            const int c = n * 8 + ((lane & 3) << 1);
            *(float2*)(ob0 + c) = make_float2(Of[n][0] * inv0, Of[n][1] * inv0);
            *(float2*)(ob1 + c) = make_float2(Of[n][2] * inv1, Of[n][3] * inv1);
        }
    }
}

// ---------------------------------------------------------------------------
// Launch
// ---------------------------------------------------------------------------
extern "C" void kernel_launch(void* const* d_in, const int* in_sizes, int n_in,
                              void* d_out, int out_size) {
    const float* qry  = (const float*)d_in[0];
    const float* key  = (const float*)d_in[1];
    const float* val  = (const float*)d_in[2];
    const int*   mask = (const int*)d_in[3];
    float* out = (float*)d_out;

    int total_warps = NH * NB * NB;
    int cta = (total_warps * 32 + 255) / 256;
    block_mask_kernel<<<cta, 256>>>(mask);

    static int attr_set = 0;
    if (!attr_set) {
        cudaFuncSetAttribute(attn_mma,
                             cudaFuncAttributeMaxDynamicSharedMemorySize, SMEM_BYTES);
        attr_set = 1;
    }
    attn_mma<<<2 * NSM, 256, SMEM_BYTES>>>(qry, key, val, out);
}

// round 11
// speedup vs baseline: 6.3467x; 1.5075x over previous
#include <cuda_runtime.h>
#include <cuda_bf16.h>
#include <math.h>
#include <stdint.h>

#define SEQ  2048
#define DIM  64
#define NH   16
#define NB   64            // 32-wide mask blocks per dim
#define QTR  128           // q rows per work item
#define KTC  64            // k cols per tile
#define NQT  (SEQ / QTR)   // 16
#define NWORK (NH * NQT)   // 256
#define NSM  152
#define NELEM (NH * SEQ * DIM)

__device__ unsigned char g_bm[NH * NB * NB];
__device__ int g_ctr;
// precomputed bf16 hi/lo planes (row-major [h][r][d], 128B rows)
__device__ uint16_t g_qhi[NELEM], g_qlo[NELEM];
__device__ uint16_t g_khi[NELEM], g_klo[NELEM];
__device__ uint16_t g_vhi[NELEM], g_vlo[NELEM];

// ---------------- smem layout (bytes) ----------------
#define OF_QHI 128
#define OF_QLO (OF_QHI + 16384)     // Q planes: 128 x 64 bf16 each
#define OF_KV  (OF_QLO + 16384)     // 2 stages x (KHI|KLO|VHI|VLO), 8KB each
#define STG_SZ 32768
#define SMEM_BYTES (OF_KV + 2 * STG_SZ)   // 98432

// ---------------------------------------------------------------------------
// helpers (baseline PTX only)
// ---------------------------------------------------------------------------
__device__ __forceinline__ uint32_t smem_u32(const void* p) {
    uint32_t a;
    asm("{ .reg .u64 t; cvta.to.shared.u64 t, %1; cvt.u32.u64 %0, t; }"
        : "=r"(a) : "l"(p));
    return a;
}
__device__ __forceinline__ uint32_t swz(uint32_t o) { return o ^ ((o >> 3) & 0x70); }

__device__ __forceinline__ void ldsm4(uint32_t addr, uint32_t r[4]) {
    asm volatile("ldmatrix.sync.aligned.m8n8.x4.shared.b16 {%0,%1,%2,%3}, [%4];"
        : "=r"(r[0]), "=r"(r[1]), "=r"(r[2]), "=r"(r[3]) : "r"(addr));
}
__device__ __forceinline__ void ldsm4t(uint32_t addr, uint32_t r[4]) {
    asm volatile("ldmatrix.sync.aligned.m8n8.x4.trans.shared.b16 {%0,%1,%2,%3}, [%4];"
        : "=r"(r[0]), "=r"(r[1]), "=r"(r[2]), "=r"(r[3]) : "r"(addr));
}
__device__ __forceinline__ void mma16816(float c[4], const uint32_t a[4],
                                         const uint32_t b[2]) {
    asm volatile(
        "mma.sync.aligned.m16n8k16.row.col.f32.bf16.bf16.f32 "
        "{%0,%1,%2,%3}, {%4,%5,%6,%7}, {%8,%9}, {%0,%1,%2,%3};"
        : "+f"(c[0]), "+f"(c[1]), "+f"(c[2]), "+f"(c[3])
        : "r"(a[0]), "r"(a[1]), "r"(a[2]), "r"(a[3]), "r"(b[0]), "r"(b[1]));
}
__device__ __forceinline__ void bsplit(float x, uint16_t& hb, float& lo) {
    __nv_bfloat16 bh = __float2bfloat16(x);
    hb = __bfloat16_as_ushort(bh);
    lo = x - __bfloat162float(bh);
}
__device__ __forceinline__ uint32_t pkbf(float x, float y) {  // lo=x, hi=y
    uint32_t r;
    asm("cvt.rn.bf16x2.f32 %0, %1, %2;" : "=r"(r) : "f"(y), "f"(x));
    return r;
}
__device__ __forceinline__ void cp16(uint32_t sd, const void* gs) {
    asm volatile("cp.async.cg.shared.global [%0], [%1], 16;"
                 :: "r"(sd), "l"(gs));
}
#define CP_COMMIT() asm volatile("cp.async.commit_group;" ::: "memory")
#define CP_WAIT0()  asm volatile("cp.async.wait_group 0;" ::: "memory")

// ---------------------------------------------------------------------------
// Kernel 1: block-OR pooling of the dense mask -> g_bm (lower-tri only)
// ---------------------------------------------------------------------------
__global__ void block_mask_kernel(const int* __restrict__ mask) {
    if (blockIdx.x == 0 && threadIdx.x == 0) g_ctr = 0;
    int wid  = (blockIdx.x * blockDim.x + threadIdx.x) >> 5;
    int lane = threadIdx.x & 31;
    if (wid >= NH * NB * NB) return;
    int h   = wid >> 12;
    int rem = wid & (NB * NB - 1);
    int qb  = rem >> 6;
    int kb  = rem & (NB - 1);

    unsigned char res = 0;
    if (kb <= qb) {
        const int4* p = (const int4*)(mask +
            ((size_t)h * SEQ + (size_t)qb * 32 + lane) * SEQ + (size_t)kb * 32);
        int acc = 0;
        #pragma unroll
        for (int i = 0; i < 8; i++) {
            int4 a = p[i];
            acc |= a.x | a.y | a.z | a.w;
        }
        unsigned ballot = __ballot_sync(0xffffffffu, acc != 0);
        res = ballot ? 1 : 0;
    }
    if (lane == 0) g_bm[wid] = res;
}

// ---------------------------------------------------------------------------
// Kernel 1b: fp32 -> bf16 hi/lo plane conversion (pure streaming)
// ---------------------------------------------------------------------------
__global__ void cvt_kernel(const float* __restrict__ src,
                           uint16_t* __restrict__ hi,
                           uint16_t* __restrict__ lo) {
    int i = (blockIdx.x * 256 + threadIdx.x) * 4;
    if (i >= NELEM) return;
    float4 v = *(const float4*)(src + i);
    uint16_t h0, h1, h2, h3;
    float l0, l1, l2, l3;
    bsplit(v.x, h0, l0); bsplit(v.y, h1, l1);
    bsplit(v.z, h2, l2); bsplit(v.w, h3, l3);
    *(uint2*)(hi + i) = make_uint2(h0 | ((uint32_t)h1 << 16),
                                   h2 | ((uint32_t)h3 << 16));
    *(uint2*)(lo + i) = make_uint2(pkbf(l0, l1), pkbf(l2, l3));
}

// ---------------------------------------------------------------------------
// Kernel 2: block-sparse causal flash attention, mma.sync bf16 3-term split,
// cp.async double-buffered K/V, bitmap tile loop, persistent work queue.
// 256 threads = 8 warps; warp owns 16 q-rows; P stays in registers.
// ---------------------------------------------------------------------------
__global__ void __launch_bounds__(256, 2)
attn_mma(float* __restrict__ out) {
    extern __shared__ char smem[];
    const uint32_t sb = smem_u32(smem);
    int* widx = (int*)smem;
    unsigned int* bmap = (unsigned int*)(smem + 8);

    const int tid  = threadIdx.x;
    const int w    = tid >> 5;
    const int lane = tid & 31;
    const int R0   = w * 16;

    for (;;) {
        __syncthreads();                       // prev item fully done
        if (tid == 0) { *widx = atomicAdd(&g_ctr, 1); *bmap = 0u; }
        __syncthreads();
        const int idx = *widx;
        if (idx >= NWORK) break;
        const int qt = (NQT - 1) - (idx >> 4); // heavy items first
        const int h  = idx & (NH - 1);

        // ---- stage Q planes via cp.async (pure copy) ----
        {
            const size_t gq = ((size_t)h * SEQ + (size_t)qt * QTR) * DIM;
            const char* qh = (const char*)(g_qhi + gq);
            const char* ql = (const char*)(g_qlo + gq);
            #pragma unroll
            for (int j = 0; j < 4; j++) {
                int ch = tid + j * 256;
                uint32_t so = swz((uint32_t)(ch * 16));
                cp16(sb + OF_QHI + so, qh + ch * 16);
                cp16(sb + OF_QLO + so, ql + ch * 16);
            }
        }

        // ---- per-warp activity bitmaps (lane = kt) ----
        const unsigned char* bmp = g_bm +
            ((size_t)h * NB + (qt * 4 + (w >> 1))) * NB;
        const int mb0 = bmp[2 * lane], mb1 = bmp[2 * lane + 1];
        const uint32_t actL = __ballot_sync(0xffffffffu, mb0 != 0);
        const uint32_t actR = __ballot_sync(0xffffffffu, mb1 != 0);
        if (lane == 0) atomicOr(bmap, actL | actR);
        __syncthreads();
        uint32_t bits = *bmap;

        // ---- per-thread softmax/output state (rows gr0, gr0+8) ----
        float Of[8][4];
        #pragma unroll
        for (int n = 0; n < 8; n++)
            #pragma unroll
            for (int j = 0; j < 4; j++) Of[n][j] = 0.f;
        float m0 = -1e30f, m1 = -1e30f, l0s = 0.f, l1s = 0.f;
        const int gr0 = qt * QTR + R0 + (lane >> 2);
        const int gr1 = gr0 + 8;

        int kt = -1, stage = 0;
        if (bits) {
            kt = __ffs(bits) - 1; bits &= bits - 1;
            // issue first K/V stage
            const size_t g = ((size_t)h * SEQ + (size_t)kt * KTC) * DIM;
            const uint32_t s0 = sb + OF_KV;
            #pragma unroll
            for (int j = 0; j < 2; j++) {
                int ch = tid + j * 256;
                uint32_t so = swz((uint32_t)(ch * 16));
                cp16(s0 + so,         (const char*)(g_khi + g) + ch * 16);
                cp16(s0 + 8192 + so,  (const char*)(g_klo + g) + ch * 16);
                cp16(s0 + 16384 + so, (const char*)(g_vhi + g) + ch * 16);
                cp16(s0 + 24576 + so, (const char*)(g_vlo + g) + ch * 16);
            }
            CP_COMMIT();
        }

        while (kt >= 0) {
            int nkt = -1;
            if (bits) { nkt = __ffs(bits) - 1; bits &= bits - 1; }

            CP_WAIT0();          // current tile (and Q on first iter) arrived
            __syncthreads();     // all threads' copies visible; prev compute done

            if (nkt >= 0) {      // prefetch next tile into other stage
                const size_t g = ((size_t)h * SEQ + (size_t)nkt * KTC) * DIM;
                const uint32_t s1 = sb + OF_KV + (stage ^ 1) * STG_SZ;
                #pragma unroll
                for (int j = 0; j < 2; j++) {
                    int ch = tid + j * 256;
                    uint32_t so = swz((uint32_t)(ch * 16));
                    cp16(s1 + so,         (const char*)(g_khi + g) + ch * 16);
                    cp16(s1 + 8192 + so,  (const char*)(g_klo + g) + ch * 16);
                    cp16(s1 + 16384 + so, (const char*)(g_vhi + g) + ch * 16);
                    cp16(s1 + 24576 + so, (const char*)(g_vlo + g) + ch * 16);
                }
                CP_COMMIT();
            }

            const uint32_t kbh = sb + OF_KV + stage * STG_SZ;
            const uint32_t kbl = kbh + 8192;
            const uint32_t vbh = kbh + 16384;
            const uint32_t vbl = kbh + 24576;

            // ---- QK: S[16 x 64] per warp, 3 split terms ----
            float Sf[8][4];
            #pragma unroll
            for (int n = 0; n < 8; n++)
                #pragma unroll
                for (int j = 0; j < 4; j++) Sf[n][j] = 0.f;

            #pragma unroll
            for (int ks = 0; ks < 4; ks++) {
                uint32_t ahi[4], alo[4];
                const int arow = R0 + (lane & 15);
                const int acol = ks * 16 + ((lane >> 4) << 3);
                const uint32_t ao = swz((uint32_t)(arow * 128 + acol * 2));
                ldsm4(sb + OF_QHI + ao, ahi);
                ldsm4(sb + OF_QLO + ao, alo);
                #pragma unroll
                for (int np = 0; np < 4; np++) {
                    const uint32_t bo = swz((uint32_t)(
                        (np * 16 + ((lane >> 4) << 3) + (lane & 7)) * 128 +
                        (ks * 16 + (((lane >> 3) & 1) << 3)) * 2));
                    uint32_t bh[4], bl[4];
                    ldsm4(kbh + bo, bh);
                    ldsm4(kbl + bo, bl);
                    mma16816(Sf[2 * np],     ahi, bh);
                    mma16816(Sf[2 * np],     ahi, bl);
                    mma16816(Sf[2 * np],     alo, bh);
                    mma16816(Sf[2 * np + 1], ahi, bh + 2);
                    mma16816(Sf[2 * np + 1], ahi, bl + 2);
                    mma16816(Sf[2 * np + 1], alo, bh + 2);
                }
            }

            // ---- mask + row max ----
            const bool aL = (actL >> kt) & 1, aR = (actR >> kt) & 1;
            const bool dg = (kt >= 2 * qt);
            const int  cb = kt * KTC;
            float rm0 = -1e30f, rm1 = -1e30f;
            #pragma unroll
            for (int n = 0; n < 8; n++) {
                const bool an = (n < 4) ? aL : aR;
                const int c0 = cb + n * 8 + ((lane & 3) << 1);
                const bool k00 = an && (!dg || c0     <= gr0);
                const bool k01 = an && (!dg || c0 + 1 <= gr0);
                const bool k10 = an && (!dg || c0     <= gr1);
                const bool k11 = an && (!dg || c0 + 1 <= gr1);
                Sf[n][0] = k00 ? Sf[n][0] : -1e30f;
                Sf[n][1] = k01 ? Sf[n][1] : -1e30f;
                Sf[n][2] = k10 ? Sf[n][2] : -1e30f;
                Sf[n][3] = k11 ? Sf[n][3] : -1e30f;
                rm0 = fmaxf(rm0, fmaxf(Sf[n][0], Sf[n][1]));
                rm1 = fmaxf(rm1, fmaxf(Sf[n][2], Sf[n][3]));
            }
            rm0 = fmaxf(rm0, __shfl_xor_sync(0xffffffffu, rm0, 1));
            rm0 = fmaxf(rm0, __shfl_xor_sync(0xffffffffu, rm0, 2));
            rm1 = fmaxf(rm1, __shfl_xor_sync(0xffffffffu, rm1, 1));
            rm1 = fmaxf(rm1, __shfl_xor_sync(0xffffffffu, rm1, 2));

            const float nm0 = fmaxf(m0, rm0), nm1 = fmaxf(m1, rm1);
            const float corr0 = __expf(m0 - nm0), corr1 = __expf(m1 - nm1);
            m0 = nm0; m1 = nm1;

            // ---- exp + P fragments (hi/lo) in registers ----
            uint32_t Pah[4][4], Pal[4][4];
            float rs0 = 0.f, rs1 = 0.f;
            #pragma unroll
            for (int ks = 0; ks < 4; ks++) {
                #pragma unroll
                for (int j = 0; j < 2; j++) {
                    const int n = 2 * ks + j;
                    float e0 = __expf(Sf[n][0] - nm0);
                    float e1 = __expf(Sf[n][1] - nm0);
                    float e2 = __expf(Sf[n][2] - nm1);
                    float e3 = __expf(Sf[n][3] - nm1);
                    rs0 += e0 + e1;
                    rs1 += e2 + e3;
                    uint16_t hb0, hb1, hb2, hb3;
                    float q0, q1, q2, q3;
                    bsplit(e0, hb0, q0); bsplit(e1, hb1, q1);
                    bsplit(e2, hb2, q2); bsplit(e3, hb3, q3);
                    Pah[ks][2 * j]     = hb0 | ((uint32_t)hb1 << 16);
                    Pah[ks][2 * j + 1] = hb2 | ((uint32_t)hb3 << 16);
                    Pal[ks][2 * j]     = pkbf(q0, q1);
                    Pal[ks][2 * j + 1] = pkbf(q2, q3);
                }
            }
            rs0 += __shfl_xor_sync(0xffffffffu, rs0, 1);
            rs0 += __shfl_xor_sync(0xffffffffu, rs0, 2);
            rs1 += __shfl_xor_sync(0xffffffffu, rs1, 1);
            rs1 += __shfl_xor_sync(0xffffffffu, rs1, 2);
            l0s = l0s * corr0 + rs0;
            l1s = l1s * corr1 + rs1;

            // ---- rescale O, then PV (3 split terms) ----
            #pragma unroll
            for (int n = 0; n < 8; n++) {
                Of[n][0] *= corr0; Of[n][1] *= corr0;
                Of[n][2] *= corr1; Of[n][3] *= corr1;
            }
            #pragma unroll
            for (int ks = 0; ks < 4; ks++) {
                #pragma unroll
                for (int np = 0; np < 4; np++) {
                    const uint32_t vo = swz((uint32_t)(
                        (ks * 16 + (lane & 15)) * 128 +
                        (np * 16 + ((lane >> 4) << 3)) * 2));
                    uint32_t vh[4], vl[4];
                    ldsm4t(vbh + vo, vh);
                    ldsm4t(vbl + vo, vl);
                    mma16816(Of[2 * np],     Pah[ks], vh);
                    mma16816(Of[2 * np],     Pah[ks], vl);
                    mma16816(Of[2 * np],     Pal[ks], vh);
                    mma16816(Of[2 * np + 1], Pah[ks], vh + 2);
                    mma16816(Of[2 * np + 1], Pah[ks], vl + 2);
                    mma16816(Of[2 * np + 1], Pal[ks], vh + 2);
                }
            }

            kt = nkt;
            stage ^= 1;
        }

        // ---- epilogue ----
        const float inv0 = (m0 > -1e29f) ? (1.f / l0s) : 0.f;
        const float inv1 = (m1 > -1e29f) ? (1.f / l1s) : 0.f;
        float* ob0 = out + ((size_t)(h * SEQ + gr0)) * DIM;
        float* ob1 = out + ((size_t)(h * SEQ + gr1)) * DIM;
        #pragma unroll
        for (int n = 0; n < 8; n++) {
            const int c = n * 8 + ((lane & 3) << 1);
            *(float2*)(ob0 + c) = make_float2(Of[n][0] * inv0, Of[n][1] * inv0);
            *(float2*)(ob1 + c) = make_float2(Of[n][2] * inv1, Of[n][3] * inv1);
        }
    }
}

// ---------------------------------------------------------------------------
// Launch
// ---------------------------------------------------------------------------
extern "C" void kernel_launch(void* const* d_in, const int* in_sizes, int n_in,
                              void* d_out, int out_size) {
    const float* qry  = (const float*)d_in[0];
    const float* key  = (const float*)d_in[1];
    const float* val  = (const float*)d_in[2];
    const int*   mask = (const int*)d_in[3];
    float* out = (float*)d_out;

    int total_warps = NH * NB * NB;
    int cta = (total_warps * 32 + 255) / 256;
    block_mask_kernel<<<cta, 256>>>(mask);

    uint16_t *qhi, *qlo, *khi, *klo, *vhi, *vlo;
    cudaGetSymbolAddress((void**)&qhi, g_qhi);
    cudaGetSymbolAddress((void**)&qlo, g_qlo);
    cudaGetSymbolAddress((void**)&khi, g_khi);
    cudaGetSymbolAddress((void**)&klo, g_klo);
    cudaGetSymbolAddress((void**)&vhi, g_vhi);
    cudaGetSymbolAddress((void**)&vlo, g_vlo);

    int cvt_cta = (NELEM / 4 + 255) / 256;
    cvt_kernel<<<cvt_cta, 256>>>(qry, qhi, qlo);
    cvt_kernel<<<cvt_cta, 256>>>(key, khi, klo);
    cvt_kernel<<<cvt_cta, 256>>>(val, vhi, vlo);

    static int attr_set = 0;
    if (!attr_set) {
        cudaFuncSetAttribute(attn_mma,
                             cudaFuncAttributeMaxDynamicSharedMemorySize, SMEM_BYTES);
        attr_set = 1;
    }
    attn_mma<<<2 * NSM, 256, SMEM_BYTES>>>(out);
}

// round 12
// speedup vs baseline: 6.9718x; 1.0985x over previous
#include <cuda_runtime.h>
#include <cuda_bf16.h>
#include <math.h>
#include <stdint.h>

#define SEQ  2048
#define DIM  64
#define NH   16
#define NB   64            // 32-wide mask blocks per dim
#define QTR  128           // q rows per work item
#define KTC  64            // k cols per tile
#define NQT  (SEQ / QTR)   // 16
#define NWORK (NH * NQT)   // 256
#define NSM  152
#define NELEM (NH * SEQ * DIM)
#define LOG2E 1.4426950408889634f

__device__ unsigned char g_bm[NH * NB * NB];
__device__ int g_ctr;
// precomputed bf16 hi/lo planes (row-major [h][r][d], 128B rows)
// Q planes are pre-scaled by log2(e) so softmax uses ex2 directly.
__device__ uint16_t g_qhi[NELEM], g_qlo[NELEM];
__device__ uint16_t g_khi[NELEM], g_klo[NELEM];
__device__ uint16_t g_vhi[NELEM], g_vlo[NELEM];

// ---------------- smem layout (bytes) ----------------
#define OF_QHI 128
#define OF_QLO (OF_QHI + 16384)     // Q planes: 128 x 64 bf16 each
#define OF_KV  (OF_QLO + 16384)     // 2 stages x (KHI|KLO|VHI|VLO), 8KB each
#define STG_SZ 32768
#define SMEM_BYTES (OF_KV + 2 * STG_SZ)   // 98432

// ---------------------------------------------------------------------------
// helpers (baseline PTX only)
// ---------------------------------------------------------------------------
__device__ __forceinline__ uint32_t smem_u32(const void* p) {
    uint32_t a;
    asm("{ .reg .u64 t; cvta.to.shared.u64 t, %1; cvt.u32.u64 %0, t; }"
        : "=r"(a) : "l"(p));
    return a;
}
__device__ __forceinline__ uint32_t swz(uint32_t o) { return o ^ ((o >> 3) & 0x70); }

__device__ __forceinline__ void ldsm4(uint32_t addr, uint32_t r[4]) {
    asm volatile("ldmatrix.sync.aligned.m8n8.x4.shared.b16 {%0,%1,%2,%3}, [%4];"
        : "=r"(r[0]), "=r"(r[1]), "=r"(r[2]), "=r"(r[3]) : "r"(addr));
}
__device__ __forceinline__ void ldsm4t(uint32_t addr, uint32_t r[4]) {
    asm volatile("ldmatrix.sync.aligned.m8n8.x4.trans.shared.b16 {%0,%1,%2,%3}, [%4];"
        : "=r"(r[0]), "=r"(r[1]), "=r"(r[2]), "=r"(r[3]) : "r"(addr));
}
__device__ __forceinline__ void mma16816(float c[4], const uint32_t a[4],
                                         const uint32_t b[2]) {
    asm volatile(
        "mma.sync.aligned.m16n8k16.row.col.f32.bf16.bf16.f32 "
        "{%0,%1,%2,%3}, {%4,%5,%6,%7}, {%8,%9}, {%0,%1,%2,%3};"
        : "+f"(c[0]), "+f"(c[1]), "+f"(c[2]), "+f"(c[3])
        : "r"(a[0]), "r"(a[1]), "r"(a[2]), "r"(a[3]), "r"(b[0]), "r"(b[1]));
}
__device__ __forceinline__ uint32_t pkbf(float x, float y) {  // lo=x, hi=y
    uint32_t r;
    asm("cvt.rn.bf16x2.f32 %0, %1, %2;" : "=r"(r) : "f"(y), "f"(x));
    return r;
}
__device__ __forceinline__ float ex2(float x) {
    float r;
    asm("ex2.approx.f32 %0, %1;" : "=f"(r) : "f"(x));
    return r;
}
__device__ __forceinline__ void cp16(uint32_t sd, const void* gs) {
    asm volatile("cp.async.cg.shared.global [%0], [%1], 16;"
                 :: "r"(sd), "l"(gs));
}
#define CP_COMMIT() asm volatile("cp.async.commit_group;" ::: "memory")
#define CP_WAIT0()  asm volatile("cp.async.wait_group 0;" ::: "memory")

// ---------------------------------------------------------------------------
// Kernel 1: block-OR pooling of the dense mask -> g_bm (lower-tri only)
// ---------------------------------------------------------------------------
__global__ void block_mask_kernel(const int* __restrict__ mask) {
    if (blockIdx.x == 0 && threadIdx.x == 0) g_ctr = 0;
    int wid  = (blockIdx.x * blockDim.x + threadIdx.x) >> 5;
    int lane = threadIdx.x & 31;
    if (wid >= NH * NB * NB) return;
    int h   = wid >> 12;
    int rem = wid & (NB * NB - 1);
    int qb  = rem >> 6;
    int kb  = rem & (NB - 1);

    unsigned char res = 0;
    if (kb <= qb) {
        const int4* p = (const int4*)(mask +
            ((size_t)h * SEQ + (size_t)qb * 32 + lane) * SEQ + (size_t)kb * 32);
        int acc = 0;
        #pragma unroll
        for (int i = 0; i < 8; i++) {
            int4 a = p[i];
            acc |= a.x | a.y | a.z | a.w;
        }
        unsigned ballot = __ballot_sync(0xffffffffu, acc != 0);
        res = ballot ? 1 : 0;
    }
    if (lane == 0) g_bm[wid] = res;
}

// ---------------------------------------------------------------------------
// Kernel 1b: fused fp32 -> bf16 hi/lo plane conversion for Q (x log2e), K, V
// ---------------------------------------------------------------------------
#define CVT_CTAS (NELEM / 1024)    // 2048 CTAs per tensor
__global__ void cvt_all(const float* __restrict__ q,
                        const float* __restrict__ k,
                        const float* __restrict__ v) {
    const int which = blockIdx.x / CVT_CTAS;
    const int cb    = blockIdx.x % CVT_CTAS;
    const int i     = (cb * 256 + threadIdx.x) * 4;
    const float* src = (which == 0) ? q : (which == 1) ? k : v;
    uint16_t* hi = (which == 0) ? g_qhi : (which == 1) ? g_khi : g_vhi;
    uint16_t* lo = (which == 0) ? g_qlo : (which == 1) ? g_klo : g_vlo;
    const float sc = (which == 0) ? LOG2E : 1.0f;

    float4 x = *(const float4*)(src + i);
    x.x *= sc; x.y *= sc; x.z *= sc; x.w *= sc;
    uint32_t h01 = pkbf(x.x, x.y);
    uint32_t h23 = pkbf(x.z, x.w);
    float h0 = __uint_as_float(h01 << 16);
    float h1 = __uint_as_float(h01 & 0xFFFF0000u);
    float h2 = __uint_as_float(h23 << 16);
    float h3 = __uint_as_float(h23 & 0xFFFF0000u);
    *(uint2*)(hi + i) = make_uint2(h01, h23);
    *(uint2*)(lo + i) = make_uint2(pkbf(x.x - h0, x.y - h1),
                                   pkbf(x.z - h2, x.w - h3));
}

// ---------------------------------------------------------------------------
// Kernel 2: block-sparse causal flash attention, mma.sync bf16 3-term split,
// cp.async double-buffered K/V, bitmap tile loop, persistent work queue.
// Scores arrive in log2 domain (Q pre-scaled) -> softmax is bare ex2.
// ---------------------------------------------------------------------------
__global__ void __launch_bounds__(256, 2)
attn_mma(float* __restrict__ out) {
    extern __shared__ char smem[];
    const uint32_t sb = smem_u32(smem);
    int* widx = (int*)smem;
    unsigned int* bmap = (unsigned int*)(smem + 8);

    const int tid  = threadIdx.x;
    const int w    = tid >> 5;
    const int lane = tid & 31;
    const int R0   = w * 16;

    for (;;) {
        __syncthreads();                       // prev item fully done
        if (tid == 0) { *widx = atomicAdd(&g_ctr, 1); *bmap = 0u; }
        __syncthreads();
        const int idx = *widx;
        if (idx >= NWORK) break;
        const int qt = (NQT - 1) - (idx >> 4); // heavy items first
        const int h  = idx & (NH - 1);

        // ---- stage Q planes via cp.async (pure copy) ----
        {
            const size_t gq = ((size_t)h * SEQ + (size_t)qt * QTR) * DIM;
            const char* qh = (const char*)(g_qhi + gq);
            const char* ql = (const char*)(g_qlo + gq);
            #pragma unroll
            for (int j = 0; j < 4; j++) {
                int ch = tid + j * 256;
                uint32_t so = swz((uint32_t)(ch * 16));
                cp16(sb + OF_QHI + so, qh + ch * 16);
                cp16(sb + OF_QLO + so, ql + ch * 16);
            }
        }

        // ---- per-warp activity bitmaps (lane = kt) ----
        const unsigned char* bmp = g_bm +
            ((size_t)h * NB + (qt * 4 + (w >> 1))) * NB;
        const int mb0 = bmp[2 * lane], mb1 = bmp[2 * lane + 1];
        const uint32_t actL = __ballot_sync(0xffffffffu, mb0 != 0);
        const uint32_t actR = __ballot_sync(0xffffffffu, mb1 != 0);
        if (lane == 0) atomicOr(bmap, actL | actR);
        __syncthreads();
        uint32_t bits = *bmap;

        // ---- per-thread softmax/output state (rows gr0, gr0+8) ----
        float Of[8][4];
        #pragma unroll
        for (int n = 0; n < 8; n++)
            #pragma unroll
            for (int j = 0; j < 4; j++) Of[n][j] = 0.f;
        float m0 = -1e30f, m1 = -1e30f, l0s = 0.f, l1s = 0.f;
        const int gr0 = qt * QTR + R0 + (lane >> 2);
        const int gr1 = gr0 + 8;

        int kt = -1, stage = 0;
        if (bits) {
            kt = __ffs(bits) - 1; bits &= bits - 1;
            const size_t g = ((size_t)h * SEQ + (size_t)kt * KTC) * DIM;
            const uint32_t s0 = sb + OF_KV;
            #pragma unroll
            for (int j = 0; j < 2; j++) {
                int ch = tid + j * 256;
                uint32_t so = swz((uint32_t)(ch * 16));
                cp16(s0 + so,         (const char*)(g_khi + g) + ch * 16);
                cp16(s0 + 8192 + so,  (const char*)(g_klo + g) + ch * 16);
                cp16(s0 + 16384 + so, (const char*)(g_vhi + g) + ch * 16);
                cp16(s0 + 24576 + so, (const char*)(g_vlo + g) + ch * 16);
            }
            CP_COMMIT();
        }

        while (kt >= 0) {
            int nkt = -1;
            if (bits) { nkt = __ffs(bits) - 1; bits &= bits - 1; }

            CP_WAIT0();          // current tile (and Q on first iter) arrived
            __syncthreads();     // all threads' copies visible; prev compute done

            if (nkt >= 0) {      // prefetch next tile into other stage
                const size_t g = ((size_t)h * SEQ + (size_t)nkt * KTC) * DIM;
                const uint32_t s1 = sb + OF_KV + (stage ^ 1) * STG_SZ;
                #pragma unroll
                for (int j = 0; j < 2; j++) {
                    int ch = tid + j * 256;
                    uint32_t so = swz((uint32_t)(ch * 16));
                    cp16(s1 + so,         (const char*)(g_khi + g) + ch * 16);
                    cp16(s1 + 8192 + so,  (const char*)(g_klo + g) + ch * 16);
                    cp16(s1 + 16384 + so, (const char*)(g_vhi + g) + ch * 16);
                    cp16(s1 + 24576 + so, (const char*)(g_vlo + g) + ch * 16);
                }
                CP_COMMIT();
            }

            const uint32_t kbh = sb + OF_KV + stage * STG_SZ;
            const uint32_t kbl = kbh + 8192;
            const uint32_t vbh = kbh + 16384;
            const uint32_t vbl = kbh + 24576;

            // ---- QK: S[16 x 64] per warp, 3 split terms ----
            float Sf[8][4];
            #pragma unroll
            for (int n = 0; n < 8; n++)
                #pragma unroll
                for (int j = 0; j < 4; j++) Sf[n][j] = 0.f;

            #pragma unroll
            for (int ks = 0; ks < 4; ks++) {
                uint32_t ahi[4], alo[4];
                const int arow = R0 + (lane & 15);
                const int acol = ks * 16 + ((lane >> 4) << 3);
                const uint32_t ao = swz((uint32_t)(arow * 128 + acol * 2));
                ldsm4(sb + OF_QHI + ao, ahi);
                ldsm4(sb + OF_QLO + ao, alo);
                #pragma unroll
                for (int np = 0; np < 4; np++) {
                    const uint32_t bo = swz((uint32_t)(
                        (np * 16 + ((lane >> 4) << 3) + (lane & 7)) * 128 +
                        (ks * 16 + (((lane >> 3) & 1) << 3)) * 2));
                    uint32_t bh[4], bl[4];
                    ldsm4(kbh + bo, bh);
                    ldsm4(kbl + bo, bl);
                    mma16816(Sf[2 * np],     ahi, bh);
                    mma16816(Sf[2 * np],     ahi, bl);
                    mma16816(Sf[2 * np],     alo, bh);
                    mma16816(Sf[2 * np + 1], ahi, bh + 2);
                    mma16816(Sf[2 * np + 1], ahi, bl + 2);
                    mma16816(Sf[2 * np + 1], alo, bh + 2);
                }
            }

            // ---- mask (3 paths) + row max ----
            const bool aL = (actL >> kt) & 1, aR = (actR >> kt) & 1;
            const bool dg = (kt >= 2 * qt);
            float rm0 = -1e30f, rm1 = -1e30f;
            if (!dg && aL && aR) {
                // fast path: no masking at all
                #pragma unroll
                for (int n = 0; n < 8; n++) {
                    rm0 = fmaxf(rm0, fmaxf(Sf[n][0], Sf[n][1]));
                    rm1 = fmaxf(rm1, fmaxf(Sf[n][2], Sf[n][3]));
                }
            } else if (!dg) {
                // additive bias path (partial half-activity)
                const float bL = aL ? 0.f : -1e30f;
                const float bR = aR ? 0.f : -1e30f;
                #pragma unroll
                for (int n = 0; n < 8; n++) {
                    const float b = (n < 4) ? bL : bR;
                    Sf[n][0] += b; Sf[n][1] += b;
                    Sf[n][2] += b; Sf[n][3] += b;
                    rm0 = fmaxf(rm0, fmaxf(Sf[n][0], Sf[n][1]));
                    rm1 = fmaxf(rm1, fmaxf(Sf[n][2], Sf[n][3]));
                }
            } else {
                // diagonal: per-element causal + activity predicates
                const int cb = kt * KTC;
                #pragma unroll
                for (int n = 0; n < 8; n++) {
                    const bool an = (n < 4) ? aL : aR;
                    const int c0 = cb + n * 8 + ((lane & 3) << 1);
                    const bool k00 = an && (c0     <= gr0);
                    const bool k01 = an && (c0 + 1 <= gr0);
                    const bool k10 = an && (c0     <= gr1);
                    const bool k11 = an && (c0 + 1 <= gr1);
                    Sf[n][0] = k00 ? Sf[n][0] : -1e30f;
                    Sf[n][1] = k01 ? Sf[n][1] : -1e30f;
                    Sf[n][2] = k10 ? Sf[n][2] : -1e30f;
                    Sf[n][3] = k11 ? Sf[n][3] : -1e30f;
                    rm0 = fmaxf(rm0, fmaxf(Sf[n][0], Sf[n][1]));
                    rm1 = fmaxf(rm1, fmaxf(Sf[n][2], Sf[n][3]));
                }
            }
            rm0 = fmaxf(rm0, __shfl_xor_sync(0xffffffffu, rm0, 1));
            rm0 = fmaxf(rm0, __shfl_xor_sync(0xffffffffu, rm0, 2));
            rm1 = fmaxf(rm1, __shfl_xor_sync(0xffffffffu, rm1, 1));
            rm1 = fmaxf(rm1, __shfl_xor_sync(0xffffffffu, rm1, 2));

            const float nm0 = fmaxf(m0, rm0), nm1 = fmaxf(m1, rm1);
            const float corr0 = ex2(m0 - nm0), corr1 = ex2(m1 - nm1);
            m0 = nm0; m1 = nm1;

            // ---- ex2 + packed P hi/lo fragments in registers ----
            uint32_t Pah[4][4], Pal[4][4];
            float rs0 = 0.f, rs1 = 0.f;
            #pragma unroll
            for (int ks = 0; ks < 4; ks++) {
                #pragma unroll
                for (int j = 0; j < 2; j++) {
                    const int n = 2 * ks + j;
                    float e0 = ex2(Sf[n][0] - nm0);
                    float e1 = ex2(Sf[n][1] - nm0);
                    float e2 = ex2(Sf[n][2] - nm1);
                    float e3 = ex2(Sf[n][3] - nm1);
                    rs0 += e0 + e1;
                    rs1 += e2 + e3;
                    uint32_t h01 = pkbf(e0, e1);
                    uint32_t h23 = pkbf(e2, e3);
                    float h0f = __uint_as_float(h01 << 16);
                    float h1f = __uint_as_float(h01 & 0xFFFF0000u);
                    float h2f = __uint_as_float(h23 << 16);
                    float h3f = __uint_as_float(h23 & 0xFFFF0000u);
                    Pah[ks][2 * j]     = h01;
                    Pah[ks][2 * j + 1] = h23;
                    Pal[ks][2 * j]     = pkbf(e0 - h0f, e1 - h1f);
                    Pal[ks][2 * j + 1] = pkbf(e2 - h2f, e3 - h3f);
                }
            }
            rs0 += __shfl_xor_sync(0xffffffffu, rs0, 1);
            rs0 += __shfl_xor_sync(0xffffffffu, rs0, 2);
            rs1 += __shfl_xor_sync(0xffffffffu, rs1, 1);
            rs1 += __shfl_xor_sync(0xffffffffu, rs1, 2);
            l0s = l0s * corr0 + rs0;
            l1s = l1s * corr1 + rs1;

            // ---- rescale O, then PV (3 split terms) ----
            #pragma unroll
            for (int n = 0; n < 8; n++) {
                Of[n][0] *= corr0; Of[n][1] *= corr0;
                Of[n][2] *= corr1; Of[n][3] *= corr1;
            }
            #pragma unroll
            for (int ks = 0; ks < 4; ks++) {
                #pragma unroll
                for (int np = 0; np < 4; np++) {
                    const uint32_t vo = swz((uint32_t)(
                        (ks * 16 + (lane & 15)) * 128 +
                        (np * 16 + ((lane >> 4) << 3)) * 2));
                    uint32_t vh[4], vl[4];
                    ldsm4t(vbh + vo, vh);
                    ldsm4t(vbl + vo, vl);
                    mma16816(Of[2 * np],     Pah[ks], vh);
                    mma16816(Of[2 * np],     Pah[ks], vl);
                    mma16816(Of[2 * np],     Pal[ks], vh);
                    mma16816(Of[2 * np + 1], Pah[ks], vh + 2);
                    mma16816(Of[2 * np + 1], Pah[ks], vl + 2);
                    mma16816(Of[2 * np + 1], Pal[ks], vh + 2);
                }
            }

            kt = nkt;
            stage ^= 1;
        }

        // ---- epilogue ----
        const float inv0 = (m0 > -1e29f) ? (1.f / l0s) : 0.f;
        const float inv1 = (m1 > -1e29f) ? (1.f / l1s) : 0.f;
        float* ob0 = out + ((size_t)(h * SEQ + gr0)) * DIM;
        float* ob1 = out + ((size_t)(h * SEQ + gr1)) * DIM;
        #pragma unroll
        for (int n = 0; n < 8; n++) {
            const int c = n * 8 + ((lane & 3) << 1);
            *(float2*)(ob0 + c) = make_float2(Of[n][0] * inv0, Of[n][1] * inv0);
            *(float2*)(ob1 + c) = make_float2(Of[n][2] * inv1, Of[n][3] * inv1);
        }
    }
}

// ---------------------------------------------------------------------------
// Launch
// ---------------------------------------------------------------------------
extern "C" void kernel_launch(void* const* d_in, const int* in_sizes, int n_in,
                              void* d_out, int out_size) {
    const float* qry  = (const float*)d_in[0];
    const float* key  = (const float*)d_in[1];
    const float* val  = (const float*)d_in[2];
    const int*   mask = (const int*)d_in[3];
    float* out = (float*)d_out;

    int total_warps = NH * NB * NB;
    int cta = (total_warps * 32 + 255) / 256;
    block_mask_kernel<<<cta, 256>>>(mask);

    cvt_all<<<3 * CVT_CTAS, 256>>>(qry, key, val);

    static int attr_set = 0;
    if (!attr_set) {
        cudaFuncSetAttribute(attn_mma,
                             cudaFuncAttributeMaxDynamicSharedMemorySize, SMEM_BYTES);
        attr_set = 1;
    }
    attn_mma<<<2 * NSM, 256, SMEM_BYTES>>>(out);
}

// round 13
// speedup vs baseline: 8.3996x; 1.2048x over previous
#include <cuda_runtime.h>
#include <cuda_bf16.h>
#include <math.h>
#include <stdint.h>

#define SEQ  2048
#define DIM  64
#define NH   16
#define NB   64            // 32-wide mask blocks per dim
#define QTR  128           // q rows per work item
#define KTC  64            // k cols per tile
#define NQT  (SEQ / QTR)   // 16
#define NWORK (NH * NQT)   // 256
#define NSM  152
#define NELEM (NH * SEQ * DIM)
#define LOG2E 1.4426950408889634f

__device__ unsigned char g_bm[NH * NB * NB];
__device__ int g_ctr;
// precomputed bf16 hi/lo planes (row-major [h][r][d], 128B rows)
// Q planes are pre-scaled by log2(e) so softmax uses ex2 directly.
__device__ uint16_t g_qhi[NELEM], g_qlo[NELEM];
__device__ uint16_t g_khi[NELEM], g_klo[NELEM];
__device__ uint16_t g_vhi[NELEM], g_vlo[NELEM];

// ---------------- smem layout (bytes) ----------------
#define OF_QHI 128
#define OF_QLO (OF_QHI + 16384)     // Q planes: 128 x 64 bf16 each
#define OF_KV  (OF_QLO + 16384)     // 2 stages x (KHI|KLO|VHI|VLO), 8KB each
#define STG_SZ 32768
#define SMEM_BYTES (OF_KV + 2 * STG_SZ)   // 98432

// ---------------------------------------------------------------------------
// helpers (baseline PTX only)
// ---------------------------------------------------------------------------
__device__ __forceinline__ uint32_t smem_u32(const void* p) {
    uint32_t a;
    asm("{ .reg .u64 t; cvta.to.shared.u64 t, %1; cvt.u32.u64 %0, t; }"
        : "=r"(a) : "l"(p));
    return a;
}
__device__ __forceinline__ uint32_t swz(uint32_t o) { return o ^ ((o >> 3) & 0x70); }

__device__ __forceinline__ void ldsm4(uint32_t addr, uint32_t r[4]) {
    asm volatile("ldmatrix.sync.aligned.m8n8.x4.shared.b16 {%0,%1,%2,%3}, [%4];"
        : "=r"(r[0]), "=r"(r[1]), "=r"(r[2]), "=r"(r[3]) : "r"(addr));
}
__device__ __forceinline__ void ldsm4t(uint32_t addr, uint32_t r[4]) {
    asm volatile("ldmatrix.sync.aligned.m8n8.x4.trans.shared.b16 {%0,%1,%2,%3}, [%4];"
        : "=r"(r[0]), "=r"(r[1]), "=r"(r[2]), "=r"(r[3]) : "r"(addr));
}
__device__ __forceinline__ void mma16816(float c[4], const uint32_t a[4],
                                         const uint32_t b[2]) {
    asm volatile(
        "mma.sync.aligned.m16n8k16.row.col.f32.bf16.bf16.f32 "
        "{%0,%1,%2,%3}, {%4,%5,%6,%7}, {%8,%9}, {%0,%1,%2,%3};"
        : "+f"(c[0]), "+f"(c[1]), "+f"(c[2]), "+f"(c[3])
        : "r"(a[0]), "r"(a[1]), "r"(a[2]), "r"(a[3]), "r"(b[0]), "r"(b[1]));
}
__device__ __forceinline__ uint32_t pkbf(float x, float y) {  // lo=x, hi=y
    uint32_t r;
    asm("cvt.rn.bf16x2.f32 %0, %1, %2;" : "=r"(r) : "f"(y), "f"(x));
    return r;
}
__device__ __forceinline__ float ex2(float x) {
    float r;
    asm("ex2.approx.f32 %0, %1;" : "=f"(r) : "f"(x));
    return r;
}
__device__ __forceinline__ void cp16(uint32_t sd, const void* gs) {
    asm volatile("cp.async.cg.shared.global [%0], [%1], 16;"
                 :: "r"(sd), "l"(gs));
}
#define CP_COMMIT() asm volatile("cp.async.commit_group;" ::: "memory")
#define CP_WAIT0()  asm volatile("cp.async.wait_group 0;" ::: "memory")

// ---------------------------------------------------------------------------
// Kernel 1: block-OR pooling of the dense mask -> g_bm (lower-tri only).
// Sampling: read row 0 of each 32x32 block (32 ints). Any nonzero -> active
// (certain). All-zero (prob 2^-32) -> exact fallback scans rows 1..31.
// 8 lanes x int4 per block; 4 consecutive kb-blocks per warp = 512B coalesced.
// ---------------------------------------------------------------------------
__global__ void block_mask_kernel(const int* __restrict__ mask) {
    if (blockIdx.x == 0 && threadIdx.x == 0) g_ctr = 0;
    const int gwarp = (blockIdx.x * blockDim.x + threadIdx.x) >> 5;
    const int lane  = threadIdx.x & 31;
    const int grp   = lane >> 3;          // 4 block-groups per warp
    const int sub   = lane & 7;           // lane within group
    const int blk   = gwarp * 4 + grp;
    if (blk >= NH * NB * NB) return;
    const int h   = blk >> 12;
    const int rem = blk & (NB * NB - 1);
    const int qb  = rem >> 6;
    const int kb  = rem & (NB - 1);
    const unsigned gm = 0xFFu << (grp * 8);

    unsigned char res = 0;
    if (kb <= qb) {
        const int* base = mask + ((size_t)h * SEQ + (size_t)qb * 32) * SEQ
                               + (size_t)kb * 32;
        int4 a = *((const int4*)base + sub);
        unsigned bal = __ballot_sync(gm, (a.x | a.y | a.z | a.w) != 0);
        if (bal) {
            res = 1;
        } else {
            // exact fallback (astronomically rare): scan rows 1..31
            int acc = 0;
            for (int r = 1; r < 32; r++) {
                int4 b = *((const int4*)(base + (size_t)r * SEQ) + sub);
                acc |= b.x | b.y | b.z | b.w;
            }
            unsigned bal2 = __ballot_sync(gm, acc != 0);
            res = bal2 ? 1 : 0;
        }
    }
    if (sub == 0) g_bm[blk] = res;
}

// ---------------------------------------------------------------------------
// Kernel 1b: fused fp32 -> bf16 hi/lo plane conversion for Q (x log2e), K, V
// ---------------------------------------------------------------------------
#define CVT_CTAS (NELEM / 1024)    // 2048 CTAs per tensor
__global__ void cvt_all(const float* __restrict__ q,
                        const float* __restrict__ k,
                        const float* __restrict__ v) {
    const int which = blockIdx.x / CVT_CTAS;
    const int cb    = blockIdx.x % CVT_CTAS;
    const int i     = (cb * 256 + threadIdx.x) * 4;
    const float* src = (which == 0) ? q : (which == 1) ? k : v;
    uint16_t* hi = (which == 0) ? g_qhi : (which == 1) ? g_khi : g_vhi;
    uint16_t* lo = (which == 0) ? g_qlo : (which == 1) ? g_klo : g_vlo;
    const float sc = (which == 0) ? LOG2E : 1.0f;

    float4 x = *(const float4*)(src + i);
    x.x *= sc; x.y *= sc; x.z *= sc; x.w *= sc;
    uint32_t h01 = pkbf(x.x, x.y);
    uint32_t h23 = pkbf(x.z, x.w);
    float h0 = __uint_as_float(h01 << 16);
    float h1 = __uint_as_float(h01 & 0xFFFF0000u);
    float h2 = __uint_as_float(h23 << 16);
    float h3 = __uint_as_float(h23 & 0xFFFF0000u);
    *(uint2*)(hi + i) = make_uint2(h01, h23);
    *(uint2*)(lo + i) = make_uint2(pkbf(x.x - h0, x.y - h1),
                                   pkbf(x.z - h2, x.w - h3));
}

// ---------------------------------------------------------------------------
// Kernel 2: block-sparse causal flash attention, mma.sync bf16 3-term split,
// cp.async double-buffered K/V, bitmap tile loop, persistent work queue.
// Scores arrive in log2 domain (Q pre-scaled) -> softmax is bare ex2.
// ---------------------------------------------------------------------------
__global__ void __launch_bounds__(256, 2)
attn_mma(float* __restrict__ out) {
    extern __shared__ char smem[];
    const uint32_t sb = smem_u32(smem);
    int* widx = (int*)smem;
    unsigned int* bmap = (unsigned int*)(smem + 8);

    const int tid  = threadIdx.x;
    const int w    = tid >> 5;
    const int lane = tid & 31;
    const int R0   = w * 16;

    for (;;) {
        __syncthreads();                       // prev item fully done
        if (tid == 0) { *widx = atomicAdd(&g_ctr, 1); *bmap = 0u; }
        __syncthreads();
        const int idx = *widx;
        if (idx >= NWORK) break;
        const int qt = (NQT - 1) - (idx >> 4); // heavy items first
        const int h  = idx & (NH - 1);

        // ---- stage Q planes via cp.async (pure copy) ----
        {
            const size_t gq = ((size_t)h * SEQ + (size_t)qt * QTR) * DIM;
            const char* qh = (const char*)(g_qhi + gq);
            const char* ql = (const char*)(g_qlo + gq);
            #pragma unroll
            for (int j = 0; j < 4; j++) {
                int ch = tid + j * 256;
                uint32_t so = swz((uint32_t)(ch * 16));
                cp16(sb + OF_QHI + so, qh + ch * 16);
                cp16(sb + OF_QLO + so, ql + ch * 16);
            }
        }

        // ---- per-warp activity bitmaps (lane = kt) ----
        const unsigned char* bmp = g_bm +
            ((size_t)h * NB + (qt * 4 + (w >> 1))) * NB;
        const int mb0 = bmp[2 * lane], mb1 = bmp[2 * lane + 1];
        const uint32_t actL = __ballot_sync(0xffffffffu, mb0 != 0);
        const uint32_t actR = __ballot_sync(0xffffffffu, mb1 != 0);
        if (lane == 0) atomicOr(bmap, actL | actR);
        __syncthreads();
        uint32_t bits = *bmap;

        // ---- per-thread softmax/output state (rows gr0, gr0+8) ----
        float Of[8][4];
        #pragma unroll
        for (int n = 0; n < 8; n++)
            #pragma unroll
            for (int j = 0; j < 4; j++) Of[n][j] = 0.f;
        float m0 = -1e30f, m1 = -1e30f, l0s = 0.f, l1s = 0.f;
        const int gr0 = qt * QTR + R0 + (lane >> 2);
        const int gr1 = gr0 + 8;

        int kt = -1, stage = 0;
        if (bits) {
            kt = __ffs(bits) - 1; bits &= bits - 1;
            const size_t g = ((size_t)h * SEQ + (size_t)kt * KTC) * DIM;
            const uint32_t s0 = sb + OF_KV;
            #pragma unroll
            for (int j = 0; j < 2; j++) {
                int ch = tid + j * 256;
                uint32_t so = swz((uint32_t)(ch * 16));
                cp16(s0 + so,         (const char*)(g_khi + g) + ch * 16);
                cp16(s0 + 8192 + so,  (const char*)(g_klo + g) + ch * 16);
                cp16(s0 + 16384 + so, (const char*)(g_vhi + g) + ch * 16);
                cp16(s0 + 24576 + so, (const char*)(g_vlo + g) + ch * 16);
            }
            CP_COMMIT();
        }

        while (kt >= 0) {
            int nkt = -1;
            if (bits) { nkt = __ffs(bits) - 1; bits &= bits - 1; }

            CP_WAIT0();          // current tile (and Q on first iter) arrived
            __syncthreads();     // all threads' copies visible; prev compute done

            if (nkt >= 0) {      // prefetch next tile into other stage
                const size_t g = ((size_t)h * SEQ + (size_t)nkt * KTC) * DIM;
                const uint32_t s1 = sb + OF_KV + (stage ^ 1) * STG_SZ;
                #pragma unroll
                for (int j = 0; j < 2; j++) {
                    int ch = tid + j * 256;
                    uint32_t so = swz((uint32_t)(ch * 16));
                    cp16(s1 + so,         (const char*)(g_khi + g) + ch * 16);
                    cp16(s1 + 8192 + so,  (const char*)(g_klo + g) + ch * 16);
                    cp16(s1 + 16384 + so, (const char*)(g_vhi + g) + ch * 16);
                    cp16(s1 + 24576 + so, (const char*)(g_vlo + g) + ch * 16);
                }
                CP_COMMIT();
            }

            const uint32_t kbh = sb + OF_KV + stage * STG_SZ;
            const uint32_t kbl = kbh + 8192;
            const uint32_t vbh = kbh + 16384;
            const uint32_t vbl = kbh + 24576;

            // ---- QK: S[16 x 64] per warp, 3 split terms ----
            float Sf[8][4];
            #pragma unroll
            for (int n = 0; n < 8; n++)
                #pragma unroll
                for (int j = 0; j < 4; j++) Sf[n][j] = 0.f;

            #pragma unroll
            for (int ks = 0; ks < 4; ks++) {
                uint32_t ahi[4], alo[4];
                const int arow = R0 + (lane & 15);
                const int acol = ks * 16 + ((lane >> 4) << 3);
                const uint32_t ao = swz((uint32_t)(arow * 128 + acol * 2));
                ldsm4(sb + OF_QHI + ao, ahi);
                ldsm4(sb + OF_QLO + ao, alo);
                #pragma unroll
                for (int np = 0; np < 4; np++) {
                    const uint32_t bo = swz((uint32_t)(
                        (np * 16 + ((lane >> 4) << 3) + (lane & 7)) * 128 +
                        (ks * 16 + (((lane >> 3) & 1) << 3)) * 2));
                    uint32_t bh[4], bl[4];
                    ldsm4(kbh + bo, bh);
                    ldsm4(kbl + bo, bl);
                    mma16816(Sf[2 * np],     ahi, bh);
                    mma16816(Sf[2 * np],     ahi, bl);
                    mma16816(Sf[2 * np],     alo, bh);
                    mma16816(Sf[2 * np + 1], ahi, bh + 2);
                    mma16816(Sf[2 * np + 1], ahi, bl + 2);
                    mma16816(Sf[2 * np + 1], alo, bh + 2);
                }
            }

            // ---- mask (3 paths) + row max ----
            const bool aL = (actL >> kt) & 1, aR = (actR >> kt) & 1;
            const bool dg = (kt >= 2 * qt);
            float rm0 = -1e30f, rm1 = -1e30f;
            if (!dg && aL && aR) {
                // fast path: no masking at all
                #pragma unroll
                for (int n = 0; n < 8; n++) {
                    rm0 = fmaxf(rm0, fmaxf(Sf[n][0], Sf[n][1]));
                    rm1 = fmaxf(rm1, fmaxf(Sf[n][2], Sf[n][3]));
                }
            } else if (!dg) {
                // additive bias path (partial half-activity)
                const float bL = aL ? 0.f : -1e30f;
                const float bR = aR ? 0.f : -1e30f;
                #pragma unroll
                for (int n = 0; n < 8; n++) {
                    const float b = (n < 4) ? bL : bR;
                    Sf[n][0] += b; Sf[n][1] += b;
                    Sf[n][2] += b; Sf[n][3] += b;
                    rm0 = fmaxf(rm0, fmaxf(Sf[n][0], Sf[n][1]));
                    rm1 = fmaxf(rm1, fmaxf(Sf[n][2], Sf[n][3]));
                }
            } else {
                // diagonal: per-element causal + activity predicates
                const int cb = kt * KTC;
                #pragma unroll
                for (int n = 0; n < 8; n++) {
                    const bool an = (n < 4) ? aL : aR;
                    const int c0 = cb + n * 8 + ((lane & 3) << 1);
                    const bool k00 = an && (c0     <= gr0);
                    const bool k01 = an && (c0 + 1 <= gr0);
                    const bool k10 = an && (c0     <= gr1);
                    const bool k11 = an && (c0 + 1 <= gr1);
                    Sf[n][0] = k00 ? Sf[n][0] : -1e30f;
                    Sf[n][1] = k01 ? Sf[n][1] : -1e30f;
                    Sf[n][2] = k10 ? Sf[n][2] : -1e30f;
                    Sf[n][3] = k11 ? Sf[n][3] : -1e30f;
                    rm0 = fmaxf(rm0, fmaxf(Sf[n][0], Sf[n][1]));
                    rm1 = fmaxf(rm1, fmaxf(Sf[n][2], Sf[n][3]));
                }
            }
            rm0 = fmaxf(rm0, __shfl_xor_sync(0xffffffffu, rm0, 1));
            rm0 = fmaxf(rm0, __shfl_xor_sync(0xffffffffu, rm0, 2));
            rm1 = fmaxf(rm1, __shfl_xor_sync(0xffffffffu, rm1, 1));
            rm1 = fmaxf(rm1, __shfl_xor_sync(0xffffffffu, rm1, 2));

            const float nm0 = fmaxf(m0, rm0), nm1 = fmaxf(m1, rm1);
            const float corr0 = ex2(m0 - nm0), corr1 = ex2(m1 - nm1);
            m0 = nm0; m1 = nm1;

            // ---- ex2 + packed P hi/lo fragments in registers ----
            uint32_t Pah[4][4], Pal[4][4];
            float rs0 = 0.f, rs1 = 0.f;
            #pragma unroll
            for (int ks = 0; ks < 4; ks++) {
                #pragma unroll
                for (int j = 0; j < 2; j++) {
                    const int n = 2 * ks + j;
                    float e0 = ex2(Sf[n][0] - nm0);
                    float e1 = ex2(Sf[n][1] - nm0);
                    float e2 = ex2(Sf[n][2] - nm1);
                    float e3 = ex2(Sf[n][3] - nm1);
                    rs0 += e0 + e1;
                    rs1 += e2 + e3;
                    uint32_t h01 = pkbf(e0, e1);
                    uint32_t h23 = pkbf(e2, e3);
                    float h0f = __uint_as_float(h01 << 16);
                    float h1f = __uint_as_float(h01 & 0xFFFF0000u);
                    float h2f = __uint_as_float(h23 << 16);
                    float h3f = __uint_as_float(h23 & 0xFFFF0000u);
                    Pah[ks][2 * j]     = h01;
                    Pah[ks][2 * j + 1] = h23;
                    Pal[ks][2 * j]     = pkbf(e0 - h0f, e1 - h1f);
                    Pal[ks][2 * j + 1] = pkbf(e2 - h2f, e3 - h3f);
                }
            }
            rs0 += __shfl_xor_sync(0xffffffffu, rs0, 1);
            rs0 += __shfl_xor_sync(0xffffffffu, rs0, 2);
            rs1 += __shfl_xor_sync(0xffffffffu, rs1, 1);
            rs1 += __shfl_xor_sync(0xffffffffu, rs1, 2);
            l0s = l0s * corr0 + rs0;
            l1s = l1s * corr1 + rs1;

            // ---- rescale O, then PV (3 split terms) ----
            #pragma unroll
            for (int n = 0; n < 8; n++) {
                Of[n][0] *= corr0; Of[n][1] *= corr0;
                Of[n][2] *= corr1; Of[n][3] *= corr1;
            }
            #pragma unroll
            for (int ks = 0; ks < 4; ks++) {
                #pragma unroll
                for (int np = 0; np < 4; np++) {
                    const uint32_t vo = swz((uint32_t)(
                        (ks * 16 + (lane & 15)) * 128 +
                        (np * 16 + ((lane >> 4) << 3)) * 2));
                    uint32_t vh[4], vl[4];
                    ldsm4t(vbh + vo, vh);
                    ldsm4t(vbl + vo, vl);
                    mma16816(Of[2 * np],     Pah[ks], vh);
                    mma16816(Of[2 * np],     Pah[ks], vl);
                    mma16816(Of[2 * np],     Pal[ks], vh);
                    mma16816(Of[2 * np + 1], Pah[ks], vh + 2);
                    mma16816(Of[2 * np + 1], Pah[ks], vl + 2);
                    mma16816(Of[2 * np + 1], Pal[ks], vh + 2);
                }
            }

            kt = nkt;
            stage ^= 1;
        }

        // ---- epilogue ----
        const float inv0 = (m0 > -1e29f) ? (1.f / l0s) : 0.f;
        const float inv1 = (m1 > -1e29f) ? (1.f / l1s) : 0.f;
        float* ob0 = out + ((size_t)(h * SEQ + gr0)) * DIM;
        float* ob1 = out + ((size_t)(h * SEQ + gr1)) * DIM;
        #pragma unroll
        for (int n = 0; n < 8; n++) {
            const int c = n * 8 + ((lane & 3) << 1);
            *(float2*)(ob0 + c) = make_float2(Of[n][0] * inv0, Of[n][1] * inv0);
            *(float2*)(ob1 + c) = make_float2(Of[n][2] * inv1, Of[n][3] * inv1);
        }
    }
}

// ---------------------------------------------------------------------------
// Launch
// ---------------------------------------------------------------------------
extern "C" void kernel_launch(void* const* d_in, const int* in_sizes, int n_in,
                              void* d_out, int out_size) {
    const float* qry  = (const float*)d_in[0];
    const float* key  = (const float*)d_in[1];
    const float* val  = (const float*)d_in[2];
    const int*   mask = (const int*)d_in[3];
    float* out = (float*)d_out;

    // 4 mask blocks per warp, 8 warps per CTA
    int nblk = NH * NB * NB;               // 65536
    int cta  = (nblk / 4 * 32 + 255) / 256; // 2048
    block_mask_kernel<<<cta, 256>>>(mask);

    cvt_all<<<3 * CVT_CTAS, 256>>>(qry, key, val);

    static int attr_set = 0;
    if (!attr_set) {
        cudaFuncSetAttribute(attn_mma,
                             cudaFuncAttributeMaxDynamicSharedMemorySize, SMEM_BYTES);
        attr_set = 1;
    }
    attn_mma<<<2 * NSM, 256, SMEM_BYTES>>>(out);
}

// round 14
// speedup vs baseline: 9.6833x; 1.1528x over previous
#include <cuda_runtime.h>
#include <cuda_fp16.h>
#include <math.h>
#include <stdint.h>

#define SEQ  2048
#define DIM  64
#define NH   16
#define NB   64            // 32-wide mask blocks per dim
#define QTR  128           // q rows per work item
#define KTC  64            // k cols per tile
#define NQT  (SEQ / QTR)   // 16
#define NWORK (NH * NQT)   // 256
#define NSM  152
#define NELEM (NH * SEQ * DIM)
#define LOG2E 1.4426950408889634f

__device__ unsigned char g_bm[NH * NB * NB];
__device__ int g_ctr;
// precomputed fp16 hi/lo planes (row-major [h][r][d], 128B rows)
// Q planes are pre-scaled by log2(e) so softmax uses ex2 directly.
// V has a single (hi) plane: fp16 rounding of V is within error budget.
__device__ uint16_t g_qhi[NELEM], g_qlo[NELEM];
__device__ uint16_t g_khi[NELEM], g_klo[NELEM];
__device__ uint16_t g_vhi[NELEM];

// ---------------- smem layout (bytes) ----------------
#define OF_QHI 128
#define OF_QLO (OF_QHI + 16384)     // Q planes: 128 x 64 fp16 each
#define OF_KV  (OF_QLO + 16384)     // 2 stages x (KHI|KLO|VHI), 8KB each
#define STG_SZ 24576
#define SMEM_BYTES (OF_KV + 2 * STG_SZ)   // 82048

// ---------------------------------------------------------------------------
// helpers (baseline PTX only)
// ---------------------------------------------------------------------------
__device__ __forceinline__ uint32_t smem_u32(const void* p) {
    uint32_t a;
    asm("{ .reg .u64 t; cvta.to.shared.u64 t, %1; cvt.u32.u64 %0, t; }"
        : "=r"(a) : "l"(p));
    return a;
}
__device__ __forceinline__ uint32_t swz(uint32_t o) { return o ^ ((o >> 3) & 0x70); }

__device__ __forceinline__ void ldsm4(uint32_t addr, uint32_t r[4]) {
    asm volatile("ldmatrix.sync.aligned.m8n8.x4.shared.b16 {%0,%1,%2,%3}, [%4];"
        : "=r"(r[0]), "=r"(r[1]), "=r"(r[2]), "=r"(r[3]) : "r"(addr));
}
__device__ __forceinline__ void ldsm4t(uint32_t addr, uint32_t r[4]) {
    asm volatile("ldmatrix.sync.aligned.m8n8.x4.trans.shared.b16 {%0,%1,%2,%3}, [%4];"
        : "=r"(r[0]), "=r"(r[1]), "=r"(r[2]), "=r"(r[3]) : "r"(addr));
}
__device__ __forceinline__ void mma16816(float c[4], const uint32_t a[4],
                                         const uint32_t b[2]) {
    asm volatile(
        "mma.sync.aligned.m16n8k16.row.col.f32.f16.f16.f32 "
        "{%0,%1,%2,%3}, {%4,%5,%6,%7}, {%8,%9}, {%0,%1,%2,%3};"
        : "+f"(c[0]), "+f"(c[1]), "+f"(c[2]), "+f"(c[3])
        : "r"(a[0]), "r"(a[1]), "r"(a[2]), "r"(a[3]), "r"(b[0]), "r"(b[1]));
}
// pack two floats to fp16x2 (x -> lo, y -> hi); also return rounded floats
__device__ __forceinline__ uint32_t pkhf(float x, float y) {
    __half2 h = __floats2half2_rn(x, y);
    return *(uint32_t*)&h;
}
__device__ __forceinline__ float2 unpkhf(uint32_t v) {
    __half2 h = *(__half2*)&v;
    return __half22float2(h);
}
__device__ __forceinline__ float ex2(float x) {
    float r;
    asm("ex2.approx.f32 %0, %1;" : "=f"(r) : "f"(x));
    return r;
}
__device__ __forceinline__ void cp16(uint32_t sd, const void* gs) {
    asm volatile("cp.async.cg.shared.global [%0], [%1], 16;"
                 :: "r"(sd), "l"(gs));
}
#define CP_COMMIT() asm volatile("cp.async.commit_group;" ::: "memory")
#define CP_WAIT0()  asm volatile("cp.async.wait_group 0;" ::: "memory")

// ---------------------------------------------------------------------------
// Kernel 1: block-OR pooling of the dense mask -> g_bm (lower-tri only).
// Row-0 sampling with exact all-zero fallback (prob 2^-32 per block).
// ---------------------------------------------------------------------------
__global__ void block_mask_kernel(const int* __restrict__ mask) {
    if (blockIdx.x == 0 && threadIdx.x == 0) g_ctr = 0;
    const int gwarp = (blockIdx.x * blockDim.x + threadIdx.x) >> 5;
    const int lane  = threadIdx.x & 31;
    const int grp   = lane >> 3;
    const int sub   = lane & 7;
    const int blk   = gwarp * 4 + grp;
    if (blk >= NH * NB * NB) return;
    const int h   = blk >> 12;
    const int rem = blk & (NB * NB - 1);
    const int qb  = rem >> 6;
    const int kb  = rem & (NB - 1);
    const unsigned gm = 0xFFu << (grp * 8);

    unsigned char res = 0;
    if (kb <= qb) {
        const int* base = mask + ((size_t)h * SEQ + (size_t)qb * 32) * SEQ
                               + (size_t)kb * 32;
        int4 a = *((const int4*)base + sub);
        unsigned bal = __ballot_sync(gm, (a.x | a.y | a.z | a.w) != 0);
        if (bal) {
            res = 1;
        } else {
            int acc = 0;
            for (int r = 1; r < 32; r++) {
                int4 b = *((const int4*)(base + (size_t)r * SEQ) + sub);
                acc |= b.x | b.y | b.z | b.w;
            }
            unsigned bal2 = __ballot_sync(gm, acc != 0);
            res = bal2 ? 1 : 0;
        }
    }
    if (sub == 0) g_bm[blk] = res;
}

// ---------------------------------------------------------------------------
// Kernel 1b: fused fp32 -> fp16 hi/lo plane conversion.
// Q (x log2e): hi+lo.  K: hi+lo.  V: hi only.
// ---------------------------------------------------------------------------
#define CVT_CTAS (NELEM / 1024)    // 2048 CTAs per tensor
__global__ void cvt_all(const float* __restrict__ q,
                        const float* __restrict__ k,
                        const float* __restrict__ v) {
    const int which = blockIdx.x / CVT_CTAS;
    const int cb    = blockIdx.x % CVT_CTAS;
    const int i     = (cb * 256 + threadIdx.x) * 4;
    const float* src = (which == 0) ? q : (which == 1) ? k : v;

    float4 x = *(const float4*)(src + i);
    if (which == 0) {
        x.x *= LOG2E; x.y *= LOG2E; x.z *= LOG2E; x.w *= LOG2E;
    }
    uint32_t h01 = pkhf(x.x, x.y);
    uint32_t h23 = pkhf(x.z, x.w);
    if (which == 2) {
        *(uint2*)(g_vhi + i) = make_uint2(h01, h23);
        return;
    }
    uint16_t* hi = (which == 0) ? g_qhi : g_khi;
    uint16_t* lo = (which == 0) ? g_qlo : g_klo;
    float2 f01 = unpkhf(h01);
    float2 f23 = unpkhf(h23);
    *(uint2*)(hi + i) = make_uint2(h01, h23);
    *(uint2*)(lo + i) = make_uint2(pkhf(x.x - f01.x, x.y - f01.y),
                                   pkhf(x.z - f23.x, x.w - f23.y));
}

// ---------------------------------------------------------------------------
// Kernel 2: block-sparse causal flash attention, mma.sync fp16 split,
// QK 3-term (hi*hi + hi*lo + lo*hi), PV 2-term ((Phi+Plo)*Vhi).
// cp.async double-buffered K/V, bitmap tile loop, persistent work queue.
// ---------------------------------------------------------------------------
__global__ void __launch_bounds__(256, 2)
attn_mma(float* __restrict__ out) {
    extern __shared__ char smem[];
    const uint32_t sb = smem_u32(smem);
    int* widx = (int*)smem;
    unsigned int* bmap = (unsigned int*)(smem + 8);

    const int tid  = threadIdx.x;
    const int w    = tid >> 5;
    const int lane = tid & 31;
    const int R0   = w * 16;

    for (;;) {
        __syncthreads();                       // prev item fully done
        if (tid == 0) { *widx = atomicAdd(&g_ctr, 1); *bmap = 0u; }
        __syncthreads();
        const int idx = *widx;
        if (idx >= NWORK) break;
        const int qt = (NQT - 1) - (idx >> 4); // heavy items first
        const int h  = idx & (NH - 1);

        // ---- stage Q planes via cp.async (pure copy) ----
        {
            const size_t gq = ((size_t)h * SEQ + (size_t)qt * QTR) * DIM;
            const char* qh = (const char*)(g_qhi + gq);
            const char* ql = (const char*)(g_qlo + gq);
            #pragma unroll
            for (int j = 0; j < 4; j++) {
                int ch = tid + j * 256;
                uint32_t so = swz((uint32_t)(ch * 16));
                cp16(sb + OF_QHI + so, qh + ch * 16);
                cp16(sb + OF_QLO + so, ql + ch * 16);
            }
        }

        // ---- per-warp activity bitmaps (lane = kt) ----
        const unsigned char* bmp = g_bm +
            ((size_t)h * NB + (qt * 4 + (w >> 1))) * NB;
        const int mb0 = bmp[2 * lane], mb1 = bmp[2 * lane + 1];
        const uint32_t actL = __ballot_sync(0xffffffffu, mb0 != 0);
        const uint32_t actR = __ballot_sync(0xffffffffu, mb1 != 0);
        if (lane == 0) atomicOr(bmap, actL | actR);
        __syncthreads();
        uint32_t bits = *bmap;

        // ---- per-thread softmax/output state (rows gr0, gr0+8) ----
        float Of[8][4];
        #pragma unroll
        for (int n = 0; n < 8; n++)
            #pragma unroll
            for (int j = 0; j < 4; j++) Of[n][j] = 0.f;
        float m0 = -1e30f, m1 = -1e30f, l0s = 0.f, l1s = 0.f;
        const int gr0 = qt * QTR + R0 + (lane >> 2);
        const int gr1 = gr0 + 8;

        int kt = -1, stage = 0;
        if (bits) {
            kt = __ffs(bits) - 1; bits &= bits - 1;
            const size_t g = ((size_t)h * SEQ + (size_t)kt * KTC) * DIM;
            const uint32_t s0 = sb + OF_KV;
            #pragma unroll
            for (int j = 0; j < 2; j++) {
                int ch = tid + j * 256;
                uint32_t so = swz((uint32_t)(ch * 16));
                cp16(s0 + so,         (const char*)(g_khi + g) + ch * 16);
                cp16(s0 + 8192 + so,  (const char*)(g_klo + g) + ch * 16);
                cp16(s0 + 16384 + so, (const char*)(g_vhi + g) + ch * 16);
            }
            CP_COMMIT();
        }

        while (kt >= 0) {
            int nkt = -1;
            if (bits) { nkt = __ffs(bits) - 1; bits &= bits - 1; }

            CP_WAIT0();          // current tile (and Q on first iter) arrived
            __syncthreads();     // all threads' copies visible; prev compute done

            if (nkt >= 0) {      // prefetch next tile into other stage
                const size_t g = ((size_t)h * SEQ + (size_t)nkt * KTC) * DIM;
                const uint32_t s1 = sb + OF_KV + (stage ^ 1) * STG_SZ;
                #pragma unroll
                for (int j = 0; j < 2; j++) {
                    int ch = tid + j * 256;
                    uint32_t so = swz((uint32_t)(ch * 16));
                    cp16(s1 + so,         (const char*)(g_khi + g) + ch * 16);
                    cp16(s1 + 8192 + so,  (const char*)(g_klo + g) + ch * 16);
                    cp16(s1 + 16384 + so, (const char*)(g_vhi + g) + ch * 16);
                }
                CP_COMMIT();
            }

            const uint32_t kbh = sb + OF_KV + stage * STG_SZ;
            const uint32_t kbl = kbh + 8192;
            const uint32_t vbh = kbh + 16384;

            // ---- QK: S[16 x 64] per warp, 3 split terms ----
            float Sf[8][4];
            #pragma unroll
            for (int n = 0; n < 8; n++)
                #pragma unroll
                for (int j = 0; j < 4; j++) Sf[n][j] = 0.f;

            #pragma unroll
            for (int ks = 0; ks < 4; ks++) {
                uint32_t ahi[4], alo[4];
                const int arow = R0 + (lane & 15);
                const int acol = ks * 16 + ((lane >> 4) << 3);
                const uint32_t ao = swz((uint32_t)(arow * 128 + acol * 2));
                ldsm4(sb + OF_QHI + ao, ahi);
                ldsm4(sb + OF_QLO + ao, alo);
                #pragma unroll
                for (int np = 0; np < 4; np++) {
                    const uint32_t bo = swz((uint32_t)(
                        (np * 16 + ((lane >> 4) << 3) + (lane & 7)) * 128 +
                        (ks * 16 + (((lane >> 3) & 1) << 3)) * 2));
                    uint32_t bh[4], bl[4];
                    ldsm4(kbh + bo, bh);
                    ldsm4(kbl + bo, bl);
                    mma16816(Sf[2 * np],     ahi, bh);
                    mma16816(Sf[2 * np],     ahi, bl);
                    mma16816(Sf[2 * np],     alo, bh);
                    mma16816(Sf[2 * np + 1], ahi, bh + 2);
                    mma16816(Sf[2 * np + 1], ahi, bl + 2);
                    mma16816(Sf[2 * np + 1], alo, bh + 2);
                }
            }

            // ---- mask (3 paths) + row max ----
            const bool aL = (actL >> kt) & 1, aR = (actR >> kt) & 1;
            const bool dg = (kt >= 2 * qt);
            float rm0 = -1e30f, rm1 = -1e30f;
            if (!dg && aL && aR) {
                #pragma unroll
                for (int n = 0; n < 8; n++) {
                    rm0 = fmaxf(rm0, fmaxf(Sf[n][0], Sf[n][1]));
                    rm1 = fmaxf(rm1, fmaxf(Sf[n][2], Sf[n][3]));
                }
            } else if (!dg) {
                const float bL = aL ? 0.f : -1e30f;
                const float bR = aR ? 0.f : -1e30f;
                #pragma unroll
                for (int n = 0; n < 8; n++) {
                    const float b = (n < 4) ? bL : bR;
                    Sf[n][0] += b; Sf[n][1] += b;
                    Sf[n][2] += b; Sf[n][3] += b;
                    rm0 = fmaxf(rm0, fmaxf(Sf[n][0], Sf[n][1]));
                    rm1 = fmaxf(rm1, fmaxf(Sf[n][2], Sf[n][3]));
                }
            } else {
                const int cb = kt * KTC;
                #pragma unroll
                for (int n = 0; n < 8; n++) {
                    const bool an = (n < 4) ? aL : aR;
                    const int c0 = cb + n * 8 + ((lane & 3) << 1);
                    const bool k00 = an && (c0     <= gr0);
                    const bool k01 = an && (c0 + 1 <= gr0);
                    const bool k10 = an && (c0     <= gr1);
                    const bool k11 = an && (c0 + 1 <= gr1);
                    Sf[n][0] = k00 ? Sf[n][0] : -1e30f;
                    Sf[n][1] = k01 ? Sf[n][1] : -1e30f;
                    Sf[n][2] = k10 ? Sf[n][2] : -1e30f;
                    Sf[n][3] = k11 ? Sf[n][3] : -1e30f;
                    rm0 = fmaxf(rm0, fmaxf(Sf[n][0], Sf[n][1]));
                    rm1 = fmaxf(rm1, fmaxf(Sf[n][2], Sf[n][3]));
                }
            }
            rm0 = fmaxf(rm0, __shfl_xor_sync(0xffffffffu, rm0, 1));
            rm0 = fmaxf(rm0, __shfl_xor_sync(0xffffffffu, rm0, 2));
            rm1 = fmaxf(rm1, __shfl_xor_sync(0xffffffffu, rm1, 1));
            rm1 = fmaxf(rm1, __shfl_xor_sync(0xffffffffu, rm1, 2));

            const float nm0 = fmaxf(m0, rm0), nm1 = fmaxf(m1, rm1);
            const float corr0 = ex2(m0 - nm0), corr1 = ex2(m1 - nm1);
            m0 = nm0; m1 = nm1;

            // ---- ex2 + packed P hi/lo fragments in registers ----
            uint32_t Pah[4][4], Pal[4][4];
            float rs0 = 0.f, rs1 = 0.f;
            #pragma unroll
            for (int ks = 0; ks < 4; ks++) {
                #pragma unroll
                for (int j = 0; j < 2; j++) {
                    const int n = 2 * ks + j;
                    float e0 = ex2(Sf[n][0] - nm0);
                    float e1 = ex2(Sf[n][1] - nm0);
                    float e2 = ex2(Sf[n][2] - nm1);
                    float e3 = ex2(Sf[n][3] - nm1);
                    rs0 += e0 + e1;
                    rs1 += e2 + e3;
                    uint32_t h01 = pkhf(e0, e1);
                    uint32_t h23 = pkhf(e2, e3);
                    float2 f01 = unpkhf(h01);
                    float2 f23 = unpkhf(h23);
                    Pah[ks][2 * j]     = h01;
                    Pah[ks][2 * j + 1] = h23;
                    Pal[ks][2 * j]     = pkhf(e0 - f01.x, e1 - f01.y);
                    Pal[ks][2 * j + 1] = pkhf(e2 - f23.x, e3 - f23.y);
                }
            }
            rs0 += __shfl_xor_sync(0xffffffffu, rs0, 1);
            rs0 += __shfl_xor_sync(0xffffffffu, rs0, 2);
            rs1 += __shfl_xor_sync(0xffffffffu, rs1, 1);
            rs1 += __shfl_xor_sync(0xffffffffu, rs1, 2);
            l0s = l0s * corr0 + rs0;
            l1s = l1s * corr1 + rs1;

            // ---- rescale O, then PV: (Phi + Plo) x Vhi  (2 terms) ----
            #pragma unroll
            for (int n = 0; n < 8; n++) {
                Of[n][0] *= corr0; Of[n][1] *= corr0;
                Of[n][2] *= corr1; Of[n][3] *= corr1;
            }
            #pragma unroll
            for (int ks = 0; ks < 4; ks++) {
                #pragma unroll
                for (int np = 0; np < 4; np++) {
                    const uint32_t vo = swz((uint32_t)(
                        (ks * 16 + (lane & 15)) * 128 +
                        (np * 16 + ((lane >> 4) << 3)) * 2));
                    uint32_t vh[4];
                    ldsm4t(vbh + vo, vh);
                    mma16816(Of[2 * np],     Pah[ks], vh);
                    mma16816(Of[2 * np],     Pal[ks], vh);
                    mma16816(Of[2 * np + 1], Pah[ks], vh + 2);
                    mma16816(Of[2 * np + 1], Pal[ks], vh + 2);
                }
            }

            kt = nkt;
            stage ^= 1;
        }

        // ---- epilogue ----
        const float inv0 = (m0 > -1e29f) ? (1.f / l0s) : 0.f;
        const float inv1 = (m1 > -1e29f) ? (1.f / l1s) : 0.f;
        float* ob0 = out + ((size_t)(h * SEQ + gr0)) * DIM;
        float* ob1 = out + ((size_t)(h * SEQ + gr1)) * DIM;
        #pragma unroll
        for (int n = 0; n < 8; n++) {
            const int c = n * 8 + ((lane & 3) << 1);
            *(float2*)(ob0 + c) = make_float2(Of[n][0] * inv0, Of[n][1] * inv0);
            *(float2*)(ob1 + c) = make_float2(Of[n][2] * inv1, Of[n][3] * inv1);
        }
    }
}

// ---------------------------------------------------------------------------
// Launch
// ---------------------------------------------------------------------------
extern "C" void kernel_launch(void* const* d_in, const int* in_sizes, int n_in,
                              void* d_out, int out_size) {
    const float* qry  = (const float*)d_in[0];
    const float* key  = (const float*)d_in[1];
    const float* val  = (const float*)d_in[2];
    const int*   mask = (const int*)d_in[3];
    float* out = (float*)d_out;

    int nblk = NH * NB * NB;                // 65536
    int cta  = (nblk / 4 * 32 + 255) / 256; // 2048
    block_mask_kernel<<<cta, 256>>>(mask);

    cvt_all<<<3 * CVT_CTAS, 256>>>(qry, key, val);

    static int attr_set = 0;
    if (!attr_set) {
        cudaFuncSetAttribute(attn_mma,
                             cudaFuncAttributeMaxDynamicSharedMemorySize, SMEM_BYTES);
        attr_set = 1;
    }
    attn_mma<<<2 * NSM, 256, SMEM_BYTES>>>(out);
}

// round 15
// speedup vs baseline: 13.7821x; 1.4233x over previous
#include <cuda_runtime.h>
#include <cuda_fp16.h>
#include <math.h>
#include <stdint.h>

#define SEQ  2048
#define DIM  64
#define NH   16
#define NB   64            // 32-wide mask blocks per dim
#define QTR  128           // q rows per work item
#define KTC  64            // k cols per tile
#define NQT  (SEQ / QTR)   // 16
#define NSM  152
#define NELEM (NH * SEQ * DIM)
#define LOG2E 1.4426950408889634f
#define RPH   40           // chunk-items per head
#define NWORK (NH * RPH)   // 640

__device__ unsigned char g_bm[NH * NB * NB];
__device__ int g_ctr;
// fp16 hi/lo planes (row-major [h][r][d], 128B rows); Q pre-scaled by log2e.
__device__ uint16_t g_qhi[NELEM], g_qlo[NELEM];
__device__ uint16_t g_khi[NELEM], g_klo[NELEM];
__device__ uint16_t g_vhi[NELEM];
// split-softmax partials: up to 4 chunks per (h, qt)
__device__ float g_pO[NH * NQT * 4][QTR][DIM];   // unnormalized O
__device__ float g_pm[NH * NQT * 4][QTR];        // row max (log2 domain)
__device__ float g_pl[NH * NQT * 4][QTR];        // row sum

// rank -> (qt, chunk), heavy q-tiles first
__device__ const unsigned char c_r2qt[RPH] = {
    15,15,15,15, 14,14,14,14, 13,13,13,13, 12,12,12,12,
    11,11,11, 10,10,10, 9,9,9, 8,8,8,
    7,7, 6,6, 5,5, 4,4, 3, 2, 1, 0};
__device__ const unsigned char c_r2ch[RPH] = {
    0,1,2,3, 0,1,2,3, 0,1,2,3, 0,1,2,3,
    0,1,2, 0,1,2, 0,1,2, 0,1,2,
    0,1, 0,1, 0,1, 0,1, 0, 0, 0, 0};

// ---------------- smem layout (bytes) ----------------
#define OF_QHI 128
#define OF_QLO (OF_QHI + 16384)     // Q planes: 128 x 64 fp16 each
#define OF_KV  (OF_QLO + 16384)     // 2 stages x (KHI|KLO|VHI), 8KB each
#define STG_SZ 24576
#define SMEM_BYTES (OF_KV + 2 * STG_SZ)   // 82048

// ---------------------------------------------------------------------------
// helpers (baseline PTX only)
// ---------------------------------------------------------------------------
__device__ __forceinline__ uint32_t smem_u32(const void* p) {
    uint32_t a;
    asm("{ .reg .u64 t; cvta.to.shared.u64 t, %1; cvt.u32.u64 %0, t; }"
        : "=r"(a) : "l"(p));
    return a;
}
__device__ __forceinline__ uint32_t swz(uint32_t o) { return o ^ ((o >> 3) & 0x70); }

__device__ __forceinline__ void ldsm4(uint32_t addr, uint32_t r[4]) {
    asm volatile("ldmatrix.sync.aligned.m8n8.x4.shared.b16 {%0,%1,%2,%3}, [%4];"
        : "=r"(r[0]), "=r"(r[1]), "=r"(r[2]), "=r"(r[3]) : "r"(addr));
}
__device__ __forceinline__ void ldsm4t(uint32_t addr, uint32_t r[4]) {
    asm volatile("ldmatrix.sync.aligned.m8n8.x4.trans.shared.b16 {%0,%1,%2,%3}, [%4];"
        : "=r"(r[0]), "=r"(r[1]), "=r"(r[2]), "=r"(r[3]) : "r"(addr));
}
__device__ __forceinline__ void mma16816(float c[4], const uint32_t a[4],
                                         const uint32_t b[2]) {
    asm volatile(
        "mma.sync.aligned.m16n8k16.row.col.f32.f16.f16.f32 "
        "{%0,%1,%2,%3}, {%4,%5,%6,%7}, {%8,%9}, {%0,%1,%2,%3};"
        : "+f"(c[0]), "+f"(c[1]), "+f"(c[2]), "+f"(c[3])
        : "r"(a[0]), "r"(a[1]), "r"(a[2]), "r"(a[3]), "r"(b[0]), "r"(b[1]));
}
__device__ __forceinline__ uint32_t pkhf(float x, float y) {
    __half2 h = __floats2half2_rn(x, y);
    return *(uint32_t*)&h;
}
__device__ __forceinline__ float2 unpkhf(uint32_t v) {
    __half2 h = *(__half2*)&v;
    return __half22float2(h);
}
__device__ __forceinline__ float ex2(float x) {
    float r;
    asm("ex2.approx.f32 %0, %1;" : "=f"(r) : "f"(x));
    return r;
}
__device__ __forceinline__ void cp16(uint32_t sd, const void* gs) {
    asm volatile("cp.async.cg.shared.global [%0], [%1], 16;"
                 :: "r"(sd), "l"(gs));
}
#define CP_COMMIT() asm volatile("cp.async.commit_group;" ::: "memory")
#define CP_WAIT0()  asm volatile("cp.async.wait_group 0;" ::: "memory")

// ---------------------------------------------------------------------------
// Kernel 1: block-OR pooling (row-0 sampling + exact fallback)
// ---------------------------------------------------------------------------
__global__ void block_mask_kernel(const int* __restrict__ mask) {
    if (blockIdx.x == 0 && threadIdx.x == 0) g_ctr = 0;
    const int gwarp = (blockIdx.x * blockDim.x + threadIdx.x) >> 5;
    const int lane  = threadIdx.x & 31;
    const int grp   = lane >> 3;
    const int sub   = lane & 7;
    const int blk   = gwarp * 4 + grp;
    if (blk >= NH * NB * NB) return;
    const int h   = blk >> 12;
    const int rem = blk & (NB * NB - 1);
    const int qb  = rem >> 6;
    const int kb  = rem & (NB - 1);
    const unsigned gm = 0xFFu << (grp * 8);

    unsigned char res = 0;
    if (kb <= qb) {
        const int* base = mask + ((size_t)h * SEQ + (size_t)qb * 32) * SEQ
                               + (size_t)kb * 32;
        int4 a = *((const int4*)base + sub);
        unsigned bal = __ballot_sync(gm, (a.x | a.y | a.z | a.w) != 0);
        if (bal) {
            res = 1;
        } else {
            int acc = 0;
            for (int r = 1; r < 32; r++) {
                int4 b = *((const int4*)(base + (size_t)r * SEQ) + sub);
                acc |= b.x | b.y | b.z | b.w;
            }
            unsigned bal2 = __ballot_sync(gm, acc != 0);
            res = bal2 ? 1 : 0;
        }
    }
    if (sub == 0) g_bm[blk] = res;
}

// ---------------------------------------------------------------------------
// Kernel 1b: fused fp32 -> fp16 hi/lo plane conversion.
// ---------------------------------------------------------------------------
#define CVT_CTAS (NELEM / 1024)    // 2048 CTAs per tensor
__global__ void cvt_all(const float* __restrict__ q,
                        const float* __restrict__ k,
                        const float* __restrict__ v) {
    const int which = blockIdx.x / CVT_CTAS;
    const int cb    = blockIdx.x % CVT_CTAS;
    const int i     = (cb * 256 + threadIdx.x) * 4;
    const float* src = (which == 0) ? q : (which == 1) ? k : v;

    float4 x = *(const float4*)(src + i);
    if (which == 0) {
        x.x *= LOG2E; x.y *= LOG2E; x.z *= LOG2E; x.w *= LOG2E;
    }
    uint32_t h01 = pkhf(x.x, x.y);
    uint32_t h23 = pkhf(x.z, x.w);
    if (which == 2) {
        *(uint2*)(g_vhi + i) = make_uint2(h01, h23);
        return;
    }
    uint16_t* hi = (which == 0) ? g_qhi : g_khi;
    uint16_t* lo = (which == 0) ? g_qlo : g_klo;
    float2 f01 = unpkhf(h01);
    float2 f23 = unpkhf(h23);
    *(uint2*)(hi + i) = make_uint2(h01, h23);
    *(uint2*)(lo + i) = make_uint2(pkhf(x.x - f01.x, x.y - f01.y),
                                   pkhf(x.z - f23.x, x.w - f23.y));
}

// ---------------------------------------------------------------------------
// Kernel 2: chunked block-sparse causal flash attention.
// Work item = (h, 128-row q-tile, kt-chunk of <=8 tiles) -> partial softmax
// state (m log2-domain, l, unnormalized O) written to scratch.
// ---------------------------------------------------------------------------
__global__ void __launch_bounds__(256, 2)
attn_mma() {
    extern __shared__ char smem[];
    const uint32_t sb = smem_u32(smem);
    int* widx = (int*)smem;
    unsigned int* bmap = (unsigned int*)(smem + 8);

    const int tid  = threadIdx.x;
    const int w    = tid >> 5;
    const int lane = tid & 31;
    const int R0   = w * 16;

    for (;;) {
        __syncthreads();                       // prev item fully done
        if (tid == 0) { *widx = atomicAdd(&g_ctr, 1); *bmap = 0u; }
        __syncthreads();
        const int idx = *widx;
        if (idx >= NWORK) break;
        const int h    = idx & (NH - 1);
        const int rank = idx >> 4;             // heavy q-tiles first
        const int qt   = c_r2qt[rank];
        const int ch   = c_r2ch[rank];

        // ---- stage Q planes via cp.async ----
        {
            const size_t gq = ((size_t)h * SEQ + (size_t)qt * QTR) * DIM;
            const char* qh = (const char*)(g_qhi + gq);
            const char* ql = (const char*)(g_qlo + gq);
            #pragma unroll
            for (int j = 0; j < 4; j++) {
                int chn = tid + j * 256;
                uint32_t so = swz((uint32_t)(chn * 16));
                cp16(sb + OF_QHI + so, qh + chn * 16);
                cp16(sb + OF_QLO + so, ql + chn * 16);
            }
        }

        // ---- per-warp activity bitmaps (lane = kt) ----
        const unsigned char* bmp = g_bm +
            ((size_t)h * NB + (qt * 4 + (w >> 1))) * NB;
        const int mb0 = bmp[2 * lane], mb1 = bmp[2 * lane + 1];
        const uint32_t actL = __ballot_sync(0xffffffffu, mb0 != 0);
        const uint32_t actR = __ballot_sync(0xffffffffu, mb1 != 0);
        if (lane == 0) atomicOr(bmap, actL | actR);
        __syncthreads();
        uint32_t bits = *bmap & (0xFFu << (ch * 8));   // this chunk only

        // ---- per-thread partial state (rows lr0, lr0+8) ----
        float Of[8][4];
        #pragma unroll
        for (int n = 0; n < 8; n++)
            #pragma unroll
            for (int j = 0; j < 4; j++) Of[n][j] = 0.f;
        float m0 = -1e30f, m1 = -1e30f, l0s = 0.f, l1s = 0.f;
        const int lr0 = R0 + (lane >> 2);
        const int gr0 = qt * QTR + lr0;
        const int gr1 = gr0 + 8;

        int kt = -1, stage = 0;
        if (bits) {
            kt = __ffs(bits) - 1; bits &= bits - 1;
            const size_t g = ((size_t)h * SEQ + (size_t)kt * KTC) * DIM;
            const uint32_t s0 = sb + OF_KV;
            #pragma unroll
            for (int j = 0; j < 2; j++) {
                int chn = tid + j * 256;
                uint32_t so = swz((uint32_t)(chn * 16));
                cp16(s0 + so,         (const char*)(g_khi + g) + chn * 16);
                cp16(s0 + 8192 + so,  (const char*)(g_klo + g) + chn * 16);
                cp16(s0 + 16384 + so, (const char*)(g_vhi + g) + chn * 16);
            }
            CP_COMMIT();
        }

        while (kt >= 0) {
            int nkt = -1;
            if (bits) { nkt = __ffs(bits) - 1; bits &= bits - 1; }

            CP_WAIT0();
            __syncthreads();

            if (nkt >= 0) {
                const size_t g = ((size_t)h * SEQ + (size_t)nkt * KTC) * DIM;
                const uint32_t s1 = sb + OF_KV + (stage ^ 1) * STG_SZ;
                #pragma unroll
                for (int j = 0; j < 2; j++) {
                    int chn = tid + j * 256;
                    uint32_t so = swz((uint32_t)(chn * 16));
                    cp16(s1 + so,         (const char*)(g_khi + g) + chn * 16);
                    cp16(s1 + 8192 + so,  (const char*)(g_klo + g) + chn * 16);
                    cp16(s1 + 16384 + so, (const char*)(g_vhi + g) + chn * 16);
                }
                CP_COMMIT();
            }

            const uint32_t kbh = sb + OF_KV + stage * STG_SZ;
            const uint32_t kbl = kbh + 8192;
            const uint32_t vbh = kbh + 16384;

            // ---- QK: S[16 x 64] per warp, 3 split terms ----
            float Sf[8][4];
            #pragma unroll
            for (int n = 0; n < 8; n++)
                #pragma unroll
                for (int j = 0; j < 4; j++) Sf[n][j] = 0.f;

            #pragma unroll
            for (int ks = 0; ks < 4; ks++) {
                uint32_t ahi[4], alo[4];
                const int arow = R0 + (lane & 15);
                const int acol = ks * 16 + ((lane >> 4) << 3);
                const uint32_t ao = swz((uint32_t)(arow * 128 + acol * 2));
                ldsm4(sb + OF_QHI + ao, ahi);
                ldsm4(sb + OF_QLO + ao, alo);
                #pragma unroll
                for (int np = 0; np < 4; np++) {
                    const uint32_t bo = swz((uint32_t)(
                        (np * 16 + ((lane >> 4) << 3) + (lane & 7)) * 128 +
                        (ks * 16 + (((lane >> 3) & 1) << 3)) * 2));
                    uint32_t bh[4], bl[4];
                    ldsm4(kbh + bo, bh);
                    ldsm4(kbl + bo, bl);
                    mma16816(Sf[2 * np],     ahi, bh);
                    mma16816(Sf[2 * np],     ahi, bl);
                    mma16816(Sf[2 * np],     alo, bh);
                    mma16816(Sf[2 * np + 1], ahi, bh + 2);
                    mma16816(Sf[2 * np + 1], ahi, bl + 2);
                    mma16816(Sf[2 * np + 1], alo, bh + 2);
                }
            }

            // ---- mask (3 paths) + row max ----
            const bool aL = (actL >> kt) & 1, aR = (actR >> kt) & 1;
            const bool dg = (kt >= 2 * qt);
            float rm0 = -1e30f, rm1 = -1e30f;
            if (!dg && aL && aR) {
                #pragma unroll
                for (int n = 0; n < 8; n++) {
                    rm0 = fmaxf(rm0, fmaxf(Sf[n][0], Sf[n][1]));
                    rm1 = fmaxf(rm1, fmaxf(Sf[n][2], Sf[n][3]));
                }
            } else if (!dg) {
                const float bL = aL ? 0.f : -1e30f;
                const float bR = aR ? 0.f : -1e30f;
                #pragma unroll
                for (int n = 0; n < 8; n++) {
                    const float b = (n < 4) ? bL : bR;
                    Sf[n][0] += b; Sf[n][1] += b;
                    Sf[n][2] += b; Sf[n][3] += b;
                    rm0 = fmaxf(rm0, fmaxf(Sf[n][0], Sf[n][1]));
                    rm1 = fmaxf(rm1, fmaxf(Sf[n][2], Sf[n][3]));
                }
            } else {
                const int cb = kt * KTC;
                #pragma unroll
                for (int n = 0; n < 8; n++) {
                    const bool an = (n < 4) ? aL : aR;
                    const int c0 = cb + n * 8 + ((lane & 3) << 1);
                    const bool k00 = an && (c0     <= gr0);
                    const bool k01 = an && (c0 + 1 <= gr0);
                    const bool k10 = an && (c0     <= gr1);
                    const bool k11 = an && (c0 + 1 <= gr1);
                    Sf[n][0] = k00 ? Sf[n][0] : -1e30f;
                    Sf[n][1] = k01 ? Sf[n][1] : -1e30f;
                    Sf[n][2] = k10 ? Sf[n][2] : -1e30f;
                    Sf[n][3] = k11 ? Sf[n][3] : -1e30f;
                    rm0 = fmaxf(rm0, fmaxf(Sf[n][0], Sf[n][1]));
                    rm1 = fmaxf(rm1, fmaxf(Sf[n][2], Sf[n][3]));
                }
            }
            rm0 = fmaxf(rm0, __shfl_xor_sync(0xffffffffu, rm0, 1));
            rm0 = fmaxf(rm0, __shfl_xor_sync(0xffffffffu, rm0, 2));
            rm1 = fmaxf(rm1, __shfl_xor_sync(0xffffffffu, rm1, 1));
            rm1 = fmaxf(rm1, __shfl_xor_sync(0xffffffffu, rm1, 2));

            const float nm0 = fmaxf(m0, rm0), nm1 = fmaxf(m1, rm1);
            const float corr0 = ex2(m0 - nm0), corr1 = ex2(m1 - nm1);
            m0 = nm0; m1 = nm1;

            // ---- ex2 + packed P hi/lo fragments ----
            uint32_t Pah[4][4], Pal[4][4];
            float rs0 = 0.f, rs1 = 0.f;
            #pragma unroll
            for (int ks = 0; ks < 4; ks++) {
                #pragma unroll
                for (int j = 0; j < 2; j++) {
                    const int n = 2 * ks + j;
                    float e0 = ex2(Sf[n][0] - nm0);
                    float e1 = ex2(Sf[n][1] - nm0);
                    float e2 = ex2(Sf[n][2] - nm1);
                    float e3 = ex2(Sf[n][3] - nm1);
                    rs0 += e0 + e1;
                    rs1 += e2 + e3;
                    uint32_t h01 = pkhf(e0, e1);
                    uint32_t h23 = pkhf(e2, e3);
                    float2 f01 = unpkhf(h01);
                    float2 f23 = unpkhf(h23);
                    Pah[ks][2 * j]     = h01;
                    Pah[ks][2 * j + 1] = h23;
                    Pal[ks][2 * j]     = pkhf(e0 - f01.x, e1 - f01.y);
                    Pal[ks][2 * j + 1] = pkhf(e2 - f23.x, e3 - f23.y);
                }
            }
            rs0 += __shfl_xor_sync(0xffffffffu, rs0, 1);
            rs0 += __shfl_xor_sync(0xffffffffu, rs0, 2);
            rs1 += __shfl_xor_sync(0xffffffffu, rs1, 1);
            rs1 += __shfl_xor_sync(0xffffffffu, rs1, 2);
            l0s = l0s * corr0 + rs0;
            l1s = l1s * corr1 + rs1;

            // ---- rescale O, then PV: (Phi + Plo) x Vhi ----
            #pragma unroll
            for (int n = 0; n < 8; n++) {
                Of[n][0] *= corr0; Of[n][1] *= corr0;
                Of[n][2] *= corr1; Of[n][3] *= corr1;
            }
            #pragma unroll
            for (int ks = 0; ks < 4; ks++) {
                #pragma unroll
                for (int np = 0; np < 4; np++) {
                    const uint32_t vo = swz((uint32_t)(
                        (ks * 16 + (lane & 15)) * 128 +
                        (np * 16 + ((lane >> 4) << 3)) * 2));
                    uint32_t vh[4];
                    ldsm4t(vbh + vo, vh);
                    mma16816(Of[2 * np],     Pah[ks], vh);
                    mma16816(Of[2 * np],     Pal[ks], vh);
                    mma16816(Of[2 * np + 1], Pah[ks], vh + 2);
                    mma16816(Of[2 * np + 1], Pal[ks], vh + 2);
                }
            }

            kt = nkt;
            stage ^= 1;
        }

        // ---- write partial (unnormalized O + m + l) ----
        const int pidx = (h * NQT + qt) * 4 + ch;
        #pragma unroll
        for (int n = 0; n < 8; n++) {
            const int c = n * 8 + ((lane & 3) << 1);
            *(float2*)&g_pO[pidx][lr0][c]     = make_float2(Of[n][0], Of[n][1]);
            *(float2*)&g_pO[pidx][lr0 + 8][c] = make_float2(Of[n][2], Of[n][3]);
        }
        if ((lane & 3) == 0) {
            g_pm[pidx][lr0]     = m0;  g_pl[pidx][lr0]     = l0s;
            g_pm[pidx][lr0 + 8] = m1;  g_pl[pidx][lr0 + 8] = l1s;
        }
    }
}

// ---------------------------------------------------------------------------
// Kernel 3: combine partials -> normalized output.
// One CTA per (h, qt); thread t: row = t/2, col-half = (t&1)*32.
// ---------------------------------------------------------------------------
__global__ void __launch_bounds__(256)
combine_kernel(float* __restrict__ out) {
    const int bx = blockIdx.x;
    const int h  = bx & (NH - 1);
    const int qt = bx >> 4;
    const int npart = (2 * qt + 9) >> 3;   // ceil((2qt+2)/8)
    const int tid = threadIdx.x;
    const int row = tid >> 1;
    const int c0  = (tid & 1) * 32;
    const int base = (h * NQT + qt) * 4;

    float mm[4], ll[4];
    float M = -1e30f;
    #pragma unroll
    for (int p = 0; p < 4; p++) {
        if (p < npart) {
            mm[p] = g_pm[base + p][row];
            ll[p] = g_pl[base + p][row];
            M = fmaxf(M, mm[p]);
        }
    }
    float L = 0.f, wt[4];
    #pragma unroll
    for (int p = 0; p < 4; p++) {
        if (p < npart) {
            wt[p] = ex2(mm[p] - M);
            L += ll[p] * wt[p];
        }
    }
    const float inv = (L > 0.f) ? (1.f / L) : 0.f;

    float* ob = out + ((size_t)(h * SEQ + qt * QTR + row)) * DIM + c0;
    #pragma unroll
    for (int cc = 0; cc < 32; cc += 4) {
        float4 acc = make_float4(0.f, 0.f, 0.f, 0.f);
        #pragma unroll
        for (int p = 0; p < 4; p++) {
            if (p < npart) {
                float4 v = *(const float4*)&g_pO[base + p][row][c0 + cc];
                acc.x += v.x * wt[p]; acc.y += v.y * wt[p];
                acc.z += v.z * wt[p]; acc.w += v.w * wt[p];
            }
        }
        *(float4*)(ob + cc) = make_float4(acc.x * inv, acc.y * inv,
                                          acc.z * inv, acc.w * inv);
    }
}

// ---------------------------------------------------------------------------
// Launch
// ---------------------------------------------------------------------------
extern "C" void kernel_launch(void* const* d_in, const int* in_sizes, int n_in,
                              void* d_out, int out_size) {
    const float* qry  = (const float*)d_in[0];
    const float* key  = (const float*)d_in[1];
    const float* val  = (const float*)d_in[2];
    const int*   mask = (const int*)d_in[3];
    float* out = (float*)d_out;

    int nblk = NH * NB * NB;                // 65536
    int cta  = (nblk / 4 * 32 + 255) / 256; // 2048
    block_mask_kernel<<<cta, 256>>>(mask);

    cvt_all<<<3 * CVT_CTAS, 256>>>(qry, key, val);

    static int attr_set = 0;
    if (!attr_set) {
        cudaFuncSetAttribute(attn_mma,
                             cudaFuncAttributeMaxDynamicSharedMemorySize, SMEM_BYTES);
        attr_set = 1;
    }
    attn_mma<<<2 * NSM, 256, SMEM_BYTES>>>();

    combine_kernel<<<NH * NQT, 256>>>(out);
}

// round 16
// speedup vs baseline: 15.1894x; 1.1021x over previous
#include <cuda_runtime.h>
#include <cuda_fp16.h>
#include <math.h>
#include <stdint.h>

#define SEQ  2048
#define DIM  64
#define NH   16
#define NB   64            // 32-wide mask blocks per dim
#define QTR  128           // q rows per work item
#define KTC  64            // k cols per tile
#define NQT  (SEQ / QTR)   // 16
#define NSM  152
#define NELEM (NH * SEQ * DIM)
#define LOG2E 1.4426950408889634f
#define RPH   40           // chunk-items per head
#define NWORK (NH * RPH)   // 640

__device__ unsigned char g_bm[NH * NB * NB];
__device__ int g_ctr;
// fp16 hi/lo planes (row-major [h][r][d], 128B rows); Q pre-scaled by log2e.
__device__ uint16_t g_qhi[NELEM], g_qlo[NELEM];
__device__ uint16_t g_khi[NELEM], g_klo[NELEM];
__device__ uint16_t g_vhi[NELEM];
// split-softmax partials: up to 4 chunks per (h, qt)
__device__ float g_pO[NH * NQT * 4][QTR][DIM];   // unnormalized O
__device__ float g_pm[NH * NQT * 4][QTR];        // row max (log2 domain)
__device__ float g_pl[NH * NQT * 4][QTR];        // row sum

// rank -> (qt, chunk), heavy q-tiles first
__device__ const unsigned char c_r2qt[RPH] = {
    15,15,15,15, 14,14,14,14, 13,13,13,13, 12,12,12,12,
    11,11,11, 10,10,10, 9,9,9, 8,8,8,
    7,7, 6,6, 5,5, 4,4, 3, 2, 1, 0};
__device__ const unsigned char c_r2ch[RPH] = {
    0,1,2,3, 0,1,2,3, 0,1,2,3, 0,1,2,3,
    0,1,2, 0,1,2, 0,1,2, 0,1,2,
    0,1, 0,1, 0,1, 0,1, 0, 0, 0, 0};

// ---------------- smem layout (bytes) ----------------
#define OF_QHI 128
#define OF_QLO (OF_QHI + 16384)     // Q planes: 128 x 64 fp16 each
#define OF_KV  (OF_QLO + 16384)     // 2 stages x (KHI|KLO|VHI), 8KB each
#define STG_SZ 24576
#define SMEM_BYTES (OF_KV + 2 * STG_SZ)   // 82048

// ---------------------------------------------------------------------------
// helpers (baseline PTX only)
// ---------------------------------------------------------------------------
__device__ __forceinline__ uint32_t smem_u32(const void* p) {
    uint32_t a;
    asm("{ .reg .u64 t; cvta.to.shared.u64 t, %1; cvt.u32.u64 %0, t; }"
        : "=r"(a) : "l"(p));
    return a;
}
__device__ __forceinline__ uint32_t swz(uint32_t o) { return o ^ ((o >> 3) & 0x70); }

__device__ __forceinline__ void ldsm4(uint32_t addr, uint32_t r[4]) {
    asm volatile("ldmatrix.sync.aligned.m8n8.x4.shared.b16 {%0,%1,%2,%3}, [%4];"
        : "=r"(r[0]), "=r"(r[1]), "=r"(r[2]), "=r"(r[3]) : "r"(addr));
}
__device__ __forceinline__ void ldsm4t(uint32_t addr, uint32_t r[4]) {
    asm volatile("ldmatrix.sync.aligned.m8n8.x4.trans.shared.b16 {%0,%1,%2,%3}, [%4];"
        : "=r"(r[0]), "=r"(r[1]), "=r"(r[2]), "=r"(r[3]) : "r"(addr));
}
__device__ __forceinline__ void mma16816(float c[4], const uint32_t a[4],
                                         const uint32_t b[2]) {
    asm volatile(
        "mma.sync.aligned.m16n8k16.row.col.f32.f16.f16.f32 "
        "{%0,%1,%2,%3}, {%4,%5,%6,%7}, {%8,%9}, {%0,%1,%2,%3};"
        : "+f"(c[0]), "+f"(c[1]), "+f"(c[2]), "+f"(c[3])
        : "r"(a[0]), "r"(a[1]), "r"(a[2]), "r"(a[3]), "r"(b[0]), "r"(b[1]));
}
__device__ __forceinline__ uint32_t pkhf(float x, float y) {
    __half2 h = __floats2half2_rn(x, y);
    return *(uint32_t*)&h;
}
__device__ __forceinline__ float2 unpkhf(uint32_t v) {
    __half2 h = *(__half2*)&v;
    return __half22float2(h);
}
__device__ __forceinline__ float ex2(float x) {
    float r;
    asm("ex2.approx.f32 %0, %1;" : "=f"(r) : "f"(x));
    return r;
}
__device__ __forceinline__ void cp16(uint32_t sd, const void* gs) {
    asm volatile("cp.async.cg.shared.global [%0], [%1], 16;"
                 :: "r"(sd), "l"(gs));
}
#define CP_COMMIT() asm volatile("cp.async.commit_group;" ::: "memory")
#define CP_WAIT0()  asm volatile("cp.async.wait_group 0;" ::: "memory")

// ---------------------------------------------------------------------------
// Kernel 1 (fused prep): CTAs [0, MASK_CTAS) do block-OR mask pooling;
// CTAs [MASK_CTAS, MASK_CTAS + 3*CVT_CTAS) do fp32 -> fp16 plane conversion.
// The two jobs are independent; fusing lets them overlap on the memory system.
// ---------------------------------------------------------------------------
#define MASK_CTAS 2048
#define CVT_CTAS (NELEM / 1024)    // 2048 CTAs per tensor

__device__ __forceinline__ void do_block_mask(const int* __restrict__ mask,
                                              int cb) {
    if (cb == 0 && threadIdx.x == 0) g_ctr = 0;
    const int gwarp = (cb * 256 + (int)threadIdx.x) >> 5;
    const int lane  = threadIdx.x & 31;
    const int grp   = lane >> 3;
    const int sub   = lane & 7;
    const int blk   = gwarp * 4 + grp;
    if (blk >= NH * NB * NB) return;
    const int h   = blk >> 12;
    const int rem = blk & (NB * NB - 1);
    const int qb  = rem >> 6;
    const int kb  = rem & (NB - 1);
    const unsigned gm = 0xFFu << (grp * 8);

    unsigned char res = 0;
    if (kb <= qb) {
        const int* base = mask + ((size_t)h * SEQ + (size_t)qb * 32) * SEQ
                               + (size_t)kb * 32;
        int4 a = *((const int4*)base + sub);
        unsigned bal = __ballot_sync(gm, (a.x | a.y | a.z | a.w) != 0);
        if (bal) {
            res = 1;
        } else {
            int acc = 0;
            for (int r = 1; r < 32; r++) {
                int4 b = *((const int4*)(base + (size_t)r * SEQ) + sub);
                acc |= b.x | b.y | b.z | b.w;
            }
            unsigned bal2 = __ballot_sync(gm, acc != 0);
            res = bal2 ? 1 : 0;
        }
    }
    if (sub == 0) g_bm[blk] = res;
}

__device__ __forceinline__ void do_cvt(const float* __restrict__ q,
                                       const float* __restrict__ k,
                                       const float* __restrict__ v, int cb) {
    const int which = cb / CVT_CTAS;
    const int sub   = cb % CVT_CTAS;
    const int i     = (sub * 256 + (int)threadIdx.x) * 4;
    const float* src = (which == 0) ? q : (which == 1) ? k : v;

    float4 x = *(const float4*)(src + i);
    if (which == 0) {
        x.x *= LOG2E; x.y *= LOG2E; x.z *= LOG2E; x.w *= LOG2E;
    }
    uint32_t h01 = pkhf(x.x, x.y);
    uint32_t h23 = pkhf(x.z, x.w);
    if (which == 2) {
        *(uint2*)(g_vhi + i) = make_uint2(h01, h23);
        return;
    }
    uint16_t* hi = (which == 0) ? g_qhi : g_khi;
    uint16_t* lo = (which == 0) ? g_qlo : g_klo;
    float2 f01 = unpkhf(h01);
    float2 f23 = unpkhf(h23);
    *(uint2*)(hi + i) = make_uint2(h01, h23);
    *(uint2*)(lo + i) = make_uint2(pkhf(x.x - f01.x, x.y - f01.y),
                                   pkhf(x.z - f23.x, x.w - f23.y));
}

__global__ void prep_kernel(const int* __restrict__ mask,
                            const float* __restrict__ q,
                            const float* __restrict__ k,
                            const float* __restrict__ v) {
    const int bx = blockIdx.x;
    if (bx < MASK_CTAS) do_block_mask(mask, bx);
    else                do_cvt(q, k, v, bx - MASK_CTAS);
}

// ---------------------------------------------------------------------------
// Kernel 2: chunked block-sparse causal flash attention (unchanged from R15).
// ---------------------------------------------------------------------------
__global__ void __launch_bounds__(256, 2)
attn_mma() {
    extern __shared__ char smem[];
    const uint32_t sb = smem_u32(smem);
    int* widx = (int*)smem;
    unsigned int* bmap = (unsigned int*)(smem + 8);

    const int tid  = threadIdx.x;
    const int w    = tid >> 5;
    const int lane = tid & 31;
    const int R0   = w * 16;

    for (;;) {
        __syncthreads();
        if (tid == 0) { *widx = atomicAdd(&g_ctr, 1); *bmap = 0u; }
        __syncthreads();
        const int idx = *widx;
        if (idx >= NWORK) break;
        const int h    = idx & (NH - 1);
        const int rank = idx >> 4;
        const int qt   = c_r2qt[rank];
        const int ch   = c_r2ch[rank];

        // ---- stage Q planes ----
        {
            const size_t gq = ((size_t)h * SEQ + (size_t)qt * QTR) * DIM;
            const char* qh = (const char*)(g_qhi + gq);
            const char* ql = (const char*)(g_qlo + gq);
            #pragma unroll
            for (int j = 0; j < 4; j++) {
                int chn = tid + j * 256;
                uint32_t so = swz((uint32_t)(chn * 16));
                cp16(sb + OF_QHI + so, qh + chn * 16);
                cp16(sb + OF_QLO + so, ql + chn * 16);
            }
        }

        // ---- per-warp activity bitmaps ----
        const unsigned char* bmp = g_bm +
            ((size_t)h * NB + (qt * 4 + (w >> 1))) * NB;
        const int mb0 = bmp[2 * lane], mb1 = bmp[2 * lane + 1];
        const uint32_t actL = __ballot_sync(0xffffffffu, mb0 != 0);
        const uint32_t actR = __ballot_sync(0xffffffffu, mb1 != 0);
        if (lane == 0) atomicOr(bmap, actL | actR);
        __syncthreads();
        uint32_t bits = *bmap & (0xFFu << (ch * 8));

        float Of[8][4];
        #pragma unroll
        for (int n = 0; n < 8; n++)
            #pragma unroll
            for (int j = 0; j < 4; j++) Of[n][j] = 0.f;
        float m0 = -1e30f, m1 = -1e30f, l0s = 0.f, l1s = 0.f;
        const int lr0 = R0 + (lane >> 2);
        const int gr0 = qt * QTR + lr0;
        const int gr1 = gr0 + 8;

        int kt = -1, stage = 0;
        if (bits) {
            kt = __ffs(bits) - 1; bits &= bits - 1;
            const size_t g = ((size_t)h * SEQ + (size_t)kt * KTC) * DIM;
            const uint32_t s0 = sb + OF_KV;
            #pragma unroll
            for (int j = 0; j < 2; j++) {
                int chn = tid + j * 256;
                uint32_t so = swz((uint32_t)(chn * 16));
                cp16(s0 + so,         (const char*)(g_khi + g) + chn * 16);
                cp16(s0 + 8192 + so,  (const char*)(g_klo + g) + chn * 16);
                cp16(s0 + 16384 + so, (const char*)(g_vhi + g) + chn * 16);
            }
            CP_COMMIT();
        }

        while (kt >= 0) {
            int nkt = -1;
            if (bits) { nkt = __ffs(bits) - 1; bits &= bits - 1; }

            CP_WAIT0();
            __syncthreads();

            if (nkt >= 0) {
                const size_t g = ((size_t)h * SEQ + (size_t)nkt * KTC) * DIM;
                const uint32_t s1 = sb + OF_KV + (stage ^ 1) * STG_SZ;
                #pragma unroll
                for (int j = 0; j < 2; j++) {
                    int chn = tid + j * 256;
                    uint32_t so = swz((uint32_t)(chn * 16));
                    cp16(s1 + so,         (const char*)(g_khi + g) + chn * 16);
                    cp16(s1 + 8192 + so,  (const char*)(g_klo + g) + chn * 16);
                    cp16(s1 + 16384 + so, (const char*)(g_vhi + g) + chn * 16);
                }
                CP_COMMIT();
            }

            const uint32_t kbh = sb + OF_KV + stage * STG_SZ;
            const uint32_t kbl = kbh + 8192;
            const uint32_t vbh = kbh + 16384;

            // ---- QK ----
            float Sf[8][4];
            #pragma unroll
            for (int n = 0; n < 8; n++)
                #pragma unroll
                for (int j = 0; j < 4; j++) Sf[n][j] = 0.f;

            #pragma unroll
            for (int ks = 0; ks < 4; ks++) {
                uint32_t ahi[4], alo[4];
                const int arow = R0 + (lane & 15);
                const int acol = ks * 16 + ((lane >> 4) << 3);
                const uint32_t ao = swz((uint32_t)(arow * 128 + acol * 2));
                ldsm4(sb + OF_QHI + ao, ahi);
                ldsm4(sb + OF_QLO + ao, alo);
                #pragma unroll
                for (int np = 0; np < 4; np++) {
                    const uint32_t bo = swz((uint32_t)(
                        (np * 16 + ((lane >> 4) << 3) + (lane & 7)) * 128 +
                        (ks * 16 + (((lane >> 3) & 1) << 3)) * 2));
                    uint32_t bh[4], bl[4];
                    ldsm4(kbh + bo, bh);
                    ldsm4(kbl + bo, bl);
                    mma16816(Sf[2 * np],     ahi, bh);
                    mma16816(Sf[2 * np],     ahi, bl);
                    mma16816(Sf[2 * np],     alo, bh);
                    mma16816(Sf[2 * np + 1], ahi, bh + 2);
                    mma16816(Sf[2 * np + 1], ahi, bl + 2);
                    mma16816(Sf[2 * np + 1], alo, bh + 2);
                }
            }

            // ---- mask + row max ----
            const bool aL = (actL >> kt) & 1, aR = (actR >> kt) & 1;
            const bool dg = (kt >= 2 * qt);
            float rm0 = -1e30f, rm1 = -1e30f;
            if (!dg && aL && aR) {
                #pragma unroll
                for (int n = 0; n < 8; n++) {
                    rm0 = fmaxf(rm0, fmaxf(Sf[n][0], Sf[n][1]));
                    rm1 = fmaxf(rm1, fmaxf(Sf[n][2], Sf[n][3]));
                }
            } else if (!dg) {
                const float bL = aL ? 0.f : -1e30f;
                const float bR = aR ? 0.f : -1e30f;
                #pragma unroll
                for (int n = 0; n < 8; n++) {
                    const float b = (n < 4) ? bL : bR;
                    Sf[n][0] += b; Sf[n][1] += b;
                    Sf[n][2] += b; Sf[n][3] += b;
                    rm0 = fmaxf(rm0, fmaxf(Sf[n][0], Sf[n][1]));
                    rm1 = fmaxf(rm1, fmaxf(Sf[n][2], Sf[n][3]));
                }
            } else {
                const int cb = kt * KTC;
                #pragma unroll
                for (int n = 0; n < 8; n++) {
                    const bool an = (n < 4) ? aL : aR;
                    const int c0 = cb + n * 8 + ((lane & 3) << 1);
                    const bool k00 = an && (c0     <= gr0);
                    const bool k01 = an && (c0 + 1 <= gr0);
                    const bool k10 = an && (c0     <= gr1);
                    const bool k11 = an && (c0 + 1 <= gr1);
                    Sf[n][0] = k00 ? Sf[n][0] : -1e30f;
                    Sf[n][1] = k01 ? Sf[n][1] : -1e30f;
                    Sf[n][2] = k10 ? Sf[n][2] : -1e30f;
                    Sf[n][3] = k11 ? Sf[n][3] : -1e30f;
                    rm0 = fmaxf(rm0, fmaxf(Sf[n][0], Sf[n][1]));
                    rm1 = fmaxf(rm1, fmaxf(Sf[n][2], Sf[n][3]));
                }
            }
            rm0 = fmaxf(rm0, __shfl_xor_sync(0xffffffffu, rm0, 1));
            rm0 = fmaxf(rm0, __shfl_xor_sync(0xffffffffu, rm0, 2));
            rm1 = fmaxf(rm1, __shfl_xor_sync(0xffffffffu, rm1, 1));
            rm1 = fmaxf(rm1, __shfl_xor_sync(0xffffffffu, rm1, 2));

            const float nm0 = fmaxf(m0, rm0), nm1 = fmaxf(m1, rm1);
            const float corr0 = ex2(m0 - nm0), corr1 = ex2(m1 - nm1);
            m0 = nm0; m1 = nm1;

            // ---- ex2 + packed P hi/lo fragments ----
            uint32_t Pah[4][4], Pal[4][4];
            float rs0 = 0.f, rs1 = 0.f;
            #pragma unroll
            for (int ks = 0; ks < 4; ks++) {
                #pragma unroll
                for (int j = 0; j < 2; j++) {
                    const int n = 2 * ks + j;
                    float e0 = ex2(Sf[n][0] - nm0);
                    float e1 = ex2(Sf[n][1] - nm0);
                    float e2 = ex2(Sf[n][2] - nm1);
                    float e3 = ex2(Sf[n][3] - nm1);
                    rs0 += e0 + e1;
                    rs1 += e2 + e3;
                    uint32_t h01 = pkhf(e0, e1);
                    uint32_t h23 = pkhf(e2, e3);
                    float2 f01 = unpkhf(h01);
                    float2 f23 = unpkhf(h23);
                    Pah[ks][2 * j]     = h01;
                    Pah[ks][2 * j + 1] = h23;
                    Pal[ks][2 * j]     = pkhf(e0 - f01.x, e1 - f01.y);
                    Pal[ks][2 * j + 1] = pkhf(e2 - f23.x, e3 - f23.y);
                }
            }
            rs0 += __shfl_xor_sync(0xffffffffu, rs0, 1);
            rs0 += __shfl_xor_sync(0xffffffffu, rs0, 2);
            rs1 += __shfl_xor_sync(0xffffffffu, rs1, 1);
            rs1 += __shfl_xor_sync(0xffffffffu, rs1, 2);
            l0s = l0s * corr0 + rs0;
            l1s = l1s * corr1 + rs1;

            // ---- rescale O, then PV ----
            #pragma unroll
            for (int n = 0; n < 8; n++) {
                Of[n][0] *= corr0; Of[n][1] *= corr0;
                Of[n][2] *= corr1; Of[n][3] *= corr1;
            }
            #pragma unroll
            for (int ks = 0; ks < 4; ks++) {
                #pragma unroll
                for (int np = 0; np < 4; np++) {
                    const uint32_t vo = swz((uint32_t)(
                        (ks * 16 + (lane & 15)) * 128 +
                        (np * 16 + ((lane >> 4) << 3)) * 2));
                    uint32_t vh[4];
                    ldsm4t(vbh + vo, vh);
                    mma16816(Of[2 * np],     Pah[ks], vh);
                    mma16816(Of[2 * np],     Pal[ks], vh);
                    mma16816(Of[2 * np + 1], Pah[ks], vh + 2);
                    mma16816(Of[2 * np + 1], Pal[ks], vh + 2);
                }
            }

            kt = nkt;
            stage ^= 1;
        }

        // ---- write partial ----
        const int pidx = (h * NQT + qt) * 4 + ch;
        #pragma unroll
        for (int n = 0; n < 8; n++) {
            const int c = n * 8 + ((lane & 3) << 1);
            *(float2*)&g_pO[pidx][lr0][c]     = make_float2(Of[n][0], Of[n][1]);
            *(float2*)&g_pO[pidx][lr0 + 8][c] = make_float2(Of[n][2], Of[n][3]);
        }
        if ((lane & 3) == 0) {
            g_pm[pidx][lr0]     = m0;  g_pl[pidx][lr0]     = l0s;
            g_pm[pidx][lr0 + 8] = m1;  g_pl[pidx][lr0 + 8] = l1s;
        }
    }
}

// ---------------------------------------------------------------------------
// Kernel 3: combine partials -> normalized output.
// One CTA per (h, qt, 32-row group): 1024 CTAs x 256 threads.
// Thread t: row = rg*32 + t/8, 8-col group = (t&7)*8.
// ---------------------------------------------------------------------------
__global__ void __launch_bounds__(256)
combine_kernel(float* __restrict__ out) {
    const int bx = blockIdx.x;
    const int h  = bx & (NH - 1);
    const int qt = (bx >> 4) & (NQT - 1);
    const int rg = bx >> 8;                // 0..3
    const int npart = (2 * qt + 9) >> 3;   // ceil((2qt+2)/8)
    const int tid = threadIdx.x;
    const int row = rg * 32 + (tid >> 3);
    const int c0  = (tid & 7) * 8;
    const int base = (h * NQT + qt) * 4;

    float M = -1e30f, mm[4], ll[4];
    #pragma unroll
    for (int p = 0; p < 4; p++) {
        if (p < npart) {
            mm[p] = g_pm[base + p][row];
            ll[p] = g_pl[base + p][row];
            M = fmaxf(M, mm[p]);
        }
    }
    float L = 0.f, wt[4];
    #pragma unroll
    for (int p = 0; p < 4; p++) {
        if (p < npart) {
            wt[p] = ex2(mm[p] - M);
            L += ll[p] * wt[p];
        }
    }
    const float inv = (L > 0.f) ? (1.f / L) : 0.f;

    float* ob = out + ((size_t)(h * SEQ + qt * QTR + row)) * DIM + c0;
    #pragma unroll
    for (int cc = 0; cc < 8; cc += 4) {
        float4 acc = make_float4(0.f, 0.f, 0.f, 0.f);
        #pragma unroll
        for (int p = 0; p < 4; p++) {
            if (p < npart) {
                float4 v = *(const float4*)&g_pO[base + p][row][c0 + cc];
                acc.x += v.x * wt[p]; acc.y += v.y * wt[p];
                acc.z += v.z * wt[p]; acc.w += v.w * wt[p];
            }
        }
        *(float4*)(ob + cc) = make_float4(acc.x * inv, acc.y * inv,
                                          acc.z * inv, acc.w * inv);
    }
}

// ---------------------------------------------------------------------------
// Launch
// ---------------------------------------------------------------------------
extern "C" void kernel_launch(void* const* d_in, const int* in_sizes, int n_in,
                              void* d_out, int out_size) {
    const float* qry  = (const float*)d_in[0];
    const float* key  = (const float*)d_in[1];
    const float* val  = (const float*)d_in[2];
    const int*   mask = (const int*)d_in[3];
    float* out = (float*)d_out;

    prep_kernel<<<MASK_CTAS + 3 * CVT_CTAS, 256>>>(mask, qry, key, val);

    static int attr_set = 0;
    if (!attr_set) {
        cudaFuncSetAttribute(attn_mma,
                             cudaFuncAttributeMaxDynamicSharedMemorySize, SMEM_BYTES);
        attr_set = 1;
    }
    attn_mma<<<2 * NSM, 256, SMEM_BYTES>>>();

    combine_kernel<<<NH * NQT * 4, 256>>>(out);
}

// round 17
// speedup vs baseline: 16.4294x; 1.0816x over previous
#include <cuda_runtime.h>
#include <cuda_fp16.h>
#include <math.h>
#include <stdint.h>

#define SEQ  2048
#define DIM  64
#define NH   16
#define NB   64            // 32-wide mask blocks per dim
#define QTR  128           // q rows per work item
#define KTC  64            // k cols per tile
#define NQT  (SEQ / QTR)   // 16
#define NSM  152
#define NELEM (NH * SEQ * DIM)
#define LOG2E 1.4426950408889634f
#define RPH   40           // chunk-items per head
#define NWORK (NH * RPH)   // 640

__device__ unsigned char g_bm[NH * NB * NB];
__device__ int g_ctr;
// fp16 hi/lo planes (row-major [h][r][d], 128B rows); Q pre-scaled by log2e.
__device__ uint16_t g_qhi[NELEM], g_qlo[NELEM];
__device__ uint16_t g_khi[NELEM], g_klo[NELEM];
__device__ uint16_t g_vhi[NELEM];
// split-softmax partials: up to 4 chunks per (h, qt)
__device__ float g_pO[NH * NQT * 4][QTR][DIM];   // unnormalized O
__device__ float g_pm[NH * NQT * 4][QTR];        // row max (log2 domain)
__device__ float g_pl[NH * NQT * 4][QTR];        // row sum

// rank -> (qt, chunk), heavy q-tiles first
__device__ const unsigned char c_r2qt[RPH] = {
    15,15,15,15, 14,14,14,14, 13,13,13,13, 12,12,12,12,
    11,11,11, 10,10,10, 9,9,9, 8,8,8,
    7,7, 6,6, 5,5, 4,4, 3, 2, 1, 0};
__device__ const unsigned char c_r2ch[RPH] = {
    0,1,2,3, 0,1,2,3, 0,1,2,3, 0,1,2,3,
    0,1,2, 0,1,2, 0,1,2, 0,1,2,
    0,1, 0,1, 0,1, 0,1, 0, 0, 0, 0};

// ---------------- smem layout (bytes) ----------------
#define OF_QHI 128
#define OF_QLO (OF_QHI + 16384)     // Q planes: 128 x 64 fp16 each
#define OF_KV  (OF_QLO + 16384)     // 2 stages x (KHI|KLO|VHI), 8KB each
#define STG_SZ 24576
#define SMEM_BYTES (OF_KV + 2 * STG_SZ)   // 82048

// ---------------------------------------------------------------------------
// helpers (baseline PTX only)
// ---------------------------------------------------------------------------
__device__ __forceinline__ uint32_t smem_u32(const void* p) {
    uint32_t a;
    asm("{ .reg .u64 t; cvta.to.shared.u64 t, %1; cvt.u32.u64 %0, t; }"
        : "=r"(a) : "l"(p));
    return a;
}
__device__ __forceinline__ uint32_t swz(uint32_t o) { return o ^ ((o >> 3) & 0x70); }

__device__ __forceinline__ void ldsm4(uint32_t addr, uint32_t r[4]) {
    asm volatile("ldmatrix.sync.aligned.m8n8.x4.shared.b16 {%0,%1,%2,%3}, [%4];"
        : "=r"(r[0]), "=r"(r[1]), "=r"(r[2]), "=r"(r[3]) : "r"(addr));
}
__device__ __forceinline__ void ldsm4t(uint32_t addr, uint32_t r[4]) {
    asm volatile("ldmatrix.sync.aligned.m8n8.x4.trans.shared.b16 {%0,%1,%2,%3}, [%4];"
        : "=r"(r[0]), "=r"(r[1]), "=r"(r[2]), "=r"(r[3]) : "r"(addr));
}
__device__ __forceinline__ void mma16816(float c[4], const uint32_t a[4],
                                         const uint32_t b[2]) {
    asm volatile(
        "mma.sync.aligned.m16n8k16.row.col.f32.f16.f16.f32 "
        "{%0,%1,%2,%3}, {%4,%5,%6,%7}, {%8,%9}, {%0,%1,%2,%3};"
        : "+f"(c[0]), "+f"(c[1]), "+f"(c[2]), "+f"(c[3])
        : "r"(a[0]), "r"(a[1]), "r"(a[2]), "r"(a[3]), "r"(b[0]), "r"(b[1]));
}
__device__ __forceinline__ uint32_t pkhf(float x, float y) {
    __half2 h = __floats2half2_rn(x, y);
    return *(uint32_t*)&h;
}
__device__ __forceinline__ float2 unpkhf(uint32_t v) {
    __half2 h = *(__half2*)&v;
    return __half22float2(h);
}
__device__ __forceinline__ float ex2(float x) {
    float r;
    asm("ex2.approx.f32 %0, %1;" : "=f"(r) : "f"(x));
    return r;
}
__device__ __forceinline__ void cp16(uint32_t sd, const void* gs) {
    asm volatile("cp.async.cg.shared.global [%0], [%1], 16;"
                 :: "r"(sd), "l"(gs));
}
#define CP_COMMIT() asm volatile("cp.async.commit_group;" ::: "memory")
#define CP_WAIT0()  asm volatile("cp.async.wait_group 0;" ::: "memory")

// ---------------------------------------------------------------------------
// Kernel 1 (fused prep): block-OR mask pooling + fp32 -> fp16 planes.
// cvt threads process 2 x float4 each (MLP=2).
// ---------------------------------------------------------------------------
#define MASK_CTAS 2048
#define CVT_CTAS (NELEM / 2048)    // 1024 CTAs per tensor

__device__ __forceinline__ void do_block_mask(const int* __restrict__ mask,
                                              int cb) {
    if (cb == 0 && threadIdx.x == 0) g_ctr = 0;
    const int gwarp = (cb * 256 + (int)threadIdx.x) >> 5;
    const int lane  = threadIdx.x & 31;
    const int grp   = lane >> 3;
    const int sub   = lane & 7;
    const int blk   = gwarp * 4 + grp;
    if (blk >= NH * NB * NB) return;
    const int h   = blk >> 12;
    const int rem = blk & (NB * NB - 1);
    const int qb  = rem >> 6;
    const int kb  = rem & (NB - 1);
    const unsigned gm = 0xFFu << (grp * 8);

    unsigned char res = 0;
    if (kb <= qb) {
        const int* base = mask + ((size_t)h * SEQ + (size_t)qb * 32) * SEQ
                               + (size_t)kb * 32;
        int4 a = *((const int4*)base + sub);
        unsigned bal = __ballot_sync(gm, (a.x | a.y | a.z | a.w) != 0);
        if (bal) {
            res = 1;
        } else {
            int acc = 0;
            for (int r = 1; r < 32; r++) {
                int4 b = *((const int4*)(base + (size_t)r * SEQ) + sub);
                acc |= b.x | b.y | b.z | b.w;
            }
            unsigned bal2 = __ballot_sync(gm, acc != 0);
            res = bal2 ? 1 : 0;
        }
    }
    if (sub == 0) g_bm[blk] = res;
}

__device__ __forceinline__ void do_cvt(const float* __restrict__ q,
                                       const float* __restrict__ k,
                                       const float* __restrict__ v, int cb) {
    const int which = cb / CVT_CTAS;
    const int sub   = cb % CVT_CTAS;
    const float* src = (which == 0) ? q : (which == 1) ? k : v;
    const int i0 = (sub * 256 + (int)threadIdx.x) * 8;

    // two independent float4 loads for MLP
    float4 x0 = *(const float4*)(src + i0);
    float4 x1 = *(const float4*)(src + i0 + 4);
    if (which == 0) {
        x0.x *= LOG2E; x0.y *= LOG2E; x0.z *= LOG2E; x0.w *= LOG2E;
        x1.x *= LOG2E; x1.y *= LOG2E; x1.z *= LOG2E; x1.w *= LOG2E;
    }
    uint32_t a01 = pkhf(x0.x, x0.y), a23 = pkhf(x0.z, x0.w);
    uint32_t b01 = pkhf(x1.x, x1.y), b23 = pkhf(x1.z, x1.w);
    if (which == 2) {
        *(uint4*)(g_vhi + i0) = make_uint4(a01, a23, b01, b23);
        return;
    }
    uint16_t* hi = (which == 0) ? g_qhi : g_khi;
    uint16_t* lo = (which == 0) ? g_qlo : g_klo;
    *(uint4*)(hi + i0) = make_uint4(a01, a23, b01, b23);
    float2 fa01 = unpkhf(a01), fa23 = unpkhf(a23);
    float2 fb01 = unpkhf(b01), fb23 = unpkhf(b23);
    *(uint4*)(lo + i0) = make_uint4(
        pkhf(x0.x - fa01.x, x0.y - fa01.y),
        pkhf(x0.z - fa23.x, x0.w - fa23.y),
        pkhf(x1.x - fb01.x, x1.y - fb01.y),
        pkhf(x1.z - fb23.x, x1.w - fb23.y));
}

__global__ void prep_kernel(const int* __restrict__ mask,
                            const float* __restrict__ q,
                            const float* __restrict__ k,
                            const float* __restrict__ v) {
    const int bx = blockIdx.x;
    if (bx < MASK_CTAS) do_block_mask(mask, bx);
    else                do_cvt(q, k, v, bx - MASK_CTAS);
}

// ---------------------------------------------------------------------------
// Kernel 2: chunked block-sparse causal flash attention.
// QK 3-term fp16 split; PV single term (P-hi x V-hi).
// ---------------------------------------------------------------------------
__global__ void __launch_bounds__(256, 2)
attn_mma() {
    extern __shared__ char smem[];
    const uint32_t sb = smem_u32(smem);
    int* widx = (int*)smem;
    unsigned int* bmap = (unsigned int*)(smem + 8);

    const int tid  = threadIdx.x;
    const int w    = tid >> 5;
    const int lane = tid & 31;
    const int R0   = w * 16;

    for (;;) {
        __syncthreads();
        if (tid == 0) { *widx = atomicAdd(&g_ctr, 1); *bmap = 0u; }
        __syncthreads();
        const int idx = *widx;
        if (idx >= NWORK) break;
        const int h    = idx & (NH - 1);
        const int rank = idx >> 4;
        const int qt   = c_r2qt[rank];
        const int ch   = c_r2ch[rank];

        // ---- stage Q planes ----
        {
            const size_t gq = ((size_t)h * SEQ + (size_t)qt * QTR) * DIM;
            const char* qh = (const char*)(g_qhi + gq);
            const char* ql = (const char*)(g_qlo + gq);
            #pragma unroll
            for (int j = 0; j < 4; j++) {
                int chn = tid + j * 256;
                uint32_t so = swz((uint32_t)(chn * 16));
                cp16(sb + OF_QHI + so, qh + chn * 16);
                cp16(sb + OF_QLO + so, ql + chn * 16);
            }
        }

        // ---- per-warp activity bitmaps ----
        const unsigned char* bmp = g_bm +
            ((size_t)h * NB + (qt * 4 + (w >> 1))) * NB;
        const int mb0 = bmp[2 * lane], mb1 = bmp[2 * lane + 1];
        const uint32_t actL = __ballot_sync(0xffffffffu, mb0 != 0);
        const uint32_t actR = __ballot_sync(0xffffffffu, mb1 != 0);
        if (lane == 0) atomicOr(bmap, actL | actR);
        __syncthreads();
        uint32_t bits = *bmap & (0xFFu << (ch * 8));

        float Of[8][4];
        #pragma unroll
        for (int n = 0; n < 8; n++)
            #pragma unroll
            for (int j = 0; j < 4; j++) Of[n][j] = 0.f;
        float m0 = -1e30f, m1 = -1e30f, l0s = 0.f, l1s = 0.f;
        const int lr0 = R0 + (lane >> 2);
        const int gr0 = qt * QTR + lr0;
        const int gr1 = gr0 + 8;

        int kt = -1, stage = 0;
        if (bits) {
            kt = __ffs(bits) - 1; bits &= bits - 1;
            const size_t g = ((size_t)h * SEQ + (size_t)kt * KTC) * DIM;
            const uint32_t s0 = sb + OF_KV;
            #pragma unroll
            for (int j = 0; j < 2; j++) {
                int chn = tid + j * 256;
                uint32_t so = swz((uint32_t)(chn * 16));
                cp16(s0 + so,         (const char*)(g_khi + g) + chn * 16);
                cp16(s0 + 8192 + so,  (const char*)(g_klo + g) + chn * 16);
                cp16(s0 + 16384 + so, (const char*)(g_vhi + g) + chn * 16);
            }
            CP_COMMIT();
        }

        while (kt >= 0) {
            int nkt = -1;
            if (bits) { nkt = __ffs(bits) - 1; bits &= bits - 1; }

            CP_WAIT0();
            __syncthreads();

            if (nkt >= 0) {
                const size_t g = ((size_t)h * SEQ + (size_t)nkt * KTC) * DIM;
                const uint32_t s1 = sb + OF_KV + (stage ^ 1) * STG_SZ;
                #pragma unroll
                for (int j = 0; j < 2; j++) {
                    int chn = tid + j * 256;
                    uint32_t so = swz((uint32_t)(chn * 16));
                    cp16(s1 + so,         (const char*)(g_khi + g) + chn * 16);
                    cp16(s1 + 8192 + so,  (const char*)(g_klo + g) + chn * 16);
                    cp16(s1 + 16384 + so, (const char*)(g_vhi + g) + chn * 16);
                }
                CP_COMMIT();
            }

            const uint32_t kbh = sb + OF_KV + stage * STG_SZ;
            const uint32_t kbl = kbh + 8192;
            const uint32_t vbh = kbh + 16384;

            // ---- QK: S[16 x 64] per warp, 3 split terms ----
            float Sf[8][4];
            #pragma unroll
            for (int n = 0; n < 8; n++)
                #pragma unroll
                for (int j = 0; j < 4; j++) Sf[n][j] = 0.f;

            #pragma unroll
            for (int ks = 0; ks < 4; ks++) {
                uint32_t ahi[4], alo[4];
                const int arow = R0 + (lane & 15);
                const int acol = ks * 16 + ((lane >> 4) << 3);
                const uint32_t ao = swz((uint32_t)(arow * 128 + acol * 2));
                ldsm4(sb + OF_QHI + ao, ahi);
                ldsm4(sb + OF_QLO + ao, alo);
                #pragma unroll
                for (int np = 0; np < 4; np++) {
                    const uint32_t bo = swz((uint32_t)(
                        (np * 16 + ((lane >> 4) << 3) + (lane & 7)) * 128 +
                        (ks * 16 + (((lane >> 3) & 1) << 3)) * 2));
                    uint32_t bh[4], bl[4];
                    ldsm4(kbh + bo, bh);
                    ldsm4(kbl + bo, bl);
                    mma16816(Sf[2 * np],     ahi, bh);
                    mma16816(Sf[2 * np],     ahi, bl);
                    mma16816(Sf[2 * np],     alo, bh);
                    mma16816(Sf[2 * np + 1], ahi, bh + 2);
                    mma16816(Sf[2 * np + 1], ahi, bl + 2);
                    mma16816(Sf[2 * np + 1], alo, bh + 2);
                }
            }

            // ---- mask (3 paths) + row max ----
            const bool aL = (actL >> kt) & 1, aR = (actR >> kt) & 1;
            const bool dg = (kt >= 2 * qt);
            float rm0 = -1e30f, rm1 = -1e30f;
            if (!dg && aL && aR) {
                #pragma unroll
                for (int n = 0; n < 8; n++) {
                    rm0 = fmaxf(rm0, fmaxf(Sf[n][0], Sf[n][1]));
                    rm1 = fmaxf(rm1, fmaxf(Sf[n][2], Sf[n][3]));
                }
            } else if (!dg) {
                const float bL = aL ? 0.f : -1e30f;
                const float bR = aR ? 0.f : -1e30f;
                #pragma unroll
                for (int n = 0; n < 8; n++) {
                    const float b = (n < 4) ? bL : bR;
                    Sf[n][0] += b; Sf[n][1] += b;
                    Sf[n][2] += b; Sf[n][3] += b;
                    rm0 = fmaxf(rm0, fmaxf(Sf[n][0], Sf[n][1]));
                    rm1 = fmaxf(rm1, fmaxf(Sf[n][2], Sf[n][3]));
                }
            } else {
                const int cb = kt * KTC;
                #pragma unroll
                for (int n = 0; n < 8; n++) {
                    const bool an = (n < 4) ? aL : aR;
                    const int c0 = cb + n * 8 + ((lane & 3) << 1);
                    const bool k00 = an && (c0     <= gr0);
                    const bool k01 = an && (c0 + 1 <= gr0);
                    const bool k10 = an && (c0     <= gr1);
                    const bool k11 = an && (c0 + 1 <= gr1);
                    Sf[n][0] = k00 ? Sf[n][0] : -1e30f;
                    Sf[n][1] = k01 ? Sf[n][1] : -1e30f;
                    Sf[n][2] = k10 ? Sf[n][2] : -1e30f;
                    Sf[n][3] = k11 ? Sf[n][3] : -1e30f;
                    rm0 = fmaxf(rm0, fmaxf(Sf[n][0], Sf[n][1]));
                    rm1 = fmaxf(rm1, fmaxf(Sf[n][2], Sf[n][3]));
                }
            }
            rm0 = fmaxf(rm0, __shfl_xor_sync(0xffffffffu, rm0, 1));
            rm0 = fmaxf(rm0, __shfl_xor_sync(0xffffffffu, rm0, 2));
            rm1 = fmaxf(rm1, __shfl_xor_sync(0xffffffffu, rm1, 1));
            rm1 = fmaxf(rm1, __shfl_xor_sync(0xffffffffu, rm1, 2));

            const float nm0 = fmaxf(m0, rm0), nm1 = fmaxf(m1, rm1);
            const float corr0 = ex2(m0 - nm0), corr1 = ex2(m1 - nm1);
            m0 = nm0; m1 = nm1;

            // ---- ex2 + packed P fragments (single fp16 plane) ----
            uint32_t Pah[4][4];
            float rs0 = 0.f, rs1 = 0.f;
            #pragma unroll
            for (int ks = 0; ks < 4; ks++) {
                #pragma unroll
                for (int j = 0; j < 2; j++) {
                    const int n = 2 * ks + j;
                    float e0 = ex2(Sf[n][0] - nm0);
                    float e1 = ex2(Sf[n][1] - nm0);
                    float e2 = ex2(Sf[n][2] - nm1);
                    float e3 = ex2(Sf[n][3] - nm1);
                    rs0 += e0 + e1;
                    rs1 += e2 + e3;
                    Pah[ks][2 * j]     = pkhf(e0, e1);
                    Pah[ks][2 * j + 1] = pkhf(e2, e3);
                }
            }
            rs0 += __shfl_xor_sync(0xffffffffu, rs0, 1);
            rs0 += __shfl_xor_sync(0xffffffffu, rs0, 2);
            rs1 += __shfl_xor_sync(0xffffffffu, rs1, 1);
            rs1 += __shfl_xor_sync(0xffffffffu, rs1, 2);
            l0s = l0s * corr0 + rs0;
            l1s = l1s * corr1 + rs1;

            // ---- rescale O, then PV: Phi x Vhi (1 term) ----
            #pragma unroll
            for (int n = 0; n < 8; n++) {
                Of[n][0] *= corr0; Of[n][1] *= corr0;
                Of[n][2] *= corr1; Of[n][3] *= corr1;
            }
            #pragma unroll
            for (int ks = 0; ks < 4; ks++) {
                #pragma unroll
                for (int np = 0; np < 4; np++) {
                    const uint32_t vo = swz((uint32_t)(
                        (ks * 16 + (lane & 15)) * 128 +
                        (np * 16 + ((lane >> 4) << 3)) * 2));
                    uint32_t vh[4];
                    ldsm4t(vbh + vo, vh);
                    mma16816(Of[2 * np],     Pah[ks], vh);
                    mma16816(Of[2 * np + 1], Pah[ks], vh + 2);
                }
            }

            kt = nkt;
            stage ^= 1;
        }

        // ---- write partial ----
        const int pidx = (h * NQT + qt) * 4 + ch;
        #pragma unroll
        for (int n = 0; n < 8; n++) {
            const int c = n * 8 + ((lane & 3) << 1);
            *(float2*)&g_pO[pidx][lr0][c]     = make_float2(Of[n][0], Of[n][1]);
            *(float2*)&g_pO[pidx][lr0 + 8][c] = make_float2(Of[n][2], Of[n][3]);
        }
        if ((lane & 3) == 0) {
            g_pm[pidx][lr0]     = m0;  g_pl[pidx][lr0]     = l0s;
            g_pm[pidx][lr0 + 8] = m1;  g_pl[pidx][lr0 + 8] = l1s;
        }
    }
}

// ---------------------------------------------------------------------------
// Kernel 3: combine partials -> normalized output (1024 CTAs).
// ---------------------------------------------------------------------------
__global__ void __launch_bounds__(256)
combine_kernel(float* __restrict__ out) {
    const int bx = blockIdx.x;
    const int h  = bx & (NH - 1);
    const int qt = (bx >> 4) & (NQT - 1);
    const int rg = bx >> 8;                // 0..3
    const int npart = (2 * qt + 9) >> 3;   // ceil((2qt+2)/8)
    const int tid = threadIdx.x;
    const int row = rg * 32 + (tid >> 3);
    const int c0  = (tid & 7) * 8;
    const int base = (h * NQT + qt) * 4;

    float M = -1e30f, mm[4], ll[4];
    #pragma unroll
    for (int p = 0; p < 4; p++) {
        if (p < npart) {
            mm[p] = g_pm[base + p][row];
            ll[p] = g_pl[base + p][row];
            M = fmaxf(M, mm[p]);
        }
    }
    float L = 0.f, wt[4];
    #pragma unroll
    for (int p = 0; p < 4; p++) {
        if (p < npart) {
            wt[p] = ex2(mm[p] - M);
            L += ll[p] * wt[p];
        }
    }
    const float inv = (L > 0.f) ? (1.f / L) : 0.f;

    float* ob = out + ((size_t)(h * SEQ + qt * QTR + row)) * DIM + c0;
    #pragma unroll
    for (int cc = 0; cc < 8; cc += 4) {
        float4 acc = make_float4(0.f, 0.f, 0.f, 0.f);
        #pragma unroll
        for (int p = 0; p < 4; p++) {
            if (p < npart) {
                float4 v = *(const float4*)&g_pO[base + p][row][c0 + cc];
                acc.x += v.x * wt[p]; acc.y += v.y * wt[p];
                acc.z += v.z * wt[p]; acc.w += v.w * wt[p];
            }
        }
        *(float4*)(ob + cc) = make_float4(acc.x * inv, acc.y * inv,
                                          acc.z * inv, acc.w * inv);
    }
}

// ---------------------------------------------------------------------------
// Launch
// ---------------------------------------------------------------------------
extern "C" void kernel_launch(void* const* d_in, const int* in_sizes, int n_in,
                              void* d_out, int out_size) {
    const float* qry  = (const float*)d_in[0];
    const float* key  = (const float*)d_in[1];
    const float* val  = (const float*)d_in[2];
    const int*   mask = (const int*)d_in[3];
    float* out = (float*)d_out;

    prep_kernel<<<MASK_CTAS + 3 * CVT_CTAS, 256>>>(mask, qry, key, val);

    static int attr_set = 0;
    if (!attr_set) {
        cudaFuncSetAttribute(attn_mma,
                             cudaFuncAttributeMaxDynamicSharedMemorySize, SMEM_BYTES);
        attr_set = 1;
    }
    attn_mma<<<2 * NSM, 256, SMEM_BYTES>>>();

    combine_kernel<<<NH * NQT * 4, 256>>>(out);
}